// round 2
// baseline (speedup 1.0000x reference)
#include <cuda_runtime.h>

#define NEL 33554432           // 2*256*16*64*64
#define NSP 65536               // T*W*H

// ---------------- scratch (device globals; no runtime alloc) ----------------
__device__ float g_buf0[NEL];
__device__ float g_buf1[NEL];
__device__ float g_xp[NEL];
__device__ float g_q[16777216];   // B * 128 * 65536
__device__ float g_k[8388608];    // B * 128 * 32768
__device__ float g_v[16777216];   // B * 256 * 32768
__device__ float g_WT[131072];    // 256 x 512 transposed weights (q|k|v)
__device__ float g_Sp[262144];    // split-K partials
__device__ float g_S[4096];       // attn after softmax: B*64*32 max

// ---------------- weight transpose: WT[c][0:128]=Wq, [128:256]=Wk, [256:512]=Wv
__global__ __launch_bounds__(256) void wtrans_kernel(
    const float* __restrict__ Wq, const float* __restrict__ Wk,
    const float* __restrict__ Wv, float* __restrict__ WT)
{
    int idx = blockIdx.x * 256 + threadIdx.x;   // 131072 total
    int c = idx >> 9;
    int o = idx & 511;
    float val;
    if (o < 128)      val = Wq[o * 256 + c];
    else if (o < 256) val = Wk[(o - 128) * 256 + c];
    else              val = Wv[(o - 256) * 256 + c];
    WT[idx] = val;
}

// ---------------- permutes (canonical [c][t][w][h] -> permuted [c][a][p1][p2])
// W cell: a=w,p1=t,p2=h : xp[a*1024+p1*64+p2] = src[p1*4096+a*64+p2]
__global__ __launch_bounds__(256) void permuteW_kernel(
    const float* __restrict__ src, float* __restrict__ dst)
{
    size_t idx = (size_t)blockIdx.x * 256 + threadIdx.x;
    size_t bc = idx >> 16;
    int n = (int)(idx & 65535);
    int a  = n >> 10;
    int p1 = (n >> 6) & 15;
    int p2 = n & 63;
    dst[idx] = src[(bc << 16) + (size_t)p1 * 4096 + a * 64 + p2];
}

// H cell: a=h,p1=w,p2=t : xp[h*1024+w*16+t] = src[t*4096+w*64+h]; 16x64 tile transpose
__global__ __launch_bounds__(256) void permuteH_kernel(
    const float* __restrict__ src, float* __restrict__ dst)
{
    __shared__ float s[16][65];
    int w = blockIdx.x;         // 64
    int c = blockIdx.y;         // 256
    int b = blockIdx.z;         // 2
    size_t base = ((size_t)b * 256 + c) * 65536;
    int tid = threadIdx.x;
    for (int idx = tid; idx < 1024; idx += 256) {
        int t = idx >> 6, h = idx & 63;
        s[t][h] = src[base + (size_t)t * 4096 + w * 64 + h];
    }
    __syncthreads();
    for (int idx = tid; idx < 1024; idx += 256) {
        int h = idx >> 4, t = idx & 15;
        dst[base + (size_t)h * 1024 + w * 16 + t] = s[t][h];
    }
}

// ---------------- conv1x1 GEMM: out[oc][m] = sum_c WT[c][wc0+oc] * X[c][col(m)] + b
// POOL=1: max over columns n0=(2*a2)*d+p and n0+d (maxpool along A)
template<int POOL>
__global__ __launch_bounds__(256) void conv_gemm(
    const float* __restrict__ X, const float* __restrict__ WT, int wc0,
    const float* __restrict__ bias, float* __restrict__ out, int OC, int d)
{
    const int Np = POOL ? 32768 : 65536;
    int b  = blockIdx.z;
    int m0 = blockIdx.y * 64;
    int n0 = blockIdx.x * 64;
    const float* Xb = X + (size_t)b * 256 * NSP;
    float* outb = out + (size_t)b * OC * Np;

    __shared__ __align__(16) float Ws[16][64];
    __shared__ __align__(16) float Xs[16][64];

    int tid = threadIdx.x;
    int tx = tid & 15, ty = tid >> 4;

    float acc[POOL + 1][4][4];
#pragma unroll
    for (int p = 0; p <= POOL; p++)
#pragma unroll
        for (int i = 0; i < 4; i++)
#pragma unroll
            for (int j = 0; j < 4; j++) acc[p][i][j] = 0.f;

    int a2 = n0 / d;
    int p0 = n0 - a2 * d;

#pragma unroll
    for (int pass = 0; pass <= POOL; pass++) {
        int colbase = POOL ? ((2 * a2 + pass) * d + p0) : n0;
        for (int k0 = 0; k0 < 256; k0 += 16) {
#pragma unroll
            for (int l = 0; l < 4; l++) {
                int idx = tid + l * 256;
                int ki = idx >> 6;
                int mi = idx & 63;
                Ws[ki][mi] = WT[(k0 + ki) * 512 + wc0 + m0 + mi];
                Xs[ki][mi] = Xb[(size_t)(k0 + ki) * NSP + colbase + mi];
            }
            __syncthreads();
#pragma unroll
            for (int kk = 0; kk < 16; kk++) {
                float4 av = *reinterpret_cast<const float4*>(&Ws[kk][ty * 4]);
                float4 bv = *reinterpret_cast<const float4*>(&Xs[kk][tx * 4]);
                float a4[4] = {av.x, av.y, av.z, av.w};
                float b4[4] = {bv.x, bv.y, bv.z, bv.w};
#pragma unroll
                for (int i = 0; i < 4; i++)
#pragma unroll
                    for (int j = 0; j < 4; j++)
                        acc[pass][i][j] += a4[i] * b4[j];
            }
            __syncthreads();
        }
    }
#pragma unroll
    for (int i = 0; i < 4; i++) {
        int oc = m0 + ty * 4 + i;
        float bi = bias[oc];
#pragma unroll
        for (int j = 0; j < 4; j++) {
            float r = acc[0][i][j];
            if (POOL) r = fmaxf(r, acc[POOL][i][j]);
            outb[(size_t)oc * Np + n0 + tx * 4 + j] = r + bi;
        }
    }
}

// ---------------- attention logits, split-K partials (deterministic; no atomics)
// S_partial[sl][b][i][s] = sum_{j in slice sl} q[i*K+j] * k[j*A2+s]
template<int Ac, int A2c>
__global__ __launch_bounds__(256) void attn_partial(
    const float* __restrict__ q, const float* __restrict__ k,
    float* __restrict__ Sp, int K)
{
    constexpr int NOUT = (Ac * A2c + 255) / 256;
    int b = blockIdx.y, sl = blockIdx.x;
    const float* qb = q + (size_t)b * Ac * K;
    const float* kb = k + (size_t)b * K * A2c;
    __shared__ float Qs[Ac * 32];
    __shared__ float Ks[32 * A2c];
    int tid = threadIdx.x;

    int ii[NOUT], ss[NOUT];
    bool vld[NOUT];
#pragma unroll
    for (int r = 0; r < NOUT; r++) {
        int o = tid + 256 * r;
        vld[r] = (o < Ac * A2c);
        int oc_ = vld[r] ? o : 0;
        ii[r] = oc_ / A2c;
        ss[r] = oc_ % A2c;
    }
    float acc[NOUT];
#pragma unroll
    for (int r = 0; r < NOUT; r++) acc[r] = 0.f;

    int j0 = sl * 2048;
    for (int jt = 0; jt < 2048; jt += 32) {
        int jg = j0 + jt;
        for (int idx = tid; idx < Ac * 32; idx += 256) {
            int r = idx >> 5, c = idx & 31;
            Qs[idx] = qb[(size_t)r * K + jg + c];
        }
        for (int idx = tid; idx < 32 * A2c; idx += 256)
            Ks[idx] = kb[(size_t)jg * A2c + idx];
        __syncthreads();
#pragma unroll 8
        for (int kk = 0; kk < 32; kk++) {
#pragma unroll
            for (int r = 0; r < NOUT; r++)
                acc[r] += Qs[ii[r] * 32 + kk] * Ks[kk * A2c + ss[r]];
        }
        __syncthreads();
    }
    int rowbase = b * Ac * A2c;
#pragma unroll
    for (int r = 0; r < NOUT; r++)
        if (vld[r])
            Sp[(size_t)sl * (2 * Ac * A2c) + rowbase + ii[r] * A2c + ss[r]] = acc[r];
}

// ---------------- reduce partials + softmax over A2 (one warp per row)
__global__ void softmax_reduce(const float* __restrict__ Sp, float* __restrict__ S,
                               int A2, int nsl, int rowtot)
{
    int row = blockIdx.x;   // b*A + i
    int s = threadIdx.x;    // 32 lanes
    float v = 0.f;
    if (s < A2)
        for (int sl = 0; sl < nsl; sl++)
            v += Sp[(size_t)sl * rowtot + row * A2 + s];
    float vm = (s < A2) ? v : -1e30f;
#pragma unroll
    for (int off = 16; off; off >>= 1)
        vm = fmaxf(vm, __shfl_xor_sync(0xffffffffu, vm, off));
    float e = (s < A2) ? expf(v - vm) : 0.f;
    float sum = e;
#pragma unroll
    for (int off = 16; off; off >>= 1)
        sum += __shfl_xor_sync(0xffffffffu, sum, off);
    if (s < A2) S[row * A2 + s] = e / sum;
}

// ---------------- o-GEMM + un-permute + residual: out = gamma * (v2d @ attn^T) + cur
// x (the shared einsum index) is decoded per the OUTPUT reshape semantics:
//   CELL 0 (T): o.reshape(C,W,H,T)           x = c*4096 + w*64 + h, a = t
//   CELL 1 (W): o.reshape(C,T,H,W).swap(3,4) x = c*1024 + t*64 + h, a = w
//   CELL 2 (H): o.reshape(C,T,W,H)           x = c*1024 + t*64 + w, a = h
template<int CELL>
__global__ __launch_bounds__(256) void epilogue_kernel(
    const float* __restrict__ v, const float* __restrict__ S,
    const float* __restrict__ cur, float* __restrict__ outp,
    const float* __restrict__ gammap)
{
    constexpr int A  = (CELL == 0) ? 16 : 64;
    constexpr int A2 = (CELL == 0) ? 8 : 32;
    constexpr int d  = (CELL == 0) ? 4096 : 1024;

    int b = blockIdx.y;
    __shared__ float attnS[A * A2];
    int tid = threadIdx.x;
    for (int idx = tid; idx < A * A2; idx += 256)
        attnS[idx] = S[b * A * A2 + idx];
    __syncthreads();

    float g = gammap[0];
    int x = blockIdx.x * 256 + tid;   // < 256*d

    const float4* vr4 = reinterpret_cast<const float4*>(
        v + (size_t)b * 8388608 + (size_t)x * A2);
    float vv[A2];
#pragma unroll
    for (int s4 = 0; s4 < A2 / 4; s4++) {
        float4 t = vr4[s4];
        vv[s4 * 4 + 0] = t.x; vv[s4 * 4 + 1] = t.y;
        vv[s4 * 4 + 2] = t.z; vv[s4 * 4 + 3] = t.w;
    }
    int c  = x / d;
    int p  = x % d;
    int p1 = p / 64;
    int p2 = p % 64;
    size_t boff = (size_t)b * 16777216 + (size_t)c * 65536;
    int base, stride;
    if (CELL == 0)      { base = p1 * 64   + p2;        stride = 4096; } // w,h ; a=t
    else if (CELL == 1) { base = p1 * 4096 + p2;        stride = 64;   } // t,h ; a=w
    else                { base = p1 * 4096 + p2 * 64;   stride = 1;    } // t,w ; a=h

#pragma unroll 4
    for (int a = 0; a < A; a++) {
        float o = 0.f;
#pragma unroll
        for (int s = 0; s < A2; s++) o += vv[s] * attnS[a * A2 + s];
        int off = base + a * stride;
        outp[boff + off] = g * o + cur[boff + off];
    }
}

// ---------------- host orchestration ----------------
extern "C" void kernel_launch(void* const* d_in, const int* in_sizes, int n_in,
                              void* d_out, int out_size)
{
    const float* x  = (const float*)d_in[0];
    const float* Wq = (const float*)d_in[1];
    const float* bq = (const float*)d_in[2];
    const float* Wk = (const float*)d_in[3];
    const float* bk = (const float*)d_in[4];
    const float* Wv = (const float*)d_in[5];
    const float* bv = (const float*)d_in[6];
    const float* gm = (const float*)d_in[7];
    float* out = (float*)d_out;

    float *buf0, *buf1, *xp, *q, *k, *v, *WT, *Sp, *S;
    cudaGetSymbolAddress((void**)&buf0, g_buf0);
    cudaGetSymbolAddress((void**)&buf1, g_buf1);
    cudaGetSymbolAddress((void**)&xp,   g_xp);
    cudaGetSymbolAddress((void**)&q,    g_q);
    cudaGetSymbolAddress((void**)&k,    g_k);
    cudaGetSymbolAddress((void**)&v,    g_v);
    cudaGetSymbolAddress((void**)&WT,   g_WT);
    cudaGetSymbolAddress((void**)&Sp,   g_Sp);
    cudaGetSymbolAddress((void**)&S,    g_S);

    // ================= cell 0 : attention over T (permutation = identity) ======
    {
        wtrans_kernel<<<512, 256>>>(Wq, Wk, Wv, WT);
        conv_gemm<0><<<dim3(1024, 2, 2), 256>>>(x, WT, 0,   bq, q, 128, 4096);
        conv_gemm<1><<<dim3(512,  2, 2), 256>>>(x, WT, 128, bk, k, 128, 4096);
        conv_gemm<1><<<dim3(512,  4, 2), 256>>>(x, WT, 256, bv, v, 256, 4096);
        attn_partial<16, 8><<<dim3(256, 2), 256>>>(q, k, Sp, 524288);
        softmax_reduce<<<32, 32>>>(Sp, S, 8, 256, 256);
        epilogue_kernel<0><<<dim3(4096, 2), 256>>>(v, S, x, buf0, gm + 0);
    }
    // ================= cell 1 : attention over W ===============================
    {
        permuteW_kernel<<<NEL / 256, 256>>>(buf0, xp);
        wtrans_kernel<<<512, 256>>>(Wq + 32768, Wk + 32768, Wv + 65536, WT);
        conv_gemm<0><<<dim3(1024, 2, 2), 256>>>(xp, WT, 0,   bq + 128, q, 128, 1024);
        conv_gemm<1><<<dim3(512,  2, 2), 256>>>(xp, WT, 128, bk + 128, k, 128, 1024);
        conv_gemm<1><<<dim3(512,  4, 2), 256>>>(xp, WT, 256, bv + 256, v, 256, 1024);
        attn_partial<64, 32><<<dim3(64, 2), 256>>>(q, k, Sp, 131072);
        softmax_reduce<<<128, 32>>>(Sp, S, 32, 64, 4096);
        epilogue_kernel<1><<<dim3(1024, 2), 256>>>(v, S, buf0, buf1, gm + 1);
    }
    // ================= cell 2 : attention over H ===============================
    {
        permuteH_kernel<<<dim3(64, 256, 2), 256>>>(buf1, xp);
        wtrans_kernel<<<512, 256>>>(Wq + 65536, Wk + 65536, Wv + 131072, WT);
        conv_gemm<0><<<dim3(1024, 2, 2), 256>>>(xp, WT, 0,   bq + 256, q, 128, 1024);
        conv_gemm<1><<<dim3(512,  2, 2), 256>>>(xp, WT, 128, bk + 256, k, 128, 1024);
        conv_gemm<1><<<dim3(512,  4, 2), 256>>>(xp, WT, 256, bv + 512, v, 256, 1024);
        attn_partial<64, 32><<<dim3(64, 2), 256>>>(q, k, Sp, 131072);
        softmax_reduce<<<128, 32>>>(Sp, S, 32, 64, 4096);
        epilogue_kernel<2><<<dim3(1024, 2), 256>>>(v, S, buf1, out, gm + 2);
    }
}

// round 3
// speedup vs baseline: 1.2528x; 1.2528x over previous
#include <cuda_runtime.h>
#include <cstdint>

#define NEL 33554432           // 2*256*16*64*64
#define NSP 65536               // T*W*H

// ---------------- scratch (device globals; no runtime alloc) ----------------
__device__ float g_buf0[NEL];
__device__ float g_buf1[NEL];
__device__ float g_xp[NEL];
__device__ float g_q[16777216];   // B * 128 * 65536
__device__ float g_k[8388608];    // B * 128 * 32768
__device__ float g_v[16777216];   // B * 256 * 32768
__device__ float g_Whi[131072];   // 256 x 512 transposed weights, tf32-hi
__device__ float g_Wlo[131072];   // tf32-lo residual
__device__ float g_Sp[262144];    // split-K partials
__device__ float g_S[4096];       // attn after softmax: B*64*32 max

// ---------------- helpers ----------------
__device__ __forceinline__ float tf32_rna(float x) {
    uint32_t u;
    asm("cvt.rna.tf32.f32 %0, %1;" : "=r"(u) : "f"(x));
    return __uint_as_float(u);
}
__device__ __forceinline__ void split1(float x, float& h, float& l) {
    h = tf32_rna(x);
    l = tf32_rna(x - h);
}
__device__ __forceinline__ float4 ld4(const float* p) {
    return *reinterpret_cast<const float4*>(p);
}
__device__ __forceinline__ void mma_tf32(float* d, const float* a, const float* b) {
    asm volatile(
        "mma.sync.aligned.m16n8k8.row.col.f32.tf32.tf32.f32 "
        "{%0,%1,%2,%3}, {%4,%5,%6,%7}, {%8,%9}, {%0,%1,%2,%3};"
        : "+f"(d[0]), "+f"(d[1]), "+f"(d[2]), "+f"(d[3])
        : "r"(__float_as_uint(a[0])), "r"(__float_as_uint(a[1])),
          "r"(__float_as_uint(a[2])), "r"(__float_as_uint(a[3])),
          "r"(__float_as_uint(b[0])), "r"(__float_as_uint(b[1])));
}

// ---------------- weight transpose + tf32 split ----------------
__global__ __launch_bounds__(256) void wtrans_kernel(
    const float* __restrict__ Wq, const float* __restrict__ Wk,
    const float* __restrict__ Wv)
{
    int idx = blockIdx.x * 256 + threadIdx.x;   // 131072 total
    int c = idx >> 9;
    int o = idx & 511;
    float val;
    if (o < 128)      val = Wq[o * 256 + c];
    else if (o < 256) val = Wk[(o - 128) * 256 + c];
    else              val = Wv[(o - 256) * 256 + c];
    float h, l;
    split1(val, h, l);
    g_Whi[idx] = h;
    g_Wlo[idx] = l;
}

// ---------------- permutes (canonical [c][t][w][h] -> permuted [c][a][p1][p2])
__global__ __launch_bounds__(256) void permuteW_kernel(
    const float* __restrict__ src, float* __restrict__ dst)
{
    size_t idx = (size_t)blockIdx.x * 256 + threadIdx.x;
    size_t bc = idx >> 16;
    int n = (int)(idx & 65535);
    int a  = n >> 10;
    int p1 = (n >> 6) & 15;
    int p2 = n & 63;
    dst[idx] = src[(bc << 16) + (size_t)p1 * 4096 + a * 64 + p2];
}

__global__ __launch_bounds__(256) void permuteH_kernel(
    const float* __restrict__ src, float* __restrict__ dst)
{
    __shared__ float s[16][65];
    int w = blockIdx.x;
    int c = blockIdx.y;
    int b = blockIdx.z;
    size_t base = ((size_t)b * 256 + c) * 65536;
    int tid = threadIdx.x;
    for (int idx = tid; idx < 1024; idx += 256) {
        int t = idx >> 6, h = idx & 63;
        s[t][h] = src[base + (size_t)t * 4096 + w * 64 + h];
    }
    __syncthreads();
    for (int idx = tid; idx < 1024; idx += 256) {
        int h = idx >> 4, t = idx & 15;
        dst[base + (size_t)h * 1024 + w * 16 + t] = s[t][h];
    }
}

// ---------------- tensor-core conv1x1 GEMM (3xTF32), pool fused -------------
// out[oc][n] = sum_c W[c][wc0+oc] * X[c][col(n)] + bias ; POOL=1: max of 2 streams
template<int POOL>
__global__ __launch_bounds__(256) void conv_mma(
    const float* __restrict__ X, int wc0, const float* __restrict__ bias,
    float* __restrict__ out, int OC, int d)
{
    constexpr int BN = POOL ? 64 : 128;
    constexpr int NS = POOL ? 2 : 1;     // B streams
    constexpr int NT = POOL ? 2 : 4;     // n8 tiles per warp
    constexpr int PW = 132;              // Ws pitch (mod 32 == 4 -> conflict-free frags)
    constexpr int PX = POOL ? 68 : 132;  // Xs pitch
    constexpr int XTILE = 16 * PX;

    __shared__ float WsH[16 * PW], WsL[16 * PW];
    __shared__ float XsH[NS * XTILE], XsL[NS * XTILE];

    const int Np = POOL ? 32768 : 65536;
    int b  = blockIdx.z;
    int m0 = blockIdx.y * 128;
    int n0 = blockIdx.x * BN;
    const float* Xb = X + (size_t)b * 256 * NSP;
    float* outb = out + (size_t)b * OC * Np;

    int tid  = threadIdx.x;
    int lane = tid & 31, warp = tid >> 5;
    int wm = warp >> 2, wn = warp & 3;
    int g = lane >> 2, tg = lane & 3;

    int cb0, cb1;
    if (POOL) {
        int a2 = n0 / d;
        int p0 = n0 - a2 * d;
        cb0 = 2 * a2 * d + p0;
        cb1 = cb0 + d;
    } else { cb0 = n0; cb1 = 0; }

    // per-thread load coords (per BK=16 step)
    int wr = tid >> 5;               // weight rows wr, wr+8
    int wc = (tid & 31) * 4;         // weight col (within 128)
    int xr_, xc_;
    if (POOL) { xr_ = tid >> 4; xc_ = (tid & 15) * 4; }   // one row of 16, one f4/stream
    else      { xr_ = wr;       xc_ = wc; }               // rows xr_, xr_+8

    float acc[NS][4][NT][4];
#pragma unroll
    for (int st = 0; st < NS; st++)
#pragma unroll
        for (int mt = 0; mt < 4; mt++)
#pragma unroll
            for (int nt = 0; nt < NT; nt++)
#pragma unroll
                for (int r = 0; r < 4; r++) acc[st][mt][nt][r] = 0.f;

    const int wcol = wc0 + m0 + wc;
    float4 whv0, whv1, wlv0, wlv1, xv0, xv1;

    // prefetch step 0
    whv0 = ld4(g_Whi + (size_t)wr * 512 + wcol);
    whv1 = ld4(g_Whi + (size_t)(wr + 8) * 512 + wcol);
    wlv0 = ld4(g_Wlo + (size_t)wr * 512 + wcol);
    wlv1 = ld4(g_Wlo + (size_t)(wr + 8) * 512 + wcol);
    if (POOL) {
        xv0 = ld4(Xb + (size_t)xr_ * NSP + cb0 + xc_);
        xv1 = ld4(Xb + (size_t)xr_ * NSP + cb1 + xc_);
    } else {
        xv0 = ld4(Xb + (size_t)xr_ * NSP + cb0 + xc_);
        xv1 = ld4(Xb + (size_t)(xr_ + 8) * NSP + cb0 + xc_);
    }

#pragma unroll 1
    for (int s = 0; s < 16; s++) {
        // ---- store prefetched tile to smem (X gets tf32 hi/lo split) ----
        *(float4*)&WsH[wr * PW + wc]       = whv0;
        *(float4*)&WsH[(wr + 8) * PW + wc] = whv1;
        *(float4*)&WsL[wr * PW + wc]       = wlv0;
        *(float4*)&WsL[(wr + 8) * PW + wc] = wlv1;
        {
            float4 h0, l0, h1, l1;
            split1(xv0.x, h0.x, l0.x); split1(xv0.y, h0.y, l0.y);
            split1(xv0.z, h0.z, l0.z); split1(xv0.w, h0.w, l0.w);
            split1(xv1.x, h1.x, l1.x); split1(xv1.y, h1.y, l1.y);
            split1(xv1.z, h1.z, l1.z); split1(xv1.w, h1.w, l1.w);
            if (POOL) {
                *(float4*)&XsH[0 * XTILE + xr_ * PX + xc_] = h0;
                *(float4*)&XsL[0 * XTILE + xr_ * PX + xc_] = l0;
                *(float4*)&XsH[1 * XTILE + xr_ * PX + xc_] = h1;
                *(float4*)&XsL[1 * XTILE + xr_ * PX + xc_] = l1;
            } else {
                *(float4*)&XsH[xr_ * PX + xc_]       = h0;
                *(float4*)&XsL[xr_ * PX + xc_]       = l0;
                *(float4*)&XsH[(xr_ + 8) * PX + xc_] = h1;
                *(float4*)&XsL[(xr_ + 8) * PX + xc_] = l1;
            }
        }
        __syncthreads();

        // ---- prefetch next tile while computing current ----
        if (s < 15) {
            int k1 = (s + 1) * 16;
            whv0 = ld4(g_Whi + (size_t)(k1 + wr) * 512 + wcol);
            whv1 = ld4(g_Whi + (size_t)(k1 + wr + 8) * 512 + wcol);
            wlv0 = ld4(g_Wlo + (size_t)(k1 + wr) * 512 + wcol);
            wlv1 = ld4(g_Wlo + (size_t)(k1 + wr + 8) * 512 + wcol);
            if (POOL) {
                xv0 = ld4(Xb + (size_t)(k1 + xr_) * NSP + cb0 + xc_);
                xv1 = ld4(Xb + (size_t)(k1 + xr_) * NSP + cb1 + xc_);
            } else {
                xv0 = ld4(Xb + (size_t)(k1 + xr_) * NSP + cb0 + xc_);
                xv1 = ld4(Xb + (size_t)(k1 + xr_ + 8) * NSP + cb0 + xc_);
            }
        }

        // ---- compute 2 x k8 ----
#pragma unroll
        for (int kk = 0; kk < 16; kk += 8) {
            float ah[4][4], al[4][4];
            int kA = (kk + tg) * PW;
            int mrow = wm * 64 + g;
#pragma unroll
            for (int mt = 0; mt < 4; mt++) {
                int mc = mrow + mt * 16;
                ah[mt][0] = WsH[kA + mc];
                ah[mt][1] = WsH[kA + mc + 8];
                ah[mt][2] = WsH[kA + 4 * PW + mc];
                ah[mt][3] = WsH[kA + 4 * PW + mc + 8];
                al[mt][0] = WsL[kA + mc];
                al[mt][1] = WsL[kA + mc + 8];
                al[mt][2] = WsL[kA + 4 * PW + mc];
                al[mt][3] = WsL[kA + 4 * PW + mc + 8];
            }
#pragma unroll
            for (int st = 0; st < NS; st++) {
#pragma unroll
                for (int nt = 0; nt < NT; nt++) {
                    int ncol = wn * (POOL ? 16 : 32) + nt * 8 + g;
                    int kB = st * XTILE + (kk + tg) * PX + ncol;
                    float bh[2], bl[2];
                    bh[0] = XsH[kB];  bh[1] = XsH[kB + 4 * PX];
                    bl[0] = XsL[kB];  bl[1] = XsL[kB + 4 * PX];
#pragma unroll
                    for (int mt = 0; mt < 4; mt++) {
                        mma_tf32(acc[st][mt][nt], ah[mt], bh);  // hi*hi
                        mma_tf32(acc[st][mt][nt], ah[mt], bl);  // hi*lo
                        mma_tf32(acc[st][mt][nt], al[mt], bh);  // lo*hi
                    }
                }
            }
        }
        __syncthreads();
    }

    // ---- epilogue: (max) + bias, write float2 pairs ----
#pragma unroll
    for (int mt = 0; mt < 4; mt++) {
        int r0 = m0 + wm * 64 + mt * 16 + g;
        float bi0 = bias[r0], bi1 = bias[r0 + 8];
#pragma unroll
        for (int nt = 0; nt < NT; nt++) {
            int c = n0 + wn * (POOL ? 16 : 32) + nt * 8 + 2 * tg;
            float v00, v01, v10, v11;
            if (POOL) {
                v00 = fmaxf(acc[0][mt][nt][0], acc[1][mt][nt][0]) + bi0;
                v01 = fmaxf(acc[0][mt][nt][1], acc[1][mt][nt][1]) + bi0;
                v10 = fmaxf(acc[0][mt][nt][2], acc[1][mt][nt][2]) + bi1;
                v11 = fmaxf(acc[0][mt][nt][3], acc[1][mt][nt][3]) + bi1;
            } else {
                v00 = acc[0][mt][nt][0] + bi0;
                v01 = acc[0][mt][nt][1] + bi0;
                v10 = acc[0][mt][nt][2] + bi1;
                v11 = acc[0][mt][nt][3] + bi1;
            }
            *(float2*)&outb[(size_t)r0 * Np + c]       = make_float2(v00, v01);
            *(float2*)&outb[(size_t)(r0 + 8) * Np + c] = make_float2(v10, v11);
        }
    }
}

// ---------------- attention logits, split-K partials (deterministic) --------
template<int Ac, int A2c>
__global__ __launch_bounds__(256) void attn_partial(
    const float* __restrict__ q, const float* __restrict__ k,
    float* __restrict__ Sp, int K)
{
    constexpr int NOUT = (Ac * A2c + 255) / 256;
    int b = blockIdx.y, sl = blockIdx.x;
    const float* qb = q + (size_t)b * Ac * K;
    const float* kb = k + (size_t)b * K * A2c;
    __shared__ float Qs[Ac * 32];
    __shared__ float Ks[32 * A2c];
    int tid = threadIdx.x;

    int ii[NOUT], ss[NOUT];
    bool vld[NOUT];
#pragma unroll
    for (int r = 0; r < NOUT; r++) {
        int o = tid + 256 * r;
        vld[r] = (o < Ac * A2c);
        int oc_ = vld[r] ? o : 0;
        ii[r] = oc_ / A2c;
        ss[r] = oc_ % A2c;
    }
    float acc[NOUT];
#pragma unroll
    for (int r = 0; r < NOUT; r++) acc[r] = 0.f;

    int j0 = sl * 2048;
    for (int jt = 0; jt < 2048; jt += 32) {
        int jg = j0 + jt;
        for (int idx = tid; idx < Ac * 32; idx += 256) {
            int r = idx >> 5, c = idx & 31;
            Qs[idx] = qb[(size_t)r * K + jg + c];
        }
        for (int idx = tid; idx < 32 * A2c; idx += 256)
            Ks[idx] = kb[(size_t)jg * A2c + idx];
        __syncthreads();
#pragma unroll 8
        for (int kk = 0; kk < 32; kk++) {
#pragma unroll
            for (int r = 0; r < NOUT; r++)
                acc[r] += Qs[ii[r] * 32 + kk] * Ks[kk * A2c + ss[r]];
        }
        __syncthreads();
    }
    int rowbase = b * Ac * A2c;
#pragma unroll
    for (int r = 0; r < NOUT; r++)
        if (vld[r])
            Sp[(size_t)sl * (2 * Ac * A2c) + rowbase + ii[r] * A2c + ss[r]] = acc[r];
}

// ---------------- reduce partials + softmax over A2 (one warp per row) ------
__global__ void softmax_reduce(const float* __restrict__ Sp, float* __restrict__ S,
                               int A2, int nsl, int rowtot)
{
    int row = blockIdx.x;
    int s = threadIdx.x;
    float v = 0.f;
    if (s < A2)
        for (int sl = 0; sl < nsl; sl++)
            v += Sp[(size_t)sl * rowtot + row * A2 + s];
    float vm = (s < A2) ? v : -1e30f;
#pragma unroll
    for (int off = 16; off; off >>= 1)
        vm = fmaxf(vm, __shfl_xor_sync(0xffffffffu, vm, off));
    float e = (s < A2) ? expf(v - vm) : 0.f;
    float sum = e;
#pragma unroll
    for (int off = 16; off; off >>= 1)
        sum += __shfl_xor_sync(0xffffffffu, sum, off);
    if (s < A2) S[row * A2 + s] = e / sum;
}

// ---------------- o-GEMM + un-permute + residual -----------------------------
//   CELL 0 (T): x = c*4096 + w*64 + h, a = t
//   CELL 1 (W): x = c*1024 + t*64 + h, a = w
//   CELL 2 (H): x = c*1024 + t*64 + w, a = h
template<int CELL>
__global__ __launch_bounds__(256) void epilogue_kernel(
    const float* __restrict__ v, const float* __restrict__ S,
    const float* __restrict__ cur, float* __restrict__ outp,
    const float* __restrict__ gammap)
{
    constexpr int A  = (CELL == 0) ? 16 : 64;
    constexpr int A2 = (CELL == 0) ? 8 : 32;
    constexpr int d  = (CELL == 0) ? 4096 : 1024;

    int b = blockIdx.y;
    __shared__ float attnS[A * A2];
    int tid = threadIdx.x;
    for (int idx = tid; idx < A * A2; idx += 256)
        attnS[idx] = S[b * A * A2 + idx];
    __syncthreads();

    float g = gammap[0];
    int x = blockIdx.x * 256 + tid;

    const float4* vr4 = reinterpret_cast<const float4*>(
        v + (size_t)b * 8388608 + (size_t)x * A2);
    float vv[A2];
#pragma unroll
    for (int s4 = 0; s4 < A2 / 4; s4++) {
        float4 t = vr4[s4];
        vv[s4 * 4 + 0] = t.x; vv[s4 * 4 + 1] = t.y;
        vv[s4 * 4 + 2] = t.z; vv[s4 * 4 + 3] = t.w;
    }
    int c  = x / d;
    int p  = x % d;
    int p1 = p / 64;
    int p2 = p % 64;
    size_t boff = (size_t)b * 16777216 + (size_t)c * 65536;
    int base, stride;
    if (CELL == 0)      { base = p1 * 64   + p2;      stride = 4096; }
    else if (CELL == 1) { base = p1 * 4096 + p2;      stride = 64;   }
    else                { base = p1 * 4096 + p2 * 64; stride = 1;    }

#pragma unroll 4
    for (int a = 0; a < A; a++) {
        float o = 0.f;
#pragma unroll
        for (int s = 0; s < A2; s++) o += vv[s] * attnS[a * A2 + s];
        int off = base + a * stride;
        outp[boff + off] = g * o + cur[boff + off];
    }
}

// ---------------- host orchestration ----------------
extern "C" void kernel_launch(void* const* d_in, const int* in_sizes, int n_in,
                              void* d_out, int out_size)
{
    const float* x  = (const float*)d_in[0];
    const float* Wq = (const float*)d_in[1];
    const float* bq = (const float*)d_in[2];
    const float* Wk = (const float*)d_in[3];
    const float* bk = (const float*)d_in[4];
    const float* Wv = (const float*)d_in[5];
    const float* bv = (const float*)d_in[6];
    const float* gm = (const float*)d_in[7];
    float* out = (float*)d_out;

    float *buf0, *buf1, *xp, *q, *k, *v, *Sp, *S;
    cudaGetSymbolAddress((void**)&buf0, g_buf0);
    cudaGetSymbolAddress((void**)&buf1, g_buf1);
    cudaGetSymbolAddress((void**)&xp,   g_xp);
    cudaGetSymbolAddress((void**)&q,    g_q);
    cudaGetSymbolAddress((void**)&k,    g_k);
    cudaGetSymbolAddress((void**)&v,    g_v);
    cudaGetSymbolAddress((void**)&Sp,   g_Sp);
    cudaGetSymbolAddress((void**)&S,    g_S);

    // ================= cell 0 : attention over T (identity permutation) ======
    {
        wtrans_kernel<<<512, 256>>>(Wq, Wk, Wv);
        conv_mma<0><<<dim3(512, 1, 2), 256>>>(x, 0,   bq, q, 128, 4096);
        conv_mma<1><<<dim3(512, 1, 2), 256>>>(x, 128, bk, k, 128, 4096);
        conv_mma<1><<<dim3(512, 2, 2), 256>>>(x, 256, bv, v, 256, 4096);
        attn_partial<16, 8><<<dim3(256, 2), 256>>>(q, k, Sp, 524288);
        softmax_reduce<<<32, 32>>>(Sp, S, 8, 256, 256);
        epilogue_kernel<0><<<dim3(4096, 2), 256>>>(v, S, x, buf0, gm + 0);
    }
    // ================= cell 1 : attention over W ===============================
    {
        permuteW_kernel<<<NEL / 256, 256>>>(buf0, xp);
        wtrans_kernel<<<512, 256>>>(Wq + 32768, Wk + 32768, Wv + 65536);
        conv_mma<0><<<dim3(512, 1, 2), 256>>>(xp, 0,   bq + 128, q, 128, 1024);
        conv_mma<1><<<dim3(512, 1, 2), 256>>>(xp, 128, bk + 128, k, 128, 1024);
        conv_mma<1><<<dim3(512, 2, 2), 256>>>(xp, 256, bv + 256, v, 256, 1024);
        attn_partial<64, 32><<<dim3(64, 2), 256>>>(q, k, Sp, 131072);
        softmax_reduce<<<128, 32>>>(Sp, S, 32, 64, 4096);
        epilogue_kernel<1><<<dim3(1024, 2), 256>>>(v, S, buf0, buf1, gm + 1);
    }
    // ================= cell 2 : attention over H ===============================
    {
        permuteH_kernel<<<dim3(64, 256, 2), 256>>>(buf1, xp);
        wtrans_kernel<<<512, 256>>>(Wq + 65536, Wk + 65536, Wv + 131072);
        conv_mma<0><<<dim3(512, 1, 2), 256>>>(xp, 0,   bq + 256, q, 128, 1024);
        conv_mma<1><<<dim3(512, 1, 2), 256>>>(xp, 128, bk + 256, k, 128, 1024);
        conv_mma<1><<<dim3(512, 2, 2), 256>>>(xp, 256, bv + 512, v, 256, 1024);
        attn_partial<64, 32><<<dim3(64, 2), 256>>>(q, k, Sp, 131072);
        softmax_reduce<<<128, 32>>>(Sp, S, 32, 64, 4096);
        epilogue_kernel<2><<<dim3(1024, 2), 256>>>(v, S, buf1, out, gm + 2);
    }
}

// round 4
// speedup vs baseline: 1.5864x; 1.2663x over previous
#include <cuda_runtime.h>
#include <cstdint>

#define NEL 33554432           // 2*256*16*64*64
#define NSP 65536               // T*W*H

// ---------------- scratch (device globals; no runtime alloc) ----------------
__device__ float g_buf0[NEL];
__device__ float g_buf1[NEL];
__device__ float g_xp[NEL];
__device__ float g_q[16777216];   // B * 128 * 65536
__device__ float g_k[8388608];    // B * 128 * 32768
__device__ float g_v[16777216];   // B * 256 * 32768
__device__ float g_Whi[131072];   // 256 x 512 transposed weights, tf32-hi
__device__ float g_Wlo[131072];   // tf32-lo residual
__device__ float g_Sp[262144];    // split-K partials
__device__ float g_S[4096];       // attn after softmax: B*64*32 max

// ---------------- helpers ----------------
__device__ __forceinline__ float tf32_rna(float x) {
    uint32_t u;
    asm("cvt.rna.tf32.f32 %0, %1;" : "=r"(u) : "f"(x));
    return __uint_as_float(u);
}
__device__ __forceinline__ void split1(float x, float& h, float& l) {
    h = tf32_rna(x);
    l = tf32_rna(x - h);
}
__device__ __forceinline__ void split4(float4 x, float4& h, float4& l) {
    split1(x.x, h.x, l.x); split1(x.y, h.y, l.y);
    split1(x.z, h.z, l.z); split1(x.w, h.w, l.w);
}
__device__ __forceinline__ float4 rna4(float4 x) {
    x.x = tf32_rna(x.x); x.y = tf32_rna(x.y);
    x.z = tf32_rna(x.z); x.w = tf32_rna(x.w);
    return x;
}
__device__ __forceinline__ float4 ld4(const float* p) {
    return *reinterpret_cast<const float4*>(p);
}
__device__ __forceinline__ void mma_tf32(float* d, const float* a, const float* b) {
    asm volatile(
        "mma.sync.aligned.m16n8k8.row.col.f32.tf32.tf32.f32 "
        "{%0,%1,%2,%3}, {%4,%5,%6,%7}, {%8,%9}, {%0,%1,%2,%3};"
        : "+f"(d[0]), "+f"(d[1]), "+f"(d[2]), "+f"(d[3])
        : "r"(__float_as_uint(a[0])), "r"(__float_as_uint(a[1])),
          "r"(__float_as_uint(a[2])), "r"(__float_as_uint(a[3])),
          "r"(__float_as_uint(b[0])), "r"(__float_as_uint(b[1])));
}

// ---------------- weight transpose + tf32 split ----------------
__global__ __launch_bounds__(256) void wtrans_kernel(
    const float* __restrict__ Wq, const float* __restrict__ Wk,
    const float* __restrict__ Wv)
{
    int idx = blockIdx.x * 256 + threadIdx.x;   // 131072 total
    int c = idx >> 9;
    int o = idx & 511;
    float val;
    if (o < 128)      val = Wq[o * 256 + c];
    else if (o < 256) val = Wk[(o - 128) * 256 + c];
    else              val = Wv[(o - 256) * 256 + c];
    float h, l;
    split1(val, h, l);
    g_Whi[idx] = h;
    g_Wlo[idx] = l;
}

// ---------------- permute H (canonical -> [c][h][w][t]) via smem transpose ---
__global__ __launch_bounds__(256) void permuteH_kernel(
    const float* __restrict__ src, float* __restrict__ dst)
{
    __shared__ float s[16][65];
    int w = blockIdx.x;
    int c = blockIdx.y;
    int b = blockIdx.z;
    size_t base = ((size_t)b * 256 + c) * 65536;
    int tid = threadIdx.x;
    for (int idx = tid; idx < 1024; idx += 256) {
        int t = idx >> 6, h = idx & 63;
        s[t][h] = src[base + (size_t)t * 4096 + w * 64 + h];
    }
    __syncthreads();
    for (int idx = tid; idx < 1024; idx += 256) {
        int h = idx >> 4, t = idx & 15;
        dst[base + (size_t)h * 1024 + w * 16 + t] = s[t][h];
    }
}

// ---------------- tensor-core conv1x1 GEMM, double-buffered, pool fused -----
// MODE 0: permuted layout == input layout (param LOGD gives d).
// MODE 1: input is canonical [c][t][w][h], cell-W mapping (d=1024) done inline.
// NPASS 3: hi*hi + hi*lo + lo*hi TF32 split. NPASS 1: plain tf32.
template<int POOL, int NPASS, int MODE, int LOGD>
__global__ __launch_bounds__(256) void conv_mma(
    const float* __restrict__ X, int wc0, const float* __restrict__ bias,
    float* __restrict__ out, int OC)
{
    constexpr int BN = POOL ? 64 : 128;
    constexpr int NS = POOL ? 2 : 1;     // pooled streams
    constexpr int NT = POOL ? 2 : 4;     // n8 tiles per warp
    constexpr int PW = 132;
    constexpr int PX = POOL ? 68 : 132;
    constexpr int WTILE = 16 * PW;
    constexpr int XTILE = 16 * PX;

    extern __shared__ float smem[];
    float* WsH = smem;                              // 2*WTILE
    float* XsH = smem + 2 * WTILE;                  // 2*NS*XTILE
    float* WsL = XsH + 2 * NS * XTILE;              // (NPASS==3)
    float* XsL = WsL + 2 * WTILE;                   // (NPASS==3)

    const int Np = POOL ? 32768 : 65536;
    int b  = blockIdx.z;
    int m0 = blockIdx.y * 128;
    int n0 = blockIdx.x * BN;
    const float* Xb = X + (size_t)b * 256 * NSP;
    float* outb = out + (size_t)b * OC * Np;

    int tid  = threadIdx.x;
    int lane = tid & 31, warp = tid >> 5;
    int wm = warp >> 2, wn = warp & 3;
    int g = lane >> 2, tg = lane & 3;

    int wr = tid >> 5;               // weight rows wr, wr+8
    int wc = (tid & 31) * 4;
    int xr_, xc_;
    if (POOL) { xr_ = tid >> 4; xc_ = (tid & 15) * 4; }
    else      { xr_ = tid >> 5; xc_ = (tid & 31) * 4; }

    // per-thread column -> source-offset mapping (constant across K loop)
    int nn = n0 + xc_;
    int src0, src1 = 0;
    if (MODE == 0) {
        if (POOL) {
            int a2 = nn >> LOGD, r = nn & ((1 << LOGD) - 1);
            src0 = ((2 * a2) << LOGD) + r;
            src1 = src0 + (1 << LOGD);
        } else {
            src0 = nn;
        }
    } else {  // cell W: permuted col = a*1024 + p1*64 + p2 -> src p1*4096 + a*64 + p2
        int aa = nn >> 10, r = nn & 1023;
        if (POOL) {
            src0 = (r >> 6) * 4096 + (2 * aa) * 64 + (r & 63);
            src1 = src0 + 64;
        } else {
            src0 = (r >> 6) * 4096 + aa * 64 + (r & 63);
        }
    }

    float acc[NS][4][NT][4];
#pragma unroll
    for (int st = 0; st < NS; st++)
#pragma unroll
        for (int mt = 0; mt < 4; mt++)
#pragma unroll
            for (int nt = 0; nt < NT; nt++)
#pragma unroll
                for (int r = 0; r < 4; r++) acc[st][mt][nt][r] = 0.f;

    const int wcol = wc0 + m0 + wc;
    float4 whv0, whv1, wlv0, wlv1, xv0, xv1;

    auto LOAD = [&](int k1) {
        whv0 = ld4(g_Whi + (size_t)(k1 + wr) * 512 + wcol);
        whv1 = ld4(g_Whi + (size_t)(k1 + wr + 8) * 512 + wcol);
        if (NPASS == 3) {
            wlv0 = ld4(g_Wlo + (size_t)(k1 + wr) * 512 + wcol);
            wlv1 = ld4(g_Wlo + (size_t)(k1 + wr + 8) * 512 + wcol);
        }
        if (POOL) {
            xv0 = ld4(Xb + (size_t)(k1 + xr_) * NSP + src0);
            xv1 = ld4(Xb + (size_t)(k1 + xr_) * NSP + src1);
        } else {
            xv0 = ld4(Xb + (size_t)(k1 + xr_) * NSP + src0);
            xv1 = ld4(Xb + (size_t)(k1 + xr_ + 8) * NSP + src0);
        }
    };
    auto STORE = [&](int bf) {
        float* wsh = WsH + bf * WTILE;
        *(float4*)&wsh[wr * PW + wc]       = whv0;
        *(float4*)&wsh[(wr + 8) * PW + wc] = whv1;
        float* xsh = XsH + bf * NS * XTILE;
        if (NPASS == 3) {
            float* wsl = WsL + bf * WTILE;
            *(float4*)&wsl[wr * PW + wc]       = wlv0;
            *(float4*)&wsl[(wr + 8) * PW + wc] = wlv1;
            float* xsl = XsL + bf * NS * XTILE;
            float4 h0, l0, h1, l1;
            split4(xv0, h0, l0);
            split4(xv1, h1, l1);
            if (POOL) {
                *(float4*)&xsh[0 * XTILE + xr_ * PX + xc_] = h0;
                *(float4*)&xsl[0 * XTILE + xr_ * PX + xc_] = l0;
                *(float4*)&xsh[1 * XTILE + xr_ * PX + xc_] = h1;
                *(float4*)&xsl[1 * XTILE + xr_ * PX + xc_] = l1;
            } else {
                *(float4*)&xsh[xr_ * PX + xc_]       = h0;
                *(float4*)&xsl[xr_ * PX + xc_]       = l0;
                *(float4*)&xsh[(xr_ + 8) * PX + xc_] = h1;
                *(float4*)&xsl[(xr_ + 8) * PX + xc_] = l1;
            }
        } else {
            float4 h0 = rna4(xv0), h1 = rna4(xv1);
            if (POOL) {
                *(float4*)&xsh[0 * XTILE + xr_ * PX + xc_] = h0;
                *(float4*)&xsh[1 * XTILE + xr_ * PX + xc_] = h1;
            } else {
                *(float4*)&xsh[xr_ * PX + xc_]       = h0;
                *(float4*)&xsh[(xr_ + 8) * PX + xc_] = h1;
            }
        }
    };

    LOAD(0);
    STORE(0);
    __syncthreads();

#pragma unroll 1
    for (int s = 0; s < 16; s++) {
        int cb = s & 1;
        if (s < 15) LOAD((s + 1) << 4);

        const float* wsh = WsH + cb * WTILE;
        const float* xsh = XsH + cb * NS * XTILE;
        const float* wsl = WsL + cb * WTILE;
        const float* xsl = XsL + cb * NS * XTILE;
#pragma unroll
        for (int kk = 0; kk < 16; kk += 8) {
            float ah[4][4], al[4][4];
            int kA = (kk + tg) * PW;
            int mrow = wm * 64 + g;
#pragma unroll
            for (int mt = 0; mt < 4; mt++) {
                int mc = mrow + mt * 16;
                ah[mt][0] = wsh[kA + mc];
                ah[mt][1] = wsh[kA + mc + 8];
                ah[mt][2] = wsh[kA + 4 * PW + mc];
                ah[mt][3] = wsh[kA + 4 * PW + mc + 8];
                if (NPASS == 3) {
                    al[mt][0] = wsl[kA + mc];
                    al[mt][1] = wsl[kA + mc + 8];
                    al[mt][2] = wsl[kA + 4 * PW + mc];
                    al[mt][3] = wsl[kA + 4 * PW + mc + 8];
                }
            }
#pragma unroll
            for (int st = 0; st < NS; st++) {
#pragma unroll
                for (int nt = 0; nt < NT; nt++) {
                    int ncol = wn * (POOL ? 16 : 32) + nt * 8 + g;
                    int kB = st * XTILE + (kk + tg) * PX + ncol;
                    float bh[2], bl[2];
                    bh[0] = xsh[kB];  bh[1] = xsh[kB + 4 * PX];
                    if (NPASS == 3) { bl[0] = xsl[kB]; bl[1] = xsl[kB + 4 * PX]; }
#pragma unroll
                    for (int mt = 0; mt < 4; mt++) {
                        mma_tf32(acc[st][mt][nt], ah[mt], bh);
                        if (NPASS == 3) {
                            mma_tf32(acc[st][mt][nt], ah[mt], bl);
                            mma_tf32(acc[st][mt][nt], al[mt], bh);
                        }
                    }
                }
            }
        }
        if (s < 15) STORE(1 - cb);
        __syncthreads();
    }

    // ---- epilogue: (max) + bias, write float2 pairs ----
#pragma unroll
    for (int mt = 0; mt < 4; mt++) {
        int r0 = m0 + wm * 64 + mt * 16 + g;
        float bi0 = bias[r0], bi1 = bias[r0 + 8];
#pragma unroll
        for (int nt = 0; nt < NT; nt++) {
            int c = n0 + wn * (POOL ? 16 : 32) + nt * 8 + 2 * tg;
            float v00, v01, v10, v11;
            if (POOL) {
                v00 = fmaxf(acc[0][mt][nt][0], acc[1][mt][nt][0]) + bi0;
                v01 = fmaxf(acc[0][mt][nt][1], acc[1][mt][nt][1]) + bi0;
                v10 = fmaxf(acc[0][mt][nt][2], acc[1][mt][nt][2]) + bi1;
                v11 = fmaxf(acc[0][mt][nt][3], acc[1][mt][nt][3]) + bi1;
            } else {
                v00 = acc[0][mt][nt][0] + bi0;
                v01 = acc[0][mt][nt][1] + bi0;
                v10 = acc[0][mt][nt][2] + bi1;
                v11 = acc[0][mt][nt][3] + bi1;
            }
            *(float2*)&outb[(size_t)r0 * Np + c]       = make_float2(v00, v01);
            *(float2*)&outb[(size_t)(r0 + 8) * Np + c] = make_float2(v10, v11);
        }
    }
}

// ---------------- attention logits, split-K partials (deterministic) --------
template<int Ac, int A2c>
__global__ __launch_bounds__(256) void attn_partial(
    const float* __restrict__ q, const float* __restrict__ k,
    float* __restrict__ Sp, int K)
{
    constexpr int NOUT = (Ac * A2c + 255) / 256;
    int b = blockIdx.y, sl = blockIdx.x;
    const float* qb = q + (size_t)b * Ac * K;
    const float* kb = k + (size_t)b * K * A2c;
    __shared__ float Qs[Ac * 32];
    __shared__ float Ks[32 * A2c];
    int tid = threadIdx.x;

    int ii[NOUT], ss[NOUT];
    bool vld[NOUT];
#pragma unroll
    for (int r = 0; r < NOUT; r++) {
        int o = tid + 256 * r;
        vld[r] = (o < Ac * A2c);
        int oc_ = vld[r] ? o : 0;
        ii[r] = oc_ / A2c;
        ss[r] = oc_ % A2c;
    }
    float acc[NOUT];
#pragma unroll
    for (int r = 0; r < NOUT; r++) acc[r] = 0.f;

    int j0 = sl * 2048;
    for (int jt = 0; jt < 2048; jt += 32) {
        int jg = j0 + jt;
        for (int idx = tid; idx < Ac * 32; idx += 256) {
            int r = idx >> 5, c = idx & 31;
            Qs[idx] = qb[(size_t)r * K + jg + c];
        }
        for (int idx = tid; idx < 32 * A2c; idx += 256)
            Ks[idx] = kb[(size_t)jg * A2c + idx];
        __syncthreads();
#pragma unroll 8
        for (int kk = 0; kk < 32; kk++) {
#pragma unroll
            for (int r = 0; r < NOUT; r++)
                acc[r] += Qs[ii[r] * 32 + kk] * Ks[kk * A2c + ss[r]];
        }
        __syncthreads();
    }
    int rowbase = b * Ac * A2c;
#pragma unroll
    for (int r = 0; r < NOUT; r++)
        if (vld[r])
            Sp[(size_t)sl * (2 * Ac * A2c) + rowbase + ii[r] * A2c + ss[r]] = acc[r];
}

// ---------------- reduce partials + softmax over A2 (one warp per row) ------
__global__ void softmax_reduce(const float* __restrict__ Sp, float* __restrict__ S,
                               int A2, int nsl, int rowtot)
{
    int row = blockIdx.x;
    int s = threadIdx.x;
    float v = 0.f;
    if (s < A2)
        for (int sl = 0; sl < nsl; sl++)
            v += Sp[(size_t)sl * rowtot + row * A2 + s];
    float vm = (s < A2) ? v : -1e30f;
#pragma unroll
    for (int off = 16; off; off >>= 1)
        vm = fmaxf(vm, __shfl_xor_sync(0xffffffffu, vm, off));
    float e = (s < A2) ? expf(v - vm) : 0.f;
    float sum = e;
#pragma unroll
    for (int off = 16; off; off >>= 1)
        sum += __shfl_xor_sync(0xffffffffu, sum, off);
    if (s < A2) S[row * A2 + s] = e / sum;
}

// ---------------- o-GEMM + un-permute + residual (cells T, W; coalesced) ----
//   CELL 0 (T): x = c*4096 + w*64 + h, a = t ; off = w*64+h + a*4096
//   CELL 1 (W): x = c*1024 + t*64 + h, a = w ; off = t*4096+h + a*64
template<int CELL>
__global__ __launch_bounds__(256) void epilogue_kernel(
    const float* __restrict__ v, const float* __restrict__ S,
    const float* __restrict__ cur, float* __restrict__ outp,
    const float* __restrict__ gammap)
{
    constexpr int A  = (CELL == 0) ? 16 : 64;
    constexpr int A2 = (CELL == 0) ? 8 : 32;
    constexpr int d  = (CELL == 0) ? 4096 : 1024;

    int b = blockIdx.y;
    __shared__ float attnS[A * A2];
    int tid = threadIdx.x;
    for (int idx = tid; idx < A * A2; idx += 256)
        attnS[idx] = S[b * A * A2 + idx];
    __syncthreads();

    float g = gammap[0];
    int x = blockIdx.x * 256 + tid;

    const float4* vr4 = reinterpret_cast<const float4*>(
        v + (size_t)b * 8388608 + (size_t)x * A2);
    float vv[A2];
#pragma unroll
    for (int s4 = 0; s4 < A2 / 4; s4++) {
        float4 t = vr4[s4];
        vv[s4 * 4 + 0] = t.x; vv[s4 * 4 + 1] = t.y;
        vv[s4 * 4 + 2] = t.z; vv[s4 * 4 + 3] = t.w;
    }
    int c  = x / d;
    int p  = x % d;
    int p1 = p / 64;
    int p2 = p % 64;
    size_t boff = (size_t)b * 16777216 + (size_t)c * 65536;
    int base, stride;
    if (CELL == 0) { base = p1 * 64   + p2; stride = 4096; }
    else           { base = p1 * 4096 + p2; stride = 64;   }

#pragma unroll 4
    for (int a = 0; a < A; a++) {
        float o = 0.f;
#pragma unroll
        for (int s = 0; s < A2; s++) o += vv[s] * attnS[a * A2 + s];
        int off = base + a * stride;
        outp[boff + off] = g * o + cur[boff + off];
    }
}

// ---------------- cell-H epilogue: smem transpose, fully coalesced I/O ------
// x = c*1024 + p1(t)*64 + p2(w), a = h ; out off = c*65536 + p1*4096 + p2*64 + a
__global__ __launch_bounds__(256) void epilogue2_kernel(
    const float* __restrict__ v, const float* __restrict__ S,
    const float* __restrict__ cur, float* __restrict__ outp,
    const float* __restrict__ gammap)
{
    int b  = blockIdx.y;
    int cp = blockIdx.x;        // c*16 + p1
    int c = cp >> 4, p1 = cp & 15;

    __shared__ float attnS[64 * 33];
    __shared__ float vs[64 * 33];
    __shared__ float os[64 * 65];
    int tid = threadIdx.x;

    for (int i = tid; i < 2048; i += 256)
        attnS[(i >> 5) * 33 + (i & 31)] = S[b * 2048 + i];
    size_t vbase = (size_t)b * 8388608 + ((size_t)c * 1024 + p1 * 64) * 32;
    for (int i = tid; i < 2048; i += 256)
        vs[(i >> 5) * 33 + (i & 31)] = v[vbase + i];
    __syncthreads();

    int p2 = tid & 63;
    int a0 = (tid >> 6) * 16;
    float vv[32];
#pragma unroll
    for (int s = 0; s < 32; s++) vv[s] = vs[p2 * 33 + s];
#pragma unroll
    for (int ai = 0; ai < 16; ai++) {
        int a = a0 + ai;
        float o = 0.f;
#pragma unroll
        for (int s = 0; s < 32; s++) o += vv[s] * attnS[a * 33 + s];
        os[p2 * 65 + a] = o;
    }
    __syncthreads();

    float g = gammap[0];
    size_t obase = (size_t)b * 16777216 + (size_t)c * 65536 + (size_t)p1 * 4096;
    for (int i = tid; i < 4096; i += 256)
        outp[obase + i] = g * os[(i >> 6) * 65 + (i & 63)] + cur[obase + i];
}

// ---------------- host orchestration ----------------
extern "C" void kernel_launch(void* const* d_in, const int* in_sizes, int n_in,
                              void* d_out, int out_size)
{
    const float* x  = (const float*)d_in[0];
    const float* Wq = (const float*)d_in[1];
    const float* bq = (const float*)d_in[2];
    const float* Wk = (const float*)d_in[3];
    const float* bk = (const float*)d_in[4];
    const float* Wv = (const float*)d_in[5];
    const float* bv = (const float*)d_in[6];
    const float* gm = (const float*)d_in[7];
    float* out = (float*)d_out;

    float *buf0, *buf1, *xp, *q, *k, *v, *Sp, *S;
    cudaGetSymbolAddress((void**)&buf0, g_buf0);
    cudaGetSymbolAddress((void**)&buf1, g_buf1);
    cudaGetSymbolAddress((void**)&xp,   g_xp);
    cudaGetSymbolAddress((void**)&q,    g_q);
    cudaGetSymbolAddress((void**)&k,    g_k);
    cudaGetSymbolAddress((void**)&v,    g_v);
    cudaGetSymbolAddress((void**)&Sp,   g_Sp);
    cudaGetSymbolAddress((void**)&S,    g_S);

    // dynamic smem sizes (floats): see conv_mma layout
    const int SM_Q = (2 * 2112 + 2 * 1 * 2112 + 2 * 2112 + 2 * 1 * 2112) * 4; // 67584
    const int SM_K = (2 * 2112 + 2 * 2 * 1088 + 2 * 2112 + 2 * 2 * 1088) * 4; // 68608
    const int SM_V = (2 * 2112 + 2 * 2 * 1088) * 4;                           // 34304

    cudaFuncSetAttribute(conv_mma<0,3,0,12>, cudaFuncAttributeMaxDynamicSharedMemorySize, SM_Q);
    cudaFuncSetAttribute(conv_mma<1,3,0,12>, cudaFuncAttributeMaxDynamicSharedMemorySize, SM_K);
    cudaFuncSetAttribute(conv_mma<0,3,1,10>, cudaFuncAttributeMaxDynamicSharedMemorySize, SM_Q);
    cudaFuncSetAttribute(conv_mma<1,3,1,10>, cudaFuncAttributeMaxDynamicSharedMemorySize, SM_K);
    cudaFuncSetAttribute(conv_mma<0,3,0,10>, cudaFuncAttributeMaxDynamicSharedMemorySize, SM_Q);
    cudaFuncSetAttribute(conv_mma<1,3,0,10>, cudaFuncAttributeMaxDynamicSharedMemorySize, SM_K);

    // ================= cell 0 : attention over T (identity permutation) ======
    {
        wtrans_kernel<<<512, 256>>>(Wq, Wk, Wv);
        conv_mma<0,3,0,12><<<dim3(512, 1, 2), 256, SM_Q>>>(x, 0,   bq, q, 128);
        conv_mma<1,3,0,12><<<dim3(512, 1, 2), 256, SM_K>>>(x, 128, bk, k, 128);
        conv_mma<1,1,0,12><<<dim3(512, 2, 2), 256, SM_V>>>(x, 256, bv, v, 256);
        attn_partial<16, 8><<<dim3(256, 2), 256>>>(q, k, Sp, 524288);
        softmax_reduce<<<32, 32>>>(Sp, S, 8, 256, 256);
        epilogue_kernel<0><<<dim3(4096, 2), 256>>>(v, S, x, buf0, gm + 0);
    }
    // ================= cell 1 : attention over W (fused permute in conv) =====
    {
        wtrans_kernel<<<512, 256>>>(Wq + 32768, Wk + 32768, Wv + 65536);
        conv_mma<0,3,1,10><<<dim3(512, 1, 2), 256, SM_Q>>>(buf0, 0,   bq + 128, q, 128);
        conv_mma<1,3,1,10><<<dim3(512, 1, 2), 256, SM_K>>>(buf0, 128, bk + 128, k, 128);
        conv_mma<1,1,1,10><<<dim3(512, 2, 2), 256, SM_V>>>(buf0, 256, bv + 256, v, 256);
        attn_partial<64, 32><<<dim3(64, 2), 256>>>(q, k, Sp, 131072);
        softmax_reduce<<<128, 32>>>(Sp, S, 32, 64, 4096);
        epilogue_kernel<1><<<dim3(1024, 2), 256>>>(v, S, buf0, buf1, gm + 1);
    }
    // ================= cell 2 : attention over H ==============================
    {
        permuteH_kernel<<<dim3(64, 256, 2), 256>>>(buf1, xp);
        wtrans_kernel<<<512, 256>>>(Wq + 65536, Wk + 65536, Wv + 131072);
        conv_mma<0,3,0,10><<<dim3(512, 1, 2), 256, SM_Q>>>(xp, 0,   bq + 256, q, 128);
        conv_mma<1,3,0,10><<<dim3(512, 1, 2), 256, SM_K>>>(xp, 128, bk + 256, k, 128);
        conv_mma<1,1,0,10><<<dim3(512, 2, 2), 256, SM_V>>>(xp, 256, bv + 512, v, 256);
        attn_partial<64, 32><<<dim3(64, 2), 256>>>(q, k, Sp, 131072);
        softmax_reduce<<<128, 32>>>(Sp, S, 32, 64, 4096);
        epilogue2_kernel<<<dim3(4096, 2), 256>>>(v, S, buf1, out, gm + 2);
    }
}

// round 5
// speedup vs baseline: 1.7173x; 1.0825x over previous
#include <cuda_runtime.h>
#include <cuda_bf16.h>
#include <cstdint>

#define NEL 33554432           // 2*256*16*64*64
#define NSP 65536               // T*W*H

// ---------------- scratch (device globals; no runtime alloc) ----------------
__device__ float g_buf0[NEL];
__device__ float g_buf1[NEL];
__device__ float g_xp[NEL];
__device__ float g_q[16777216];   // B * 128 * 65536
__device__ float g_k[8388608];    // B * 128 * 32768
__device__ float g_v[16777216];   // B * 256 * 32768
__device__ float g_Sp[262144];    // split-K partials
__device__ float g_S[4096];       // attn after softmax: B*64*32 max

// ---------------- helpers ----------------
__device__ __forceinline__ float4 ld4(const float* p) {
    return *reinterpret_cast<const float4*>(p);
}
// split float4 into packed bf16 hi pairs + bf16 lo (residual) pairs
__device__ __forceinline__ void split_f4(float4 v, uint2& h, uint2& l) {
    asm("cvt.rn.bf16x2.f32 %0, %1, %2;" : "=r"(h.x) : "f"(v.y), "f"(v.x));
    asm("cvt.rn.bf16x2.f32 %0, %1, %2;" : "=r"(h.y) : "f"(v.w), "f"(v.z));
    float rx = v.x - __uint_as_float(h.x << 16);
    float ry = v.y - __uint_as_float(h.x & 0xffff0000u);
    float rz = v.z - __uint_as_float(h.y << 16);
    float rw = v.w - __uint_as_float(h.y & 0xffff0000u);
    asm("cvt.rn.bf16x2.f32 %0, %1, %2;" : "=r"(l.x) : "f"(ry), "f"(rx));
    asm("cvt.rn.bf16x2.f32 %0, %1, %2;" : "=r"(l.y) : "f"(rw), "f"(rz));
}
__device__ __forceinline__ void ldsm4(uint32_t* r, uint32_t a) {
    asm volatile("ldmatrix.sync.aligned.m8n8.x4.shared.b16 {%0,%1,%2,%3}, [%4];"
        : "=r"(r[0]), "=r"(r[1]), "=r"(r[2]), "=r"(r[3]) : "r"(a));
}
__device__ __forceinline__ void ldsm4t(uint32_t* r, uint32_t a) {
    asm volatile("ldmatrix.sync.aligned.m8n8.x4.trans.shared.b16 {%0,%1,%2,%3}, [%4];"
        : "=r"(r[0]), "=r"(r[1]), "=r"(r[2]), "=r"(r[3]) : "r"(a));
}
__device__ __forceinline__ void mma_bf16(float* d, const uint32_t* a, const uint32_t* b) {
    asm volatile("mma.sync.aligned.m16n8k16.row.col.f32.bf16.bf16.f32 "
        "{%0,%1,%2,%3}, {%4,%5,%6,%7}, {%8,%9}, {%0,%1,%2,%3};"
        : "+f"(d[0]), "+f"(d[1]), "+f"(d[2]), "+f"(d[3])
        : "r"(a[0]), "r"(a[1]), "r"(a[2]), "r"(a[3]), "r"(b[0]), "r"(b[1]));
}

// ---------------- permute H (canonical -> [c][h][w][t]) via smem transpose ---
__global__ __launch_bounds__(256) void permuteH_kernel(
    const float* __restrict__ src, float* __restrict__ dst)
{
    __shared__ float s[16][65];
    int w = blockIdx.x;
    int c = blockIdx.y;
    int b = blockIdx.z;
    size_t base = ((size_t)b * 256 + c) * 65536;
    int tid = threadIdx.x;
    for (int idx = tid; idx < 1024; idx += 256) {
        int t = idx >> 6, h = idx & 63;
        s[t][h] = src[base + (size_t)t * 4096 + w * 64 + h];
    }
    __syncthreads();
    for (int idx = tid; idx < 1024; idx += 256) {
        int h = idx >> 4, t = idx & 15;
        dst[base + (size_t)h * 1024 + w * 16 + t] = s[t][h];
    }
}

// ---------------- bf16x3 tensor-core conv1x1 GEMM, ldmatrix, pool fused -----
// out[oc][n] = sum_c W[oc][c] * X[c][col(n)] + bias ; POOL=1: max of 2 streams
// MODE 0: X already permuted (LOGD = log2 of d for pooled column mapping)
// MODE 1: X canonical [c][t][w][h], cell-W mapping fused
template<int POOL, int MODE, int LOGD>
__global__ __launch_bounds__(256) void conv_bf16(
    const float* __restrict__ X, const float* __restrict__ Wg,
    const float* __restrict__ bias, float* __restrict__ out, int OC)
{
    constexpr int BN  = POOL ? 64 : 128;
    constexpr int NS  = POOL ? 2 : 1;     // pooled streams
    constexpr int NT  = POOL ? 4 : 8;     // n8 tiles per warp
    constexpr int PXB = POOL ? 72 : 136;  // X smem pitch (bf16 elems)
    constexpr int XT  = 32 * PXB;         // per-stream X tile elems
    constexpr int NSX = NS * XT;          // per-buffer X elems
    constexpr int WT  = 128 * 40;         // W tile elems (pitch 40)

    extern __shared__ char smem_raw[];
    __nv_bfloat16* sm  = reinterpret_cast<__nv_bfloat16*>(smem_raw);
    __nv_bfloat16* WsH = sm;                 // [2][WT]
    __nv_bfloat16* WsL = WsH + 2 * WT;
    __nv_bfloat16* XsH = WsL + 2 * WT;       // [2][NSX]
    __nv_bfloat16* XsL = XsH + 2 * NSX;

    const int Np = POOL ? 32768 : 65536;
    int b  = blockIdx.z;
    int m0 = blockIdx.y * 128;
    int n0 = blockIdx.x * BN;
    const float* Xb = X + (size_t)b * 256 * NSP;
    float* outb = out + (size_t)b * OC * Np;

    int tid  = threadIdx.x;
    int lane = tid & 31, warp = tid >> 5;
    int wm = warp & 3, wn = warp >> 2;       // 4 m-groups x 2 n-groups
    int g = lane >> 2, tg = lane & 3;

    // ---- global load coords ----
    int wrow = tid >> 3;                     // W rows wrow + 32*i
    int wcol = (tid & 7) * 4;
    int xk, xc_;
    if (POOL) { xk = tid >> 4; xc_ = (tid & 15) * 4; }
    else      { xk = tid >> 5; xc_ = (tid & 31) * 4; }

    // per-thread output-column -> source-offset mapping
    int nn = n0 + xc_;
    int src0, src1 = 0;
    if (MODE == 0) {
        if (POOL) {
            int a2 = nn >> LOGD, r = nn & ((1 << LOGD) - 1);
            src0 = ((2 * a2) << LOGD) + r;
            src1 = src0 + (1 << LOGD);
        } else src0 = nn;
    } else {  // cell W: col = a*1024 + p1*64 + p2 -> src p1*4096 + a*64 + p2
        int aa = nn >> 10, r = nn & 1023;
        if (POOL) {
            src0 = (r >> 6) * 4096 + (2 * aa) * 64 + (r & 63);
            src1 = src0 + 64;
        } else {
            src0 = (r >> 6) * 4096 + aa * 64 + (r & 63);
        }
    }

    float acc[NS][2][NT][4];
#pragma unroll
    for (int st = 0; st < NS; st++)
#pragma unroll
        for (int mt = 0; mt < 2; mt++)
#pragma unroll
            for (int nt = 0; nt < NT; nt++)
#pragma unroll
                for (int r = 0; r < 4; r++) acc[st][mt][nt][r] = 0.f;

    // ---- ldmatrix lane offsets (elements) ----
    uint32_t sb = (uint32_t)__cvta_generic_to_shared(sm);
    int aoe = (wm * 32 + (lane & 7) + (lane & 8)) * 40 + ((lane & 16) >> 1);
    int boe = ((lane & 7) + (lane & 8)) * PXB + ((lane & 16) >> 1)
            + wn * (POOL ? 32 : 64);

    uint2 wh[4], wl[4], xh[4], xl[4];

    auto LOAD = [&](int ks) {                 // k base = ks*32
#pragma unroll
        for (int i = 0; i < 4; i++) {
            float4 wv = ld4(Wg + (size_t)(m0 + wrow + i * 32) * 256 + ks * 32 + wcol);
            split_f4(wv, wh[i], wl[i]);
        }
        if (POOL) {
#pragma unroll
            for (int i = 0; i < 2; i++) {
                float4 x0 = ld4(Xb + (size_t)(ks * 32 + xk + i * 16) * NSP + src0);
                float4 x1 = ld4(Xb + (size_t)(ks * 32 + xk + i * 16) * NSP + src1);
                split_f4(x0, xh[2 * i + 0], xl[2 * i + 0]);
                split_f4(x1, xh[2 * i + 1], xl[2 * i + 1]);
            }
        } else {
#pragma unroll
            for (int i = 0; i < 4; i++) {
                float4 xv = ld4(Xb + (size_t)(ks * 32 + xk + i * 8) * NSP + src0);
                split_f4(xv, xh[i], xl[i]);
            }
        }
    };
    auto STORE = [&](int bf) {
#pragma unroll
        for (int i = 0; i < 4; i++) {
            int off = bf * WT + (wrow + i * 32) * 40 + wcol;
            *(uint2*)&WsH[off] = wh[i];
            *(uint2*)&WsL[off] = wl[i];
        }
        if (POOL) {
#pragma unroll
            for (int i = 0; i < 2; i++)
#pragma unroll
                for (int st = 0; st < 2; st++) {
                    int off = bf * NSX + st * XT + (xk + i * 16) * PXB + xc_;
                    *(uint2*)&XsH[off] = xh[2 * i + st];
                    *(uint2*)&XsL[off] = xl[2 * i + st];
                }
        } else {
#pragma unroll
            for (int i = 0; i < 4; i++) {
                int off = bf * NSX + (xk + i * 8) * PXB + xc_;
                *(uint2*)&XsH[off] = xh[i];
                *(uint2*)&XsL[off] = xl[i];
            }
        }
    };

    LOAD(0);
    STORE(0);
    __syncthreads();

#pragma unroll 1
    for (int s = 0; s < 8; s++) {
        int cb = s & 1;
        if (s < 7) LOAD(s + 1);

        uint32_t aHb = sb + (cb * WT + aoe) * 2;
        uint32_t aLb = aHb + 2 * WT * 2;
        uint32_t xHb = sb + 4 * WT * 2 + (cb * NSX + boe) * 2;
        uint32_t xLb = xHb + 2 * NSX * 2;

#pragma unroll
        for (int ks = 0; ks < 2; ks++) {
            uint32_t Ah[2][4], Al[2][4];
#pragma unroll
            for (int mt = 0; mt < 2; mt++) {
                ldsm4(Ah[mt], aHb + (ks * 16 + mt * 640) * 2);
                ldsm4(Al[mt], aLb + (ks * 16 + mt * 640) * 2);
            }
            if (!POOL) {
#pragma unroll
                for (int pp = 0; pp < 4; pp++) {
                    uint32_t Bh[4], Bl[4];
                    ldsm4t(Bh, xHb + (ks * 16 * PXB + pp * 16) * 2);
                    ldsm4t(Bl, xLb + (ks * 16 * PXB + pp * 16) * 2);
#pragma unroll
                    for (int mt = 0; mt < 2; mt++)
#pragma unroll
                        for (int sub = 0; sub < 2; sub++) {
                            float* d = acc[0][mt][pp * 2 + sub];
                            mma_bf16(d, Ah[mt], Bh + 2 * sub);
                            mma_bf16(d, Ah[mt], Bl + 2 * sub);
                            mma_bf16(d, Al[mt], Bh + 2 * sub);
                        }
                }
            } else {
#pragma unroll
                for (int st = 0; st < 2; st++)
#pragma unroll
                    for (int pp = 0; pp < 2; pp++) {
                        uint32_t Bh[4], Bl[4];
                        ldsm4t(Bh, xHb + (st * XT + ks * 16 * PXB + pp * 16) * 2);
                        ldsm4t(Bl, xLb + (st * XT + ks * 16 * PXB + pp * 16) * 2);
#pragma unroll
                        for (int mt = 0; mt < 2; mt++)
#pragma unroll
                            for (int sub = 0; sub < 2; sub++) {
                                float* d = acc[st][mt][pp * 2 + sub];
                                mma_bf16(d, Ah[mt], Bh + 2 * sub);
                                mma_bf16(d, Ah[mt], Bl + 2 * sub);
                                mma_bf16(d, Al[mt], Bh + 2 * sub);
                            }
                    }
            }
        }
        if (s < 7) STORE(1 - cb);
        __syncthreads();
    }

    // ---- epilogue: (max) + bias, float2 writes ----
#pragma unroll
    for (int mt = 0; mt < 2; mt++) {
        int r = m0 + wm * 32 + mt * 16 + g;
        float b0 = bias[r], b1 = bias[r + 8];
#pragma unroll
        for (int nt = 0; nt < NT; nt++) {
            int c = n0 + wn * (POOL ? 32 : 64) + nt * 8 + tg * 2;
            float v00, v01, v10, v11;
            if (POOL) {
                v00 = fmaxf(acc[0][mt][nt][0], acc[1][mt][nt][0]) + b0;
                v01 = fmaxf(acc[0][mt][nt][1], acc[1][mt][nt][1]) + b0;
                v10 = fmaxf(acc[0][mt][nt][2], acc[1][mt][nt][2]) + b1;
                v11 = fmaxf(acc[0][mt][nt][3], acc[1][mt][nt][3]) + b1;
            } else {
                v00 = acc[0][mt][nt][0] + b0;
                v01 = acc[0][mt][nt][1] + b0;
                v10 = acc[0][mt][nt][2] + b1;
                v11 = acc[0][mt][nt][3] + b1;
            }
            *(float2*)&outb[(size_t)r * Np + c]       = make_float2(v00, v01);
            *(float2*)&outb[(size_t)(r + 8) * Np + c] = make_float2(v10, v11);
        }
    }
}

// ---------------- attention logits, split-K partials (deterministic) --------
template<int Ac, int A2c>
__global__ __launch_bounds__(256) void attn_partial(
    const float* __restrict__ q, const float* __restrict__ k,
    float* __restrict__ Sp, int K)
{
    constexpr int NOUT = (Ac * A2c + 255) / 256;
    int b = blockIdx.y, sl = blockIdx.x;
    const float* qb = q + (size_t)b * Ac * K;
    const float* kb = k + (size_t)b * K * A2c;
    __shared__ float Qs[Ac * 32];
    __shared__ float Ks[32 * A2c];
    int tid = threadIdx.x;

    int ii[NOUT], ss[NOUT];
    bool vld[NOUT];
#pragma unroll
    for (int r = 0; r < NOUT; r++) {
        int o = tid + 256 * r;
        vld[r] = (o < Ac * A2c);
        int oc_ = vld[r] ? o : 0;
        ii[r] = oc_ / A2c;
        ss[r] = oc_ % A2c;
    }
    float acc[NOUT];
#pragma unroll
    for (int r = 0; r < NOUT; r++) acc[r] = 0.f;

    int j0 = sl * 2048;
    for (int jt = 0; jt < 2048; jt += 32) {
        int jg = j0 + jt;
        for (int idx = tid; idx < Ac * 32; idx += 256) {
            int r = idx >> 5, c = idx & 31;
            Qs[idx] = qb[(size_t)r * K + jg + c];
        }
        for (int idx = tid; idx < 32 * A2c; idx += 256)
            Ks[idx] = kb[(size_t)jg * A2c + idx];
        __syncthreads();
#pragma unroll 8
        for (int kk = 0; kk < 32; kk++) {
#pragma unroll
            for (int r = 0; r < NOUT; r++)
                acc[r] += Qs[ii[r] * 32 + kk] * Ks[kk * A2c + ss[r]];
        }
        __syncthreads();
    }
    int rowbase = b * Ac * A2c;
#pragma unroll
    for (int r = 0; r < NOUT; r++)
        if (vld[r])
            Sp[(size_t)sl * (2 * Ac * A2c) + rowbase + ii[r] * A2c + ss[r]] = acc[r];
}

// ---------------- reduce partials + softmax over A2 (one warp per row) ------
__global__ void softmax_reduce(const float* __restrict__ Sp, float* __restrict__ S,
                               int A2, int nsl, int rowtot)
{
    int row = blockIdx.x;
    int s = threadIdx.x;
    float v = 0.f;
    if (s < A2)
        for (int sl = 0; sl < nsl; sl++)
            v += Sp[(size_t)sl * rowtot + row * A2 + s];
    float vm = (s < A2) ? v : -1e30f;
#pragma unroll
    for (int off = 16; off; off >>= 1)
        vm = fmaxf(vm, __shfl_xor_sync(0xffffffffu, vm, off));
    float e = (s < A2) ? expf(v - vm) : 0.f;
    float sum = e;
#pragma unroll
    for (int off = 16; off; off >>= 1)
        sum += __shfl_xor_sync(0xffffffffu, sum, off);
    if (s < A2) S[row * A2 + s] = e / sum;
}

// ---------------- o-GEMM + un-permute + residual (cells T, W) ---------------
template<int CELL>
__global__ __launch_bounds__(256) void epilogue_kernel(
    const float* __restrict__ v, const float* __restrict__ S,
    const float* __restrict__ cur, float* __restrict__ outp,
    const float* __restrict__ gammap)
{
    constexpr int A  = (CELL == 0) ? 16 : 64;
    constexpr int A2 = (CELL == 0) ? 8 : 32;
    constexpr int d  = (CELL == 0) ? 4096 : 1024;

    int b = blockIdx.y;
    __shared__ float attnS[A * A2];
    int tid = threadIdx.x;
    for (int idx = tid; idx < A * A2; idx += 256)
        attnS[idx] = S[b * A * A2 + idx];
    __syncthreads();

    float g = gammap[0];
    int x = blockIdx.x * 256 + tid;

    const float4* vr4 = reinterpret_cast<const float4*>(
        v + (size_t)b * 8388608 + (size_t)x * A2);
    float vv[A2];
#pragma unroll
    for (int s4 = 0; s4 < A2 / 4; s4++) {
        float4 t = vr4[s4];
        vv[s4 * 4 + 0] = t.x; vv[s4 * 4 + 1] = t.y;
        vv[s4 * 4 + 2] = t.z; vv[s4 * 4 + 3] = t.w;
    }
    int c  = x / d;
    int p  = x % d;
    int p1 = p / 64;
    int p2 = p % 64;
    size_t boff = (size_t)b * 16777216 + (size_t)c * 65536;
    int base, stride;
    if (CELL == 0) { base = p1 * 64   + p2; stride = 4096; }
    else           { base = p1 * 4096 + p2; stride = 64;   }

#pragma unroll 4
    for (int a = 0; a < A; a++) {
        float o = 0.f;
#pragma unroll
        for (int s = 0; s < A2; s++) o += vv[s] * attnS[a * A2 + s];
        int off = base + a * stride;
        outp[boff + off] = g * o + cur[boff + off];
    }
}

// ---------------- cell-H epilogue: smem transpose, fully coalesced I/O ------
__global__ __launch_bounds__(256) void epilogue2_kernel(
    const float* __restrict__ v, const float* __restrict__ S,
    const float* __restrict__ cur, float* __restrict__ outp,
    const float* __restrict__ gammap)
{
    int b  = blockIdx.y;
    int cp = blockIdx.x;        // c*16 + p1
    int c = cp >> 4, p1 = cp & 15;

    __shared__ float attnS[64 * 33];
    __shared__ float vs[64 * 33];
    __shared__ float os[64 * 65];
    int tid = threadIdx.x;

    for (int i = tid; i < 2048; i += 256)
        attnS[(i >> 5) * 33 + (i & 31)] = S[b * 2048 + i];
    size_t vbase = (size_t)b * 8388608 + ((size_t)c * 1024 + p1 * 64) * 32;
    for (int i = tid; i < 2048; i += 256)
        vs[(i >> 5) * 33 + (i & 31)] = v[vbase + i];
    __syncthreads();

    int p2 = tid & 63;
    int a0 = (tid >> 6) * 16;
    float vv[32];
#pragma unroll
    for (int s = 0; s < 32; s++) vv[s] = vs[p2 * 33 + s];
#pragma unroll
    for (int ai = 0; ai < 16; ai++) {
        int a = a0 + ai;
        float o = 0.f;
#pragma unroll
        for (int s = 0; s < 32; s++) o += vv[s] * attnS[a * 33 + s];
        os[p2 * 65 + a] = o;
    }
    __syncthreads();

    float g = gammap[0];
    size_t obase = (size_t)b * 16777216 + (size_t)c * 65536 + (size_t)p1 * 4096;
    for (int i = tid; i < 4096; i += 256)
        outp[obase + i] = g * os[(i >> 6) * 65 + (i & 63)] + cur[obase + i];
}

// ---------------- host orchestration ----------------
extern "C" void kernel_launch(void* const* d_in, const int* in_sizes, int n_in,
                              void* d_out, int out_size)
{
    const float* x  = (const float*)d_in[0];
    const float* Wq = (const float*)d_in[1];
    const float* bq = (const float*)d_in[2];
    const float* Wk = (const float*)d_in[3];
    const float* bk = (const float*)d_in[4];
    const float* Wv = (const float*)d_in[5];
    const float* bv = (const float*)d_in[6];
    const float* gm = (const float*)d_in[7];
    float* out = (float*)d_out;

    float *buf0, *buf1, *xp, *q, *k, *v, *Sp, *S;
    cudaGetSymbolAddress((void**)&buf0, g_buf0);
    cudaGetSymbolAddress((void**)&buf1, g_buf1);
    cudaGetSymbolAddress((void**)&xp,   g_xp);
    cudaGetSymbolAddress((void**)&q,    g_q);
    cudaGetSymbolAddress((void**)&k,    g_k);
    cudaGetSymbolAddress((void**)&v,    g_v);
    cudaGetSymbolAddress((void**)&Sp,   g_Sp);
    cudaGetSymbolAddress((void**)&S,    g_S);

    // dynamic smem: W 40960 B + X (8*NSX) B
    const int SM_NP = 40960 + 8 * (32 * 136);   // non-pool: 75776
    const int SM_P  = 40960 + 8 * (2 * 32 * 72); // pool: 77824

    cudaFuncSetAttribute(conv_bf16<0,0,0>,  cudaFuncAttributeMaxDynamicSharedMemorySize, SM_NP);
    cudaFuncSetAttribute(conv_bf16<0,1,0>,  cudaFuncAttributeMaxDynamicSharedMemorySize, SM_NP);
    cudaFuncSetAttribute(conv_bf16<1,0,12>, cudaFuncAttributeMaxDynamicSharedMemorySize, SM_P);
    cudaFuncSetAttribute(conv_bf16<1,0,10>, cudaFuncAttributeMaxDynamicSharedMemorySize, SM_P);
    cudaFuncSetAttribute(conv_bf16<1,1,10>, cudaFuncAttributeMaxDynamicSharedMemorySize, SM_P);

    // ================= cell 0 : attention over T (identity permutation) ======
    {
        conv_bf16<0,0,0> <<<dim3(512, 1, 2), 256, SM_NP>>>(x, Wq, bq, q, 128);
        conv_bf16<1,0,12><<<dim3(512, 1, 2), 256, SM_P >>>(x, Wk, bk, k, 128);
        conv_bf16<1,0,12><<<dim3(512, 2, 2), 256, SM_P >>>(x, Wv, bv, v, 256);
        attn_partial<16, 8><<<dim3(256, 2), 256>>>(q, k, Sp, 524288);
        softmax_reduce<<<32, 32>>>(Sp, S, 8, 256, 256);
        epilogue_kernel<0><<<dim3(4096, 2), 256>>>(v, S, x, buf0, gm + 0);
    }
    // ================= cell 1 : attention over W (fused permute in conv) =====
    {
        conv_bf16<0,1,0> <<<dim3(512, 1, 2), 256, SM_NP>>>(buf0, Wq + 32768, bq + 128, q, 128);
        conv_bf16<1,1,10><<<dim3(512, 1, 2), 256, SM_P >>>(buf0, Wk + 32768, bk + 128, k, 128);
        conv_bf16<1,1,10><<<dim3(512, 2, 2), 256, SM_P >>>(buf0, Wv + 65536, bv + 256, v, 256);
        attn_partial<64, 32><<<dim3(64, 2), 256>>>(q, k, Sp, 131072);
        softmax_reduce<<<128, 32>>>(Sp, S, 32, 64, 4096);
        epilogue_kernel<1><<<dim3(1024, 2), 256>>>(v, S, buf0, buf1, gm + 1);
    }
    // ================= cell 2 : attention over H ==============================
    {
        permuteH_kernel<<<dim3(64, 256, 2), 256>>>(buf1, xp);
        conv_bf16<0,0,0> <<<dim3(512, 1, 2), 256, SM_NP>>>(xp, Wq + 65536, bq + 256, q, 128);
        conv_bf16<1,0,10><<<dim3(512, 1, 2), 256, SM_P >>>(xp, Wk + 65536, bk + 256, k, 128);
        conv_bf16<1,0,10><<<dim3(512, 2, 2), 256, SM_P >>>(xp, Wv + 131072, bv + 512, v, 256);
        attn_partial<64, 32><<<dim3(64, 2), 256>>>(q, k, Sp, 131072);
        softmax_reduce<<<128, 32>>>(Sp, S, 32, 64, 4096);
        epilogue2_kernel<<<dim3(4096, 2), 256>>>(v, S, buf1, out, gm + 2);
    }
}

// round 6
// speedup vs baseline: 2.2237x; 1.2948x over previous
#include <cuda_runtime.h>
#include <cuda_bf16.h>
#include <cstdint>

#define NEL 33554432           // 2*256*16*64*64
#define NSP 65536               // T*W*H

// ---------------- scratch (device globals; no runtime alloc) ----------------
__device__ float g_buf0[NEL];
__device__ float g_buf1[NEL];
__device__ float g_xp[NEL];
__device__ float g_q[16777216];   // B * 128 * 65536
__device__ float g_k[8388608];    // B * 128 * 32768
__device__ float g_v[16777216];   // B * 256 * 32768
__device__ float g_Sp[1048576];   // split-K partials (256 slices * 4096)
__device__ float g_S[4096];       // attn after softmax: B*64*32 max

// ---------------- helpers ----------------
__device__ __forceinline__ float4 ld4(const float* p) {
    return *reinterpret_cast<const float4*>(p);
}
// split float4 into packed bf16 hi pairs + bf16 lo (residual) pairs
__device__ __forceinline__ void split_f4(float4 v, uint2& h, uint2& l) {
    asm("cvt.rn.bf16x2.f32 %0, %1, %2;" : "=r"(h.x) : "f"(v.y), "f"(v.x));
    asm("cvt.rn.bf16x2.f32 %0, %1, %2;" : "=r"(h.y) : "f"(v.w), "f"(v.z));
    float rx = v.x - __uint_as_float(h.x << 16);
    float ry = v.y - __uint_as_float(h.x & 0xffff0000u);
    float rz = v.z - __uint_as_float(h.y << 16);
    float rw = v.w - __uint_as_float(h.y & 0xffff0000u);
    asm("cvt.rn.bf16x2.f32 %0, %1, %2;" : "=r"(l.x) : "f"(ry), "f"(rx));
    asm("cvt.rn.bf16x2.f32 %0, %1, %2;" : "=r"(l.y) : "f"(rw), "f"(rz));
}
__device__ __forceinline__ void ldsm4(uint32_t* r, uint32_t a) {
    asm volatile("ldmatrix.sync.aligned.m8n8.x4.shared.b16 {%0,%1,%2,%3}, [%4];"
        : "=r"(r[0]), "=r"(r[1]), "=r"(r[2]), "=r"(r[3]) : "r"(a));
}
__device__ __forceinline__ void ldsm4t(uint32_t* r, uint32_t a) {
    asm volatile("ldmatrix.sync.aligned.m8n8.x4.trans.shared.b16 {%0,%1,%2,%3}, [%4];"
        : "=r"(r[0]), "=r"(r[1]), "=r"(r[2]), "=r"(r[3]) : "r"(a));
}
__device__ __forceinline__ void ldsm2t(uint32_t* r, uint32_t a) {
    asm volatile("ldmatrix.sync.aligned.m8n8.x2.trans.shared.b16 {%0,%1}, [%2];"
        : "=r"(r[0]), "=r"(r[1]) : "r"(a));
}
__device__ __forceinline__ void mma_bf16(float* d, const uint32_t* a, const uint32_t* b) {
    asm volatile("mma.sync.aligned.m16n8k16.row.col.f32.bf16.bf16.f32 "
        "{%0,%1,%2,%3}, {%4,%5,%6,%7}, {%8,%9}, {%0,%1,%2,%3};"
        : "+f"(d[0]), "+f"(d[1]), "+f"(d[2]), "+f"(d[3])
        : "r"(a[0]), "r"(a[1]), "r"(a[2]), "r"(a[3]), "r"(b[0]), "r"(b[1]));
}

// ---------------- permute H (canonical -> [c][h][w][t]) via smem transpose ---
__global__ __launch_bounds__(256) void permuteH_kernel(
    const float* __restrict__ src, float* __restrict__ dst)
{
    __shared__ float s[16][65];
    int w = blockIdx.x;
    int c = blockIdx.y;
    int b = blockIdx.z;
    size_t base = ((size_t)b * 256 + c) * 65536;
    int tid = threadIdx.x;
    for (int idx = tid; idx < 1024; idx += 256) {
        int t = idx >> 6, h = idx & 63;
        s[t][h] = src[base + (size_t)t * 4096 + w * 64 + h];
    }
    __syncthreads();
    for (int idx = tid; idx < 1024; idx += 256) {
        int h = idx >> 4, t = idx & 15;
        dst[base + (size_t)h * 1024 + w * 16 + t] = s[t][h];
    }
}

// ---------------- bf16x3 tensor-core conv1x1 GEMM, ldmatrix, pool fused -----
template<int POOL, int MODE, int LOGD>
__global__ __launch_bounds__(256) void conv_bf16(
    const float* __restrict__ X, const float* __restrict__ Wg,
    const float* __restrict__ bias, float* __restrict__ out, int OC)
{
    constexpr int BN  = POOL ? 64 : 128;
    constexpr int NS  = POOL ? 2 : 1;     // pooled streams
    constexpr int NT  = POOL ? 4 : 8;     // n8 tiles per warp
    constexpr int PXB = POOL ? 72 : 136;  // X smem pitch (bf16 elems)
    constexpr int XT  = 32 * PXB;         // per-stream X tile elems
    constexpr int NSX = NS * XT;          // per-buffer X elems
    constexpr int WT  = 128 * 40;         // W tile elems (pitch 40)

    extern __shared__ char smem_raw[];
    __nv_bfloat16* sm  = reinterpret_cast<__nv_bfloat16*>(smem_raw);
    __nv_bfloat16* WsH = sm;                 // [2][WT]
    __nv_bfloat16* WsL = WsH + 2 * WT;
    __nv_bfloat16* XsH = WsL + 2 * WT;       // [2][NSX]
    __nv_bfloat16* XsL = XsH + 2 * NSX;

    const int Np = POOL ? 32768 : 65536;
    int b  = blockIdx.z;
    int m0 = blockIdx.y * 128;
    int n0 = blockIdx.x * BN;
    const float* Xb = X + (size_t)b * 256 * NSP;
    float* outb = out + (size_t)b * OC * Np;

    int tid  = threadIdx.x;
    int lane = tid & 31, warp = tid >> 5;
    int wm = warp & 3, wn = warp >> 2;       // 4 m-groups x 2 n-groups
    int g = lane >> 2, tg = lane & 3;

    int wrow = tid >> 3;
    int wcol = (tid & 7) * 4;
    int xk, xc_;
    if (POOL) { xk = tid >> 4; xc_ = (tid & 15) * 4; }
    else      { xk = tid >> 5; xc_ = (tid & 31) * 4; }

    int nn = n0 + xc_;
    int src0, src1 = 0;
    if (MODE == 0) {
        if (POOL) {
            int a2 = nn >> LOGD, r = nn & ((1 << LOGD) - 1);
            src0 = ((2 * a2) << LOGD) + r;
            src1 = src0 + (1 << LOGD);
        } else src0 = nn;
    } else {
        int aa = nn >> 10, r = nn & 1023;
        if (POOL) {
            src0 = (r >> 6) * 4096 + (2 * aa) * 64 + (r & 63);
            src1 = src0 + 64;
        } else {
            src0 = (r >> 6) * 4096 + aa * 64 + (r & 63);
        }
    }

    float acc[NS][2][NT][4];
#pragma unroll
    for (int st = 0; st < NS; st++)
#pragma unroll
        for (int mt = 0; mt < 2; mt++)
#pragma unroll
            for (int nt = 0; nt < NT; nt++)
#pragma unroll
                for (int r = 0; r < 4; r++) acc[st][mt][nt][r] = 0.f;

    uint32_t sb = (uint32_t)__cvta_generic_to_shared(sm);
    int aoe = (wm * 32 + (lane & 7) + (lane & 8)) * 40 + ((lane & 16) >> 1);
    int boe = ((lane & 7) + (lane & 8)) * PXB + ((lane & 16) >> 1)
            + wn * (POOL ? 32 : 64);

    uint2 wh[4], wl[4], xh[4], xl[4];

    auto LOAD = [&](int ks) {
#pragma unroll
        for (int i = 0; i < 4; i++) {
            float4 wv = ld4(Wg + (size_t)(m0 + wrow + i * 32) * 256 + ks * 32 + wcol);
            split_f4(wv, wh[i], wl[i]);
        }
        if (POOL) {
#pragma unroll
            for (int i = 0; i < 2; i++) {
                float4 x0 = ld4(Xb + (size_t)(ks * 32 + xk + i * 16) * NSP + src0);
                float4 x1 = ld4(Xb + (size_t)(ks * 32 + xk + i * 16) * NSP + src1);
                split_f4(x0, xh[2 * i + 0], xl[2 * i + 0]);
                split_f4(x1, xh[2 * i + 1], xl[2 * i + 1]);
            }
        } else {
#pragma unroll
            for (int i = 0; i < 4; i++) {
                float4 xv = ld4(Xb + (size_t)(ks * 32 + xk + i * 8) * NSP + src0);
                split_f4(xv, xh[i], xl[i]);
            }
        }
    };
    auto STORE = [&](int bf) {
#pragma unroll
        for (int i = 0; i < 4; i++) {
            int off = bf * WT + (wrow + i * 32) * 40 + wcol;
            *(uint2*)&WsH[off] = wh[i];
            *(uint2*)&WsL[off] = wl[i];
        }
        if (POOL) {
#pragma unroll
            for (int i = 0; i < 2; i++)
#pragma unroll
                for (int st = 0; st < 2; st++) {
                    int off = bf * NSX + st * XT + (xk + i * 16) * PXB + xc_;
                    *(uint2*)&XsH[off] = xh[2 * i + st];
                    *(uint2*)&XsL[off] = xl[2 * i + st];
                }
        } else {
#pragma unroll
            for (int i = 0; i < 4; i++) {
                int off = bf * NSX + (xk + i * 8) * PXB + xc_;
                *(uint2*)&XsH[off] = xh[i];
                *(uint2*)&XsL[off] = xl[i];
            }
        }
    };

    LOAD(0);
    STORE(0);
    __syncthreads();

#pragma unroll 1
    for (int s = 0; s < 8; s++) {
        int cb = s & 1;
        if (s < 7) LOAD(s + 1);

        uint32_t aHb = sb + (cb * WT + aoe) * 2;
        uint32_t aLb = aHb + 2 * WT * 2;
        uint32_t xHb = sb + 4 * WT * 2 + (cb * NSX + boe) * 2;
        uint32_t xLb = xHb + 2 * NSX * 2;

#pragma unroll
        for (int ks = 0; ks < 2; ks++) {
            uint32_t Ah[2][4], Al[2][4];
#pragma unroll
            for (int mt = 0; mt < 2; mt++) {
                ldsm4(Ah[mt], aHb + (ks * 16 + mt * 640) * 2);
                ldsm4(Al[mt], aLb + (ks * 16 + mt * 640) * 2);
            }
            if (!POOL) {
#pragma unroll
                for (int pp = 0; pp < 4; pp++) {
                    uint32_t Bh[4], Bl[4];
                    ldsm4t(Bh, xHb + (ks * 16 * PXB + pp * 16) * 2);
                    ldsm4t(Bl, xLb + (ks * 16 * PXB + pp * 16) * 2);
#pragma unroll
                    for (int mt = 0; mt < 2; mt++)
#pragma unroll
                        for (int sub = 0; sub < 2; sub++) {
                            float* d = acc[0][mt][pp * 2 + sub];
                            mma_bf16(d, Ah[mt], Bh + 2 * sub);
                            mma_bf16(d, Ah[mt], Bl + 2 * sub);
                            mma_bf16(d, Al[mt], Bh + 2 * sub);
                        }
                }
            } else {
#pragma unroll
                for (int st = 0; st < 2; st++)
#pragma unroll
                    for (int pp = 0; pp < 2; pp++) {
                        uint32_t Bh[4], Bl[4];
                        ldsm4t(Bh, xHb + (st * XT + ks * 16 * PXB + pp * 16) * 2);
                        ldsm4t(Bl, xLb + (st * XT + ks * 16 * PXB + pp * 16) * 2);
#pragma unroll
                        for (int mt = 0; mt < 2; mt++)
#pragma unroll
                            for (int sub = 0; sub < 2; sub++) {
                                float* d = acc[st][mt][pp * 2 + sub];
                                mma_bf16(d, Ah[mt], Bh + 2 * sub);
                                mma_bf16(d, Ah[mt], Bl + 2 * sub);
                                mma_bf16(d, Al[mt], Bh + 2 * sub);
                            }
                    }
            }
        }
        if (s < 7) STORE(1 - cb);
        __syncthreads();
    }

#pragma unroll
    for (int mt = 0; mt < 2; mt++) {
        int r = m0 + wm * 32 + mt * 16 + g;
        float b0 = bias[r], b1 = bias[r + 8];
#pragma unroll
        for (int nt = 0; nt < NT; nt++) {
            int c = n0 + wn * (POOL ? 32 : 64) + nt * 8 + tg * 2;
            float v00, v01, v10, v11;
            if (POOL) {
                v00 = fmaxf(acc[0][mt][nt][0], acc[1][mt][nt][0]) + b0;
                v01 = fmaxf(acc[0][mt][nt][1], acc[1][mt][nt][1]) + b0;
                v10 = fmaxf(acc[0][mt][nt][2], acc[1][mt][nt][2]) + b1;
                v11 = fmaxf(acc[0][mt][nt][3], acc[1][mt][nt][3]) + b1;
            } else {
                v00 = acc[0][mt][nt][0] + b0;
                v01 = acc[0][mt][nt][1] + b0;
                v10 = acc[0][mt][nt][2] + b1;
                v11 = acc[0][mt][nt][3] + b1;
            }
            *(float2*)&outb[(size_t)r * Np + c]       = make_float2(v00, v01);
            *(float2*)&outb[(size_t)(r + 8) * Np + c] = make_float2(v10, v11);
        }
    }
}

// ---------------- attention logits: bf16x3 tensor-core streaming GEMM -------
// CELL0=1: M=16,N=8,K=524288 ; CELL0=0: M=64,N=32,K=131072. 256 slices.
template<int CELL0>
__global__ __launch_bounds__(256) void attn_mma(
    const float* __restrict__ q, const float* __restrict__ k,
    float* __restrict__ Sp)
{
    constexpr int Ac  = CELL0 ? 16 : 64;
    constexpr int A2c = CELL0 ? 8  : 32;
    constexpr int K   = CELL0 ? 524288 : 131072;
    constexpr int KSL = K / 256;            // 2048 | 512
    constexpr int CJ  = CELL0 ? 128 : 64;   // j per chunk
    constexpr int NCH = KSL / CJ;           // 16 | 8
    constexpr int PQ  = CELL0 ? 136 : 72;
    constexpr int PK  = CELL0 ? 8 : 40;
    constexpr int QT  = Ac * PQ;
    constexpr int KT  = CJ * PK;
    constexpr int NQ  = CELL0 ? 2 : 4;      // q float4 loads / thread / chunk
    constexpr int NK  = CELL0 ? 1 : 2;

    extern __shared__ __nv_bfloat16 smb[];
    __nv_bfloat16 *QH = smb, *QL = QH + 2 * QT, *KH = QL + 2 * QT, *KL = KH + 2 * KT;

    int b = blockIdx.y, sl = blockIdx.x;
    const float* qb = q + (size_t)b * Ac * K + (size_t)sl * KSL;
    const float* kb = k + ((size_t)b * K + (size_t)sl * KSL) * A2c;

    int tid = threadIdx.x, lane = tid & 31, warp = tid >> 5;
    int g = lane >> 2, tg = lane & 3;

    float4 qv[NQ], kv[NK];
    auto LOAD = [&](int ch) {
        int j0 = ch * CJ;
#pragma unroll
        for (int l = 0; l < NQ; l++) {
            int idx = tid + 256 * l;
            int row = CELL0 ? (idx >> 5) : (idx >> 4);
            int c   = CELL0 ? ((idx & 31) * 4) : ((idx & 15) * 4);
            qv[l] = ld4(qb + (size_t)row * K + j0 + c);
        }
#pragma unroll
        for (int l = 0; l < NK; l++) {
            int idx = tid + 256 * l;
            int row = CELL0 ? (idx >> 1) : (idx >> 3);
            int c   = CELL0 ? ((idx & 1) * 4) : ((idx & 7) * 4);
            kv[l] = ld4(kb + (size_t)(j0 + row) * A2c + c);
        }
    };
    auto STORE = [&](int bf) {
#pragma unroll
        for (int l = 0; l < NQ; l++) {
            int idx = tid + 256 * l;
            int row = CELL0 ? (idx >> 5) : (idx >> 4);
            int c   = CELL0 ? ((idx & 31) * 4) : ((idx & 15) * 4);
            uint2 h, lo;
            split_f4(qv[l], h, lo);
            int off = bf * QT + row * PQ + c;
            *(uint2*)&QH[off] = h;
            *(uint2*)&QL[off] = lo;
        }
#pragma unroll
        for (int l = 0; l < NK; l++) {
            int idx = tid + 256 * l;
            int row = CELL0 ? (idx >> 1) : (idx >> 3);
            int c   = CELL0 ? ((idx & 1) * 4) : ((idx & 7) * 4);
            uint2 h, lo;
            split_f4(kv[l], h, lo);
            int off = bf * KT + row * PK + c;
            *(uint2*)&KH[off] = h;
            *(uint2*)&KL[off] = lo;
        }
    };

    uint32_t sb = (uint32_t)__cvta_generic_to_shared(smb);
    int r8 = (lane & 7) + (lane & 8);
    int aoe, boe, wm = warp & 3, wn = warp >> 2;
    if (CELL0) {
        aoe = r8 * PQ + ((lane & 16) >> 1) + warp * 16;
        boe = (warp * 16 + (lane & 15)) * PK;
    } else {
        aoe = (wm * 16 + r8) * PQ + ((lane & 16) >> 1);
        boe = r8 * PK + ((lane & 16) >> 1) + wn * 16;
    }
    constexpr int NACC = CELL0 ? 1 : 2;
    float acc[NACC][4];
#pragma unroll
    for (int a = 0; a < NACC; a++)
#pragma unroll
        for (int r = 0; r < 4; r++) acc[a][r] = 0.f;

    LOAD(0);
    STORE(0);
    __syncthreads();

#pragma unroll 1
    for (int ch = 0; ch < NCH; ch++) {
        int cb = ch & 1;
        if (ch < NCH - 1) LOAD(ch + 1);
        uint32_t qh = sb + (cb * QT + aoe) * 2;
        uint32_t ql = qh + 2 * QT * 2;
        uint32_t kh = sb + 4 * QT * 2 + (cb * KT + boe) * 2;
        uint32_t kl = kh + 2 * KT * 2;
        if (CELL0) {
            uint32_t Ah[4], Al[4], Bh[2], Bl[2];
            ldsm4(Ah, qh); ldsm4(Al, ql);
            ldsm2t(Bh, kh); ldsm2t(Bl, kl);
            mma_bf16(acc[0], Ah, Bh);
            mma_bf16(acc[0], Ah, Bl);
            mma_bf16(acc[0], Al, Bh);
        } else {
#pragma unroll
            for (int ks = 0; ks < 4; ks++) {
                uint32_t Ah[4], Al[4], Bh[4], Bl[4];
                ldsm4(Ah, qh + ks * 32);
                ldsm4(Al, ql + ks * 32);
                ldsm4t(Bh, kh + ks * 16 * PK * 2);
                ldsm4t(Bl, kl + ks * 16 * PK * 2);
#pragma unroll
                for (int sub = 0; sub < 2; sub++) {
                    mma_bf16(acc[sub], Ah, Bh + 2 * sub);
                    mma_bf16(acc[sub], Ah, Bl + 2 * sub);
                    mma_bf16(acc[sub], Al, Bh + 2 * sub);
                }
            }
        }
        if (ch < NCH - 1) STORE(1 - cb);
        __syncthreads();
    }

    if (CELL0) {
        float* red = reinterpret_cast<float*>(smb);
        red[warp * 128 + g * 8 + 2 * tg]           = acc[0][0];
        red[warp * 128 + g * 8 + 2 * tg + 1]       = acc[0][1];
        red[warp * 128 + (g + 8) * 8 + 2 * tg]     = acc[0][2];
        red[warp * 128 + (g + 8) * 8 + 2 * tg + 1] = acc[0][3];
        __syncthreads();
        if (tid < 128) {
            float sum = 0.f;
#pragma unroll
            for (int w = 0; w < 8; w++) sum += red[w * 128 + tid];
            Sp[(size_t)sl * 256 + b * 128 + tid] = sum;
        }
    } else {
        size_t base = (size_t)sl * 4096 + b * 2048;
#pragma unroll
        for (int sub = 0; sub < 2; sub++) {
            int s0 = wn * 16 + sub * 8 + 2 * tg;
            int i0 = wm * 16 + g;
            Sp[base + i0 * 32 + s0]           = acc[sub][0];
            Sp[base + i0 * 32 + s0 + 1]       = acc[sub][1];
            Sp[base + (i0 + 8) * 32 + s0]     = acc[sub][2];
            Sp[base + (i0 + 8) * 32 + s0 + 1] = acc[sub][3];
        }
    }
}

// ---------------- reduce partials + softmax over A2 (one warp per row) ------
__global__ __launch_bounds__(256) void softmax_reduce(
    const float* __restrict__ Sp, float* __restrict__ S,
    int A2, int nsl, int rowtot)
{
    int row = blockIdx.x * 8 + (threadIdx.x >> 5);
    int s = threadIdx.x & 31;
    float v = 0.f;
    if (s < A2) {
        for (int sl = 0; sl < nsl; sl += 4) {
            v += Sp[(size_t)(sl + 0) * rowtot + row * A2 + s]
               + Sp[(size_t)(sl + 1) * rowtot + row * A2 + s]
               + Sp[(size_t)(sl + 2) * rowtot + row * A2 + s]
               + Sp[(size_t)(sl + 3) * rowtot + row * A2 + s];
        }
    }
    float vm = (s < A2) ? v : -1e30f;
#pragma unroll
    for (int off = 16; off; off >>= 1)
        vm = fmaxf(vm, __shfl_xor_sync(0xffffffffu, vm, off));
    float e = (s < A2) ? expf(v - vm) : 0.f;
    float sum = e;
#pragma unroll
    for (int off = 16; off; off >>= 1)
        sum += __shfl_xor_sync(0xffffffffu, sum, off);
    if (s < A2) S[row * A2 + s] = e / sum;
}

// ---------------- o-GEMM + un-permute + residual (cells T, W) ---------------
template<int CELL>
__global__ __launch_bounds__(256) void epilogue_kernel(
    const float* __restrict__ v, const float* __restrict__ S,
    const float* __restrict__ cur, float* __restrict__ outp,
    const float* __restrict__ gammap)
{
    constexpr int A  = (CELL == 0) ? 16 : 64;
    constexpr int A2 = (CELL == 0) ? 8 : 32;
    constexpr int d  = (CELL == 0) ? 4096 : 1024;

    int b = blockIdx.y;
    __shared__ float attnS[A * A2];
    int tid = threadIdx.x;
    for (int idx = tid; idx < A * A2; idx += 256)
        attnS[idx] = S[b * A * A2 + idx];
    __syncthreads();

    float g = gammap[0];
    int x = blockIdx.x * 256 + tid;

    const float4* vr4 = reinterpret_cast<const float4*>(
        v + (size_t)b * 8388608 + (size_t)x * A2);
    float vv[A2];
#pragma unroll
    for (int s4 = 0; s4 < A2 / 4; s4++) {
        float4 t = vr4[s4];
        vv[s4 * 4 + 0] = t.x; vv[s4 * 4 + 1] = t.y;
        vv[s4 * 4 + 2] = t.z; vv[s4 * 4 + 3] = t.w;
    }
    int c  = x / d;
    int p  = x % d;
    int p1 = p / 64;
    int p2 = p % 64;
    size_t boff = (size_t)b * 16777216 + (size_t)c * 65536;
    int base, stride;
    if (CELL == 0) { base = p1 * 64   + p2; stride = 4096; }
    else           { base = p1 * 4096 + p2; stride = 64;   }

#pragma unroll 4
    for (int a = 0; a < A; a++) {
        float o = 0.f;
#pragma unroll
        for (int s = 0; s < A2; s++) o += vv[s] * attnS[a * A2 + s];
        int off = base + a * stride;
        outp[boff + off] = g * o + cur[boff + off];
    }
}

// ---------------- cell-H epilogue: smem transpose, fully coalesced I/O ------
__global__ __launch_bounds__(256) void epilogue2_kernel(
    const float* __restrict__ v, const float* __restrict__ S,
    const float* __restrict__ cur, float* __restrict__ outp,
    const float* __restrict__ gammap)
{
    int b  = blockIdx.y;
    int cp = blockIdx.x;        // c*16 + p1
    int c = cp >> 4, p1 = cp & 15;

    __shared__ float attnS[64 * 33];
    __shared__ float vs[64 * 33];
    __shared__ float os[64 * 65];
    int tid = threadIdx.x;

    for (int i = tid; i < 2048; i += 256)
        attnS[(i >> 5) * 33 + (i & 31)] = S[b * 2048 + i];
    size_t vbase = (size_t)b * 8388608 + ((size_t)c * 1024 + p1 * 64) * 32;
    for (int i = tid; i < 2048; i += 256)
        vs[(i >> 5) * 33 + (i & 31)] = v[vbase + i];
    __syncthreads();

    int p2 = tid & 63;
    int a0 = (tid >> 6) * 16;
    float vv[32];
#pragma unroll
    for (int s = 0; s < 32; s++) vv[s] = vs[p2 * 33 + s];
#pragma unroll
    for (int ai = 0; ai < 16; ai++) {
        int a = a0 + ai;
        float o = 0.f;
#pragma unroll
        for (int s = 0; s < 32; s++) o += vv[s] * attnS[a * 33 + s];
        os[p2 * 65 + a] = o;
    }
    __syncthreads();

    float g = gammap[0];
    size_t obase = (size_t)b * 16777216 + (size_t)c * 65536 + (size_t)p1 * 4096;
    for (int i = tid; i < 4096; i += 256)
        outp[obase + i] = g * os[(i >> 6) * 65 + (i & 63)] + cur[obase + i];
}

// ---------------- host orchestration ----------------
extern "C" void kernel_launch(void* const* d_in, const int* in_sizes, int n_in,
                              void* d_out, int out_size)
{
    const float* x  = (const float*)d_in[0];
    const float* Wq = (const float*)d_in[1];
    const float* bq = (const float*)d_in[2];
    const float* Wk = (const float*)d_in[3];
    const float* bk = (const float*)d_in[4];
    const float* Wv = (const float*)d_in[5];
    const float* bv = (const float*)d_in[6];
    const float* gm = (const float*)d_in[7];
    float* out = (float*)d_out;

    float *buf0, *buf1, *xp, *q, *k, *v, *Sp, *S;
    cudaGetSymbolAddress((void**)&buf0, g_buf0);
    cudaGetSymbolAddress((void**)&buf1, g_buf1);
    cudaGetSymbolAddress((void**)&xp,   g_xp);
    cudaGetSymbolAddress((void**)&q,    g_q);
    cudaGetSymbolAddress((void**)&k,    g_k);
    cudaGetSymbolAddress((void**)&v,    g_v);
    cudaGetSymbolAddress((void**)&Sp,   g_Sp);
    cudaGetSymbolAddress((void**)&S,    g_S);

    const int SM_NP = 40960 + 8 * (32 * 136);    // conv non-pool
    const int SM_P  = 40960 + 8 * (2 * 32 * 72); // conv pool
    const int SM_A0 = (2 * 2176 + 2 * 2176 + 2 * 1024 + 2 * 1024) * 2;  // 25600
    const int SM_A1 = (2 * 4608 + 2 * 4608 + 2 * 2560 + 2 * 2560) * 2;  // 57344

    cudaFuncSetAttribute(conv_bf16<0,0,0>,  cudaFuncAttributeMaxDynamicSharedMemorySize, SM_NP);
    cudaFuncSetAttribute(conv_bf16<0,1,0>,  cudaFuncAttributeMaxDynamicSharedMemorySize, SM_NP);
    cudaFuncSetAttribute(conv_bf16<1,0,12>, cudaFuncAttributeMaxDynamicSharedMemorySize, SM_P);
    cudaFuncSetAttribute(conv_bf16<1,0,10>, cudaFuncAttributeMaxDynamicSharedMemorySize, SM_P);
    cudaFuncSetAttribute(conv_bf16<1,1,10>, cudaFuncAttributeMaxDynamicSharedMemorySize, SM_P);
    cudaFuncSetAttribute(attn_mma<1>, cudaFuncAttributeMaxDynamicSharedMemorySize, SM_A0);
    cudaFuncSetAttribute(attn_mma<0>, cudaFuncAttributeMaxDynamicSharedMemorySize, SM_A1);

    // ================= cell 0 : attention over T (identity permutation) ======
    {
        conv_bf16<0,0,0> <<<dim3(512, 1, 2), 256, SM_NP>>>(x, Wq, bq, q, 128);
        conv_bf16<1,0,12><<<dim3(512, 1, 2), 256, SM_P >>>(x, Wk, bk, k, 128);
        conv_bf16<1,0,12><<<dim3(512, 2, 2), 256, SM_P >>>(x, Wv, bv, v, 256);
        attn_mma<1><<<dim3(256, 2), 256, SM_A0>>>(q, k, Sp);
        softmax_reduce<<<4, 256>>>(Sp, S, 8, 256, 256);
        epilogue_kernel<0><<<dim3(4096, 2), 256>>>(v, S, x, buf0, gm + 0);
    }
    // ================= cell 1 : attention over W (fused permute in conv) =====
    {
        conv_bf16<0,1,0> <<<dim3(512, 1, 2), 256, SM_NP>>>(buf0, Wq + 32768, bq + 128, q, 128);
        conv_bf16<1,1,10><<<dim3(512, 1, 2), 256, SM_P >>>(buf0, Wk + 32768, bk + 128, k, 128);
        conv_bf16<1,1,10><<<dim3(512, 2, 2), 256, SM_P >>>(buf0, Wv + 65536, bv + 256, v, 256);
        attn_mma<0><<<dim3(256, 2), 256, SM_A1>>>(q, k, Sp);
        softmax_reduce<<<16, 256>>>(Sp, S, 32, 256, 4096);
        epilogue_kernel<1><<<dim3(1024, 2), 256>>>(v, S, buf0, buf1, gm + 1);
    }
    // ================= cell 2 : attention over H ==============================
    {
        permuteH_kernel<<<dim3(64, 256, 2), 256>>>(buf1, xp);
        conv_bf16<0,0,0> <<<dim3(512, 1, 2), 256, SM_NP>>>(xp, Wq + 65536, bq + 256, q, 128);
        conv_bf16<1,0,10><<<dim3(512, 1, 2), 256, SM_P >>>(xp, Wk + 65536, bk + 256, k, 128);
        conv_bf16<1,0,10><<<dim3(512, 2, 2), 256, SM_P >>>(xp, Wv + 131072, bv + 512, v, 256);
        attn_mma<0><<<dim3(256, 2), 256, SM_A1>>>(q, k, Sp);
        softmax_reduce<<<16, 256>>>(Sp, S, 32, 256, 4096);
        epilogue2_kernel<<<dim3(4096, 2), 256>>>(v, S, buf1, out, gm + 2);
    }
}

// round 7
// speedup vs baseline: 2.8911x; 1.3001x over previous
#include <cuda_runtime.h>
#include <cuda_bf16.h>
#include <cstdint>

#define NEL 33554432           // 2*256*16*64*64
#define NSP 65536               // T*W*H

// ---------------- scratch (device globals; no runtime alloc) ----------------
__device__ float g_buf0[NEL];
__device__ float g_buf1[NEL];
__device__ float g_xp[NEL];
__device__ float g_q[16777216];   // B * 128 * 65536
__device__ float g_k[8388608];    // B * 128 * 32768
__device__ float g_v[16777216];   // B * 256 * 32768
__device__ float g_Sp[1048576];   // split-K partials (256 slices * 4096)
__device__ float g_S[4096];       // attn after softmax: B*64*32 max

// ---------------- helpers ----------------
__device__ __forceinline__ float4 ld4(const float* p) {
    return *reinterpret_cast<const float4*>(p);
}
__device__ __forceinline__ void split_f4(float4 v, uint2& h, uint2& l) {
    asm("cvt.rn.bf16x2.f32 %0, %1, %2;" : "=r"(h.x) : "f"(v.y), "f"(v.x));
    asm("cvt.rn.bf16x2.f32 %0, %1, %2;" : "=r"(h.y) : "f"(v.w), "f"(v.z));
    float rx = v.x - __uint_as_float(h.x << 16);
    float ry = v.y - __uint_as_float(h.x & 0xffff0000u);
    float rz = v.z - __uint_as_float(h.y << 16);
    float rw = v.w - __uint_as_float(h.y & 0xffff0000u);
    asm("cvt.rn.bf16x2.f32 %0, %1, %2;" : "=r"(l.x) : "f"(ry), "f"(rx));
    asm("cvt.rn.bf16x2.f32 %0, %1, %2;" : "=r"(l.y) : "f"(rw), "f"(rz));
}
__device__ __forceinline__ void ldsm4(uint32_t* r, uint32_t a) {
    asm volatile("ldmatrix.sync.aligned.m8n8.x4.shared.b16 {%0,%1,%2,%3}, [%4];"
        : "=r"(r[0]), "=r"(r[1]), "=r"(r[2]), "=r"(r[3]) : "r"(a));
}
__device__ __forceinline__ void ldsm4t(uint32_t* r, uint32_t a) {
    asm volatile("ldmatrix.sync.aligned.m8n8.x4.trans.shared.b16 {%0,%1,%2,%3}, [%4];"
        : "=r"(r[0]), "=r"(r[1]), "=r"(r[2]), "=r"(r[3]) : "r"(a));
}
__device__ __forceinline__ void ldsm2t(uint32_t* r, uint32_t a) {
    asm volatile("ldmatrix.sync.aligned.m8n8.x2.trans.shared.b16 {%0,%1}, [%2];"
        : "=r"(r[0]), "=r"(r[1]) : "r"(a));
}
__device__ __forceinline__ void mma_bf16(float* d, const uint32_t* a, const uint32_t* b) {
    asm volatile("mma.sync.aligned.m16n8k16.row.col.f32.bf16.bf16.f32 "
        "{%0,%1,%2,%3}, {%4,%5,%6,%7}, {%8,%9}, {%0,%1,%2,%3};"
        : "+f"(d[0]), "+f"(d[1]), "+f"(d[2]), "+f"(d[3])
        : "r"(a[0]), "r"(a[1]), "r"(a[2]), "r"(a[3]), "r"(b[0]), "r"(b[1]));
}

// ---------------- permute H (canonical -> [c][h][w][t]) via smem transpose ---
__global__ __launch_bounds__(256) void permuteH_kernel(
    const float* __restrict__ src, float* __restrict__ dst)
{
    __shared__ float s[16][65];
    int w = blockIdx.x;
    int c = blockIdx.y;
    int b = blockIdx.z;
    size_t base = ((size_t)b * 256 + c) * 65536;
    int tid = threadIdx.x;
    for (int idx = tid; idx < 1024; idx += 256) {
        int t = idx >> 6, h = idx & 63;
        s[t][h] = src[base + (size_t)t * 4096 + w * 64 + h];
    }
    __syncthreads();
    for (int idx = tid; idx < 1024; idx += 256) {
        int h = idx >> 4, t = idx & 15;
        dst[base + (size_t)h * 1024 + w * 16 + t] = s[t][h];
    }
}

// ---------------- fused q/k/v conv1x1 (persistent X panel, bf16 MMA) --------
// Block: 64 pooled output columns == two 64-wide source strips (128 src cols).
// X panel loaded ONCE as bf16 hi/lo; then 4 m-chunks of 128 output rows:
//   mc0=q (3-pass, unpooled both strips), mc1=k (3-pass, pooled),
//   mc2,3=v (1-pass, pooled).
template<int MODE, int LOGD>
__global__ __launch_bounds__(256) void conv_fused(
    const float* __restrict__ X,
    const float* __restrict__ Wq, const float* __restrict__ bq,
    const float* __restrict__ Wk, const float* __restrict__ bk,
    const float* __restrict__ Wv, const float* __restrict__ bv,
    float* __restrict__ qo, float* __restrict__ ko, float* __restrict__ vo)
{
    constexpr int PP = 136;            // panel pitch (bf16)
    constexpr int PT = 256 * PP;       // panel elems per (hi|lo)
    constexpr int WT = 128 * 40;       // W tile elems

    extern __shared__ char smem_raw[];
    __nv_bfloat16* sm  = reinterpret_cast<__nv_bfloat16*>(smem_raw);
    __nv_bfloat16* XPH = sm;            // [256][136]
    __nv_bfloat16* XPL = XPH + PT;
    __nv_bfloat16* WsH = XPL + PT;      // [2][128][40]
    __nv_bfloat16* WsL = WsH + 2 * WT;

    int b  = blockIdx.z;
    int n0 = blockIdx.x * 64;
    const float* Xb = X + (size_t)b * 256 * NSP;

    int tid  = threadIdx.x;
    int lane = tid & 31, warp = tid >> 5;
    int wm = warp & 3, wn = warp >> 2;      // 4 m-groups x 2 n-groups
    int g = lane >> 2, tg = lane & 3;
    int r8 = (lane & 7) + (lane & 8);
    int ch = (lane & 16) >> 1;

    // ---- strip bases ----
    int s0, s1, qc0, qc1;
    if (MODE == 0) {
        int a2 = n0 >> LOGD;
        int p0 = n0 & ((1 << LOGD) - 1);
        s0 = ((2 * a2) << LOGD) + p0;
        s1 = s0 + (1 << LOGD);
        qc0 = s0; qc1 = s1;
    } else {   // cell W canonical: col = a*1024 + p1*64 + p2 -> src p1*4096 + a*64 + p2
        int aa = n0 >> 10;
        int r  = n0 & 1023;
        s0 = (r >> 6) * 4096 + (2 * aa) * 64;
        s1 = s0 + 64;
        qc0 = (2 * aa) * 1024 + r;
        qc1 = qc0 + 1024;
    }

    // ---- fill X panel (once) ----
    {
        int prow = tid >> 4;
        int pcol = (tid & 15) * 4;
#pragma unroll
        for (int it = 0; it < 16; it++) {
            int row = it * 16 + prow;
            float4 x0 = ld4(Xb + (size_t)row * NSP + s0 + pcol);
            float4 x1 = ld4(Xb + (size_t)row * NSP + s1 + pcol);
            uint2 h0, l0, h1, l1;
            split_f4(x0, h0, l0);
            split_f4(x1, h1, l1);
            *(uint2*)&XPH[row * PP + pcol]      = h0;
            *(uint2*)&XPL[row * PP + pcol]      = l0;
            *(uint2*)&XPH[row * PP + 64 + pcol] = h1;
            *(uint2*)&XPL[row * PP + 64 + pcol] = l1;
        }
    }
    __syncthreads();

    uint32_t sb  = (uint32_t)__cvta_generic_to_shared(sm);
    uint32_t sbW = sb + 2 * PT * 2;                 // W region base (bytes)
    int aoe = (wm * 32 + r8) * 40 + ch;             // A frag elem offset in W tile

    int wrow = tid >> 3;                            // W load rows wrow+32i
    int wcol = (tid & 7) * 4;

    const float* Wgs[4] = {Wq, Wk, Wv, Wv + 32768};
    const float* bcs[4] = {bq, bk, bv, bv + 128};

#pragma unroll
    for (int mc = 0; mc < 4; mc++) {
        const int npass = (mc < 2) ? 3 : 1;
        const float* Wg = Wgs[mc];
        const float* bc = bcs[mc];

        float acc[2][8][4];
#pragma unroll
        for (int mt = 0; mt < 2; mt++)
#pragma unroll
            for (int nt = 0; nt < 8; nt++)
#pragma unroll
                for (int r = 0; r < 4; r++) acc[mt][nt][r] = 0.f;

        uint2 wh[4], wl[4];
        auto LOADW = [&](int ks) {
#pragma unroll
            for (int i = 0; i < 4; i++) {
                float4 wv = ld4(Wg + (size_t)(wrow + i * 32) * 256 + ks * 32 + wcol);
                split_f4(wv, wh[i], wl[i]);
            }
        };
        auto STSW = [&](int bf) {
#pragma unroll
            for (int i = 0; i < 4; i++) {
                int off = bf * WT + (wrow + i * 32) * 40 + wcol;
                *(uint2*)&WsH[off] = wh[i];
                *(uint2*)&WsL[off] = wl[i];
            }
        };

        LOADW(0);
        STSW(0);
        __syncthreads();

#pragma unroll 1
        for (int s = 0; s < 8; s++) {
            int cb = s & 1;
            if (s < 7) LOADW(s + 1);

            uint32_t aHb = sbW + (cb * WT + aoe) * 2;
            uint32_t aLb = aHb + 2 * WT * 2;
#pragma unroll
            for (int ks = 0; ks < 2; ks++) {
                uint32_t Ah[2][4], Al[2][4];
#pragma unroll
                for (int mt = 0; mt < 2; mt++) {
                    ldsm4(Ah[mt], aHb + (ks * 16 + mt * 640) * 2);
                    if (npass == 3) ldsm4(Al[mt], aLb + (ks * 16 + mt * 640) * 2);
                }
#pragma unroll
                for (int pp = 0; pp < 4; pp++) {
                    int pcolp = (pp < 2) ? (wn * 32 + pp * 16)
                                         : (64 + wn * 32 + (pp - 2) * 16);
                    uint32_t bh_a = sb + (((s * 32 + ks * 16 + r8) * PP) + ch + pcolp) * 2;
                    uint32_t Bh[4], Bl[4];
                    ldsm4t(Bh, bh_a);
                    if (npass == 3) ldsm4t(Bl, bh_a + PT * 2);
#pragma unroll
                    for (int mt = 0; mt < 2; mt++)
#pragma unroll
                        for (int sub = 0; sub < 2; sub++) {
                            float* d = acc[mt][pp * 2 + sub];
                            mma_bf16(d, Ah[mt], Bh + 2 * sub);
                            if (npass == 3) {
                                mma_bf16(d, Ah[mt], Bl + 2 * sub);
                                mma_bf16(d, Al[mt], Bh + 2 * sub);
                            }
                        }
                }
            }
            if (s < 7) STSW(1 - cb);
            __syncthreads();
        }

        // ---- chunk epilogue ----
        if (mc == 0) {
            float* outb = qo + (size_t)b * 128 * 65536;
#pragma unroll
            for (int mt = 0; mt < 2; mt++) {
                int r = wm * 32 + mt * 16 + g;
                float b0 = bc[r], b1 = bc[r + 8];
#pragma unroll
                for (int nt = 0; nt < 8; nt++) {
                    int lcol = wn * 32 + ((nt & 3) >> 1) * 16 + (nt & 1) * 8 + tg * 2;
                    int col = (nt < 4 ? qc0 : qc1) + lcol;
                    *(float2*)&outb[(size_t)r * 65536 + col] =
                        make_float2(acc[mt][nt][0] + b0, acc[mt][nt][1] + b0);
                    *(float2*)&outb[(size_t)(r + 8) * 65536 + col] =
                        make_float2(acc[mt][nt][2] + b1, acc[mt][nt][3] + b1);
                }
            }
        } else {
            float* outb = (mc == 1) ? (ko + (size_t)b * 128 * 32768)
                                    : (vo + (size_t)b * 256 * 32768 + (size_t)(mc - 2) * 128 * 32768);
#pragma unroll
            for (int mt = 0; mt < 2; mt++) {
                int r = wm * 32 + mt * 16 + g;
                float b0 = bc[r], b1 = bc[r + 8];
#pragma unroll
                for (int nt = 0; nt < 4; nt++) {
                    int col = n0 + wn * 32 + (nt >> 1) * 16 + (nt & 1) * 8 + tg * 2;
                    float v00 = fmaxf(acc[mt][nt][0], acc[mt][nt + 4][0]) + b0;
                    float v01 = fmaxf(acc[mt][nt][1], acc[mt][nt + 4][1]) + b0;
                    float v10 = fmaxf(acc[mt][nt][2], acc[mt][nt + 4][2]) + b1;
                    float v11 = fmaxf(acc[mt][nt][3], acc[mt][nt + 4][3]) + b1;
                    *(float2*)&outb[(size_t)r * 32768 + col]       = make_float2(v00, v01);
                    *(float2*)&outb[(size_t)(r + 8) * 32768 + col] = make_float2(v10, v11);
                }
            }
        }
    }
}

// ---------------- attention logits: bf16x3 tensor-core streaming GEMM -------
template<int CELL0>
__global__ __launch_bounds__(256) void attn_mma(
    const float* __restrict__ q, const float* __restrict__ k,
    float* __restrict__ Sp)
{
    constexpr int Ac  = CELL0 ? 16 : 64;
    constexpr int A2c = CELL0 ? 8  : 32;
    constexpr int K   = CELL0 ? 524288 : 131072;
    constexpr int KSL = K / 256;
    constexpr int CJ  = CELL0 ? 128 : 64;
    constexpr int NCH = KSL / CJ;
    constexpr int PQ  = CELL0 ? 136 : 72;
    constexpr int PK  = CELL0 ? 8 : 40;
    constexpr int QT  = Ac * PQ;
    constexpr int KT  = CJ * PK;
    constexpr int NQ  = CELL0 ? 2 : 4;
    constexpr int NK  = CELL0 ? 1 : 2;

    extern __shared__ __nv_bfloat16 smb[];
    __nv_bfloat16 *QH = smb, *QL = QH + 2 * QT, *KH = QL + 2 * QT, *KL = KH + 2 * KT;

    int b = blockIdx.y, sl = blockIdx.x;
    const float* qb = q + (size_t)b * Ac * K + (size_t)sl * KSL;
    const float* kb = k + ((size_t)b * K + (size_t)sl * KSL) * A2c;

    int tid = threadIdx.x, lane = tid & 31, warp = tid >> 5;
    int g = lane >> 2, tg = lane & 3;

    float4 qv[NQ], kv[NK];
    auto LOAD = [&](int chk) {
        int j0 = chk * CJ;
#pragma unroll
        for (int l = 0; l < NQ; l++) {
            int idx = tid + 256 * l;
            int row = CELL0 ? (idx >> 5) : (idx >> 4);
            int c   = CELL0 ? ((idx & 31) * 4) : ((idx & 15) * 4);
            qv[l] = ld4(qb + (size_t)row * K + j0 + c);
        }
#pragma unroll
        for (int l = 0; l < NK; l++) {
            int idx = tid + 256 * l;
            int row = CELL0 ? (idx >> 1) : (idx >> 3);
            int c   = CELL0 ? ((idx & 1) * 4) : ((idx & 7) * 4);
            kv[l] = ld4(kb + (size_t)(j0 + row) * A2c + c);
        }
    };
    auto STORE = [&](int bf) {
#pragma unroll
        for (int l = 0; l < NQ; l++) {
            int idx = tid + 256 * l;
            int row = CELL0 ? (idx >> 5) : (idx >> 4);
            int c   = CELL0 ? ((idx & 31) * 4) : ((idx & 15) * 4);
            uint2 h, lo;
            split_f4(qv[l], h, lo);
            int off = bf * QT + row * PQ + c;
            *(uint2*)&QH[off] = h;
            *(uint2*)&QL[off] = lo;
        }
#pragma unroll
        for (int l = 0; l < NK; l++) {
            int idx = tid + 256 * l;
            int row = CELL0 ? (idx >> 1) : (idx >> 3);
            int c   = CELL0 ? ((idx & 1) * 4) : ((idx & 7) * 4);
            uint2 h, lo;
            split_f4(kv[l], h, lo);
            int off = bf * KT + row * PK + c;
            *(uint2*)&KH[off] = h;
            *(uint2*)&KL[off] = lo;
        }
    };

    uint32_t sb = (uint32_t)__cvta_generic_to_shared(smb);
    int r8 = (lane & 7) + (lane & 8);
    int aoe, boe, wm = warp & 3, wn = warp >> 2;
    if (CELL0) {
        aoe = r8 * PQ + ((lane & 16) >> 1) + warp * 16;
        boe = (warp * 16 + (lane & 15)) * PK;
    } else {
        aoe = (wm * 16 + r8) * PQ + ((lane & 16) >> 1);
        boe = r8 * PK + ((lane & 16) >> 1) + wn * 16;
    }
    constexpr int NACC = CELL0 ? 1 : 2;
    float acc[NACC][4];
#pragma unroll
    for (int a = 0; a < NACC; a++)
#pragma unroll
        for (int r = 0; r < 4; r++) acc[a][r] = 0.f;

    LOAD(0);
    STORE(0);
    __syncthreads();

#pragma unroll 1
    for (int chk = 0; chk < NCH; chk++) {
        int cb = chk & 1;
        if (chk < NCH - 1) LOAD(chk + 1);
        uint32_t qh = sb + (cb * QT + aoe) * 2;
        uint32_t ql = qh + 2 * QT * 2;
        uint32_t kh = sb + 4 * QT * 2 + (cb * KT + boe) * 2;
        uint32_t kl = kh + 2 * KT * 2;
        if (CELL0) {
            uint32_t Ah[4], Al[4], Bh[2], Bl[2];
            ldsm4(Ah, qh); ldsm4(Al, ql);
            ldsm2t(Bh, kh); ldsm2t(Bl, kl);
            mma_bf16(acc[0], Ah, Bh);
            mma_bf16(acc[0], Ah, Bl);
            mma_bf16(acc[0], Al, Bh);
        } else {
#pragma unroll
            for (int ks = 0; ks < 4; ks++) {
                uint32_t Ah[4], Al[4], Bh[4], Bl[4];
                ldsm4(Ah, qh + ks * 32);
                ldsm4(Al, ql + ks * 32);
                ldsm4t(Bh, kh + ks * 16 * PK * 2);
                ldsm4t(Bl, kl + ks * 16 * PK * 2);
#pragma unroll
                for (int sub = 0; sub < 2; sub++) {
                    mma_bf16(acc[sub], Ah, Bh + 2 * sub);
                    mma_bf16(acc[sub], Ah, Bl + 2 * sub);
                    mma_bf16(acc[sub], Al, Bh + 2 * sub);
                }
            }
        }
        if (chk < NCH - 1) STORE(1 - cb);
        __syncthreads();
    }

    if (CELL0) {
        float* red = reinterpret_cast<float*>(smb);
        red[warp * 128 + g * 8 + 2 * tg]           = acc[0][0];
        red[warp * 128 + g * 8 + 2 * tg + 1]       = acc[0][1];
        red[warp * 128 + (g + 8) * 8 + 2 * tg]     = acc[0][2];
        red[warp * 128 + (g + 8) * 8 + 2 * tg + 1] = acc[0][3];
        __syncthreads();
        if (tid < 128) {
            float sum = 0.f;
#pragma unroll
            for (int w = 0; w < 8; w++) sum += red[w * 128 + tid];
            Sp[(size_t)sl * 256 + b * 128 + tid] = sum;
        }
    } else {
        size_t base = (size_t)sl * 4096 + b * 2048;
#pragma unroll
        for (int sub = 0; sub < 2; sub++) {
            int s0 = wn * 16 + sub * 8 + 2 * tg;
            int i0 = wm * 16 + g;
            Sp[base + i0 * 32 + s0]           = acc[sub][0];
            Sp[base + i0 * 32 + s0 + 1]       = acc[sub][1];
            Sp[base + (i0 + 8) * 32 + s0]     = acc[sub][2];
            Sp[base + (i0 + 8) * 32 + s0 + 1] = acc[sub][3];
        }
    }
}

// ---------------- reduce partials + softmax over A2 --------------------------
__global__ __launch_bounds__(256) void softmax_reduce(
    const float* __restrict__ Sp, float* __restrict__ S,
    int A2, int nsl, int rowtot)
{
    int row = blockIdx.x * 8 + (threadIdx.x >> 5);
    int s = threadIdx.x & 31;
    float v = 0.f;
    if (s < A2) {
        for (int sl = 0; sl < nsl; sl += 4) {
            v += Sp[(size_t)(sl + 0) * rowtot + row * A2 + s]
               + Sp[(size_t)(sl + 1) * rowtot + row * A2 + s]
               + Sp[(size_t)(sl + 2) * rowtot + row * A2 + s]
               + Sp[(size_t)(sl + 3) * rowtot + row * A2 + s];
        }
    }
    float vm = (s < A2) ? v : -1e30f;
#pragma unroll
    for (int off = 16; off; off >>= 1)
        vm = fmaxf(vm, __shfl_xor_sync(0xffffffffu, vm, off));
    float e = (s < A2) ? expf(v - vm) : 0.f;
    float sum = e;
#pragma unroll
    for (int off = 16; off; off >>= 1)
        sum += __shfl_xor_sync(0xffffffffu, sum, off);
    if (s < A2) S[row * A2 + s] = e / sum;
}

// ---------------- o-GEMM + un-permute + residual (cells T, W) ---------------
template<int CELL>
__global__ __launch_bounds__(256) void epilogue_kernel(
    const float* __restrict__ v, const float* __restrict__ S,
    const float* __restrict__ cur, float* __restrict__ outp,
    const float* __restrict__ gammap)
{
    constexpr int A  = (CELL == 0) ? 16 : 64;
    constexpr int A2 = (CELL == 0) ? 8 : 32;
    constexpr int d  = (CELL == 0) ? 4096 : 1024;

    int b = blockIdx.y;
    __shared__ float attnS[A * A2];
    int tid = threadIdx.x;
    for (int idx = tid; idx < A * A2; idx += 256)
        attnS[idx] = S[b * A * A2 + idx];
    __syncthreads();

    float g = gammap[0];
    int x = blockIdx.x * 256 + tid;

    const float4* vr4 = reinterpret_cast<const float4*>(
        v + (size_t)b * 8388608 + (size_t)x * A2);
    float vv[A2];
#pragma unroll
    for (int s4 = 0; s4 < A2 / 4; s4++) {
        float4 t = vr4[s4];
        vv[s4 * 4 + 0] = t.x; vv[s4 * 4 + 1] = t.y;
        vv[s4 * 4 + 2] = t.z; vv[s4 * 4 + 3] = t.w;
    }
    int c  = x / d;
    int p  = x % d;
    int p1 = p / 64;
    int p2 = p % 64;
    size_t boff = (size_t)b * 16777216 + (size_t)c * 65536;
    int base, stride;
    if (CELL == 0) { base = p1 * 64   + p2; stride = 4096; }
    else           { base = p1 * 4096 + p2; stride = 64;   }

#pragma unroll 4
    for (int a = 0; a < A; a++) {
        float o = 0.f;
#pragma unroll
        for (int s = 0; s < A2; s++) o += vv[s] * attnS[a * A2 + s];
        int off = base + a * stride;
        outp[boff + off] = g * o + cur[boff + off];
    }
}

// ---------------- cell-H epilogue: smem transpose, fully coalesced I/O ------
__global__ __launch_bounds__(256) void epilogue2_kernel(
    const float* __restrict__ v, const float* __restrict__ S,
    const float* __restrict__ cur, float* __restrict__ outp,
    const float* __restrict__ gammap)
{
    int b  = blockIdx.y;
    int cp = blockIdx.x;        // c*16 + p1
    int c = cp >> 4, p1 = cp & 15;

    __shared__ float attnS[64 * 33];
    __shared__ float vs[64 * 33];
    __shared__ float os[64 * 65];
    int tid = threadIdx.x;

    for (int i = tid; i < 2048; i += 256)
        attnS[(i >> 5) * 33 + (i & 31)] = S[b * 2048 + i];
    size_t vbase = (size_t)b * 8388608 + ((size_t)c * 1024 + p1 * 64) * 32;
    for (int i = tid; i < 2048; i += 256)
        vs[(i >> 5) * 33 + (i & 31)] = v[vbase + i];
    __syncthreads();

    int p2 = tid & 63;
    int a0 = (tid >> 6) * 16;
    float vv[32];
#pragma unroll
    for (int s = 0; s < 32; s++) vv[s] = vs[p2 * 33 + s];
#pragma unroll
    for (int ai = 0; ai < 16; ai++) {
        int a = a0 + ai;
        float o = 0.f;
#pragma unroll
        for (int s = 0; s < 32; s++) o += vv[s] * attnS[a * 33 + s];
        os[p2 * 65 + a] = o;
    }
    __syncthreads();

    float g = gammap[0];
    size_t obase = (size_t)b * 16777216 + (size_t)c * 65536 + (size_t)p1 * 4096;
    for (int i = tid; i < 4096; i += 256)
        outp[obase + i] = g * os[(i >> 6) * 65 + (i & 63)] + cur[obase + i];
}

// ---------------- host orchestration ----------------
extern "C" void kernel_launch(void* const* d_in, const int* in_sizes, int n_in,
                              void* d_out, int out_size)
{
    const float* x  = (const float*)d_in[0];
    const float* Wq = (const float*)d_in[1];
    const float* bq = (const float*)d_in[2];
    const float* Wk = (const float*)d_in[3];
    const float* bk = (const float*)d_in[4];
    const float* Wv = (const float*)d_in[5];
    const float* bv = (const float*)d_in[6];
    const float* gm = (const float*)d_in[7];
    float* out = (float*)d_out;

    float *buf0, *buf1, *xp, *q, *k, *v, *Sp, *S;
    cudaGetSymbolAddress((void**)&buf0, g_buf0);
    cudaGetSymbolAddress((void**)&buf1, g_buf1);
    cudaGetSymbolAddress((void**)&xp,   g_xp);
    cudaGetSymbolAddress((void**)&q,    g_q);
    cudaGetSymbolAddress((void**)&k,    g_k);
    cudaGetSymbolAddress((void**)&v,    g_v);
    cudaGetSymbolAddress((void**)&Sp,   g_Sp);
    cudaGetSymbolAddress((void**)&S,    g_S);

    const int SM_CF = (2 * 256 * 136 + 4 * 128 * 40) * 2;               // 180224
    const int SM_A0 = (2 * 2176 + 2 * 2176 + 2 * 1024 + 2 * 1024) * 2;  // 25600
    const int SM_A1 = (2 * 4608 + 2 * 4608 + 2 * 2560 + 2 * 2560) * 2;  // 57344

    cudaFuncSetAttribute(conv_fused<0,12>, cudaFuncAttributeMaxDynamicSharedMemorySize, SM_CF);
    cudaFuncSetAttribute(conv_fused<1,10>, cudaFuncAttributeMaxDynamicSharedMemorySize, SM_CF);
    cudaFuncSetAttribute(conv_fused<0,10>, cudaFuncAttributeMaxDynamicSharedMemorySize, SM_CF);
    cudaFuncSetAttribute(attn_mma<1>, cudaFuncAttributeMaxDynamicSharedMemorySize, SM_A0);
    cudaFuncSetAttribute(attn_mma<0>, cudaFuncAttributeMaxDynamicSharedMemorySize, SM_A1);

    // ================= cell 0 : attention over T (identity permutation) ======
    {
        conv_fused<0,12><<<dim3(512, 1, 2), 256, SM_CF>>>(
            x, Wq, bq, Wk, bk, Wv, bv, q, k, v);
        attn_mma<1><<<dim3(256, 2), 256, SM_A0>>>(q, k, Sp);
        softmax_reduce<<<4, 256>>>(Sp, S, 8, 256, 256);
        epilogue_kernel<0><<<dim3(4096, 2), 256>>>(v, S, x, buf0, gm + 0);
    }
    // ================= cell 1 : attention over W (fused permute in conv) =====
    {
        conv_fused<1,10><<<dim3(512, 1, 2), 256, SM_CF>>>(
            buf0, Wq + 32768, bq + 128, Wk + 32768, bk + 128,
            Wv + 65536, bv + 256, q, k, v);
        attn_mma<0><<<dim3(256, 2), 256, SM_A1>>>(q, k, Sp);
        softmax_reduce<<<16, 256>>>(Sp, S, 32, 256, 4096);
        epilogue_kernel<1><<<dim3(1024, 2), 256>>>(v, S, buf0, buf1, gm + 1);
    }
    // ================= cell 2 : attention over H ==============================
    {
        permuteH_kernel<<<dim3(64, 256, 2), 256>>>(buf1, xp);
        conv_fused<0,10><<<dim3(512, 1, 2), 256, SM_CF>>>(
            xp, Wq + 65536, bq + 256, Wk + 65536, bk + 256,
            Wv + 131072, bv + 512, q, k, v);
        attn_mma<0><<<dim3(256, 2), 256, SM_A1>>>(q, k, Sp);
        softmax_reduce<<<16, 256>>>(Sp, S, 32, 256, 4096);
        epilogue2_kernel<<<dim3(4096, 2), 256>>>(v, S, buf1, out, gm + 2);
    }
}

// round 9
// speedup vs baseline: 2.9259x; 1.0121x over previous
#include <cuda_runtime.h>
#include <cuda_bf16.h>
#include <cstdint>

#define NEL 33554432           // 2*256*16*64*64
#define NSP 65536               // T*W*H

// ---------------- scratch (device globals; no runtime alloc) ----------------
__device__ float g_buf0[NEL];
__device__ float g_buf1[NEL];
__device__ float g_xp[NEL];
__device__ float g_q[16777216];   // B * 128 * 65536
__device__ float g_k[8388608];    // B * 128 * 32768
__device__ float g_v[16777216];   // B * 256 * 32768
__device__ float g_Sp[1048576];   // split-K partials (256 slices * 4096)
__device__ float g_S[4096];       // attn after softmax: B*64*32 max
// fragment-major packed weights: 512 rows x 256 cols -> 32 mtiles x 16 ktiles
// tile = 32 lanes x 4 uint32 (m16n8k16 A-fragment layout), hi and lo planes
__device__ __align__(16) uint32_t g_wfh[65536];
__device__ __align__(16) uint32_t g_wfl[65536];

// ---------------- helpers ----------------
__device__ __forceinline__ float4 ld4(const float* p) {
    return *reinterpret_cast<const float4*>(p);
}
__device__ __forceinline__ void split_f4(float4 v, uint2& h, uint2& l) {
    asm("cvt.rn.bf16x2.f32 %0, %1, %2;" : "=r"(h.x) : "f"(v.y), "f"(v.x));
    asm("cvt.rn.bf16x2.f32 %0, %1, %2;" : "=r"(h.y) : "f"(v.w), "f"(v.z));
    float rx = v.x - __uint_as_float(h.x << 16);
    float ry = v.y - __uint_as_float(h.x & 0xffff0000u);
    float rz = v.z - __uint_as_float(h.y << 16);
    float rw = v.w - __uint_as_float(h.y & 0xffff0000u);
    asm("cvt.rn.bf16x2.f32 %0, %1, %2;" : "=r"(l.x) : "f"(ry), "f"(rx));
    asm("cvt.rn.bf16x2.f32 %0, %1, %2;" : "=r"(l.y) : "f"(rw), "f"(rz));
}
__device__ __forceinline__ void split_pair(float a, float b, uint32_t& h, uint32_t& l) {
    // pack pair (a at low, b at high) hi + residual lo
    asm("cvt.rn.bf16x2.f32 %0, %1, %2;" : "=r"(h) : "f"(b), "f"(a));
    float ra = a - __uint_as_float(h << 16);
    float rb = b - __uint_as_float(h & 0xffff0000u);
    asm("cvt.rn.bf16x2.f32 %0, %1, %2;" : "=r"(l) : "f"(rb), "f"(ra));
}
__device__ __forceinline__ void ldsm4(uint32_t* r, uint32_t a) {
    asm volatile("ldmatrix.sync.aligned.m8n8.x4.shared.b16 {%0,%1,%2,%3}, [%4];"
        : "=r"(r[0]), "=r"(r[1]), "=r"(r[2]), "=r"(r[3]) : "r"(a));
}
__device__ __forceinline__ void ldsm4t(uint32_t* r, uint32_t a) {
    asm volatile("ldmatrix.sync.aligned.m8n8.x4.trans.shared.b16 {%0,%1,%2,%3}, [%4];"
        : "=r"(r[0]), "=r"(r[1]), "=r"(r[2]), "=r"(r[3]) : "r"(a));
}
__device__ __forceinline__ void ldsm2t(uint32_t* r, uint32_t a) {
    asm volatile("ldmatrix.sync.aligned.m8n8.x2.trans.shared.b16 {%0,%1}, [%2];"
        : "=r"(r[0]), "=r"(r[1]) : "r"(a));
}
__device__ __forceinline__ void mma_bf16(float* d, const uint32_t* a, const uint32_t* b) {
    asm volatile("mma.sync.aligned.m16n8k16.row.col.f32.bf16.bf16.f32 "
        "{%0,%1,%2,%3}, {%4,%5,%6,%7}, {%8,%9}, {%0,%1,%2,%3};"
        : "+f"(d[0]), "+f"(d[1]), "+f"(d[2]), "+f"(d[3])
        : "r"(a[0]), "r"(a[1]), "r"(a[2]), "r"(a[3]), "r"(b[0]), "r"(b[1]));
}

// ---------------- W fragment pre-pack (per cell) -----------------------------
// rows 0..127 = Wq, 128..255 = Wk, 256..511 = Wv (each [oc][256] row-major)
__global__ __launch_bounds__(256) void wfrag_prep(
    const float* __restrict__ Wq, const float* __restrict__ Wk,
    const float* __restrict__ Wv)
{
    int idx = blockIdx.x * 256 + threadIdx.x;   // 16384 = 512 tiles * 32 lanes
    int tile = idx >> 5, lane = idx & 31;
    int mtile = tile >> 4, kt = tile & 15;
    int g = lane >> 2, tg = lane & 3;
    int r0 = mtile * 16 + g;
    int c0 = kt * 16 + tg * 2;

    uint32_t h[4], l[4];
#pragma unroll
    for (int j = 0; j < 4; j++) {
        int r = r0 + ((j & 1) ? 8 : 0);
        int c = c0 + ((j & 2) ? 8 : 0);
        const float* Wr;
        if (r < 128)      Wr = Wq + r * 256;
        else if (r < 256) Wr = Wk + (r - 128) * 256;
        else              Wr = Wv + (r - 256) * 256;
        split_pair(Wr[c], Wr[c + 1], h[j], l[j]);
    }
    *(uint4*)&g_wfh[tile * 128 + lane * 4] = make_uint4(h[0], h[1], h[2], h[3]);
    *(uint4*)&g_wfl[tile * 128 + lane * 4] = make_uint4(l[0], l[1], l[2], l[3]);
}

// ---------------- permute H (canonical -> [c][h][w][t]) via smem transpose ---
__global__ __launch_bounds__(256) void permuteH_kernel(
    const float* __restrict__ src, float* __restrict__ dst)
{
    __shared__ float s[16][65];
    int w = blockIdx.x;
    int c = blockIdx.y;
    int b = blockIdx.z;
    size_t base = ((size_t)b * 256 + c) * 65536;
    int tid = threadIdx.x;
    for (int idx = tid; idx < 1024; idx += 256) {
        int t = idx >> 6, h = idx & 63;
        s[t][h] = src[base + (size_t)t * 4096 + w * 64 + h];
    }
    __syncthreads();
    for (int idx = tid; idx < 1024; idx += 256) {
        int h = idx >> 4, t = idx & 15;
        dst[base + (size_t)h * 1024 + w * 16 + t] = s[t][h];
    }
}

// ---------------- fused q/k/v conv1x1, W frags via LDG, no mainloop syncs ---
// Block: 64 pooled output columns (two 64-col source strips). X panel (hi/lo)
// resident in smem; per-warp independent MMA stream; A-frags LDG.128 from
// fragment-major W (L2-resident); q 3-pass, k 3-pass, v 1-pass.
template<int MODE, int LOGD>
__global__ __launch_bounds__(256) void conv_fx(
    const float* __restrict__ X,
    const float* __restrict__ bq, const float* __restrict__ bk,
    const float* __restrict__ bv,
    float* __restrict__ qo, float* __restrict__ ko, float* __restrict__ vo)
{
    constexpr int PP = 136;            // panel pitch (bf16)
    constexpr int PT = 256 * PP;       // panel elems per (hi|lo)

    extern __shared__ char smem_raw[];
    __nv_bfloat16* XPH = reinterpret_cast<__nv_bfloat16*>(smem_raw);
    __nv_bfloat16* XPL = XPH + PT;

    int b  = blockIdx.z;
    int n0 = blockIdx.x * 64;
    const float* Xb = X + (size_t)b * 256 * NSP;

    int tid  = threadIdx.x;
    int lane = tid & 31, warp = tid >> 5;
    int wm = warp & 3, wn = warp >> 2;      // 4 m-groups x 2 n-groups
    int g = lane >> 2, tg = lane & 3;
    int r8 = (lane & 7) + (lane & 8);
    int ch = (lane & 16) >> 1;

    // ---- strip bases ----
    int s0, s1, qc0, qc1;
    if (MODE == 0) {
        int a2 = n0 >> LOGD;
        int p0 = n0 & ((1 << LOGD) - 1);
        s0 = ((2 * a2) << LOGD) + p0;
        s1 = s0 + (1 << LOGD);
        qc0 = s0; qc1 = s1;
    } else {   // cell W canonical: col = a*1024 + p1*64 + p2 -> src p1*4096 + a*64 + p2
        int aa = n0 >> 10;
        int r  = n0 & 1023;
        s0 = (r >> 6) * 4096 + (2 * aa) * 64;
        s1 = s0 + 64;
        qc0 = (2 * aa) * 1024 + r;
        qc1 = qc0 + 1024;
    }

    // ---- fill X panel (once) ----
    {
        int prow = tid >> 4;
        int pcol = (tid & 15) * 4;
#pragma unroll
        for (int it = 0; it < 16; it++) {
            int row = it * 16 + prow;
            float4 x0 = ld4(Xb + (size_t)row * NSP + s0 + pcol);
            float4 x1 = ld4(Xb + (size_t)row * NSP + s1 + pcol);
            uint2 h0, l0, h1, l1;
            split_f4(x0, h0, l0);
            split_f4(x1, h1, l1);
            *(uint2*)&XPH[row * PP + pcol]      = h0;
            *(uint2*)&XPL[row * PP + pcol]      = l0;
            *(uint2*)&XPH[row * PP + 64 + pcol] = h1;
            *(uint2*)&XPL[row * PP + 64 + pcol] = l1;
        }
    }
    __syncthreads();

    uint32_t sb = (uint32_t)__cvta_generic_to_shared(XPH);
    const uint4* wfh4 = reinterpret_cast<const uint4*>(g_wfh);
    const uint4* wfl4 = reinterpret_cast<const uint4*>(g_wfl);

#pragma unroll 1
    for (int mc = 0; mc < 4; mc++) {
        const bool need_lo = (mc < 2);

        float acc[2][8][4];
#pragma unroll
        for (int mt = 0; mt < 2; mt++)
#pragma unroll
            for (int nt = 0; nt < 8; nt++)
#pragma unroll
                for (int r = 0; r < 4; r++) acc[mt][nt][r] = 0.f;

        int tbase = (mc * 8 + wm * 2) * 16;   // first mtile's tile row base

#pragma unroll 2
        for (int kt = 0; kt < 16; kt++) {
            uint4 Ah[2], Al[2];
#pragma unroll
            for (int mt = 0; mt < 2; mt++) {
                int tile = tbase + mt * 16 + kt;
                Ah[mt] = wfh4[tile * 32 + lane];
                if (need_lo) Al[mt] = wfl4[tile * 32 + lane];
            }
#pragma unroll
            for (int pp = 0; pp < 4; pp++) {
                int pcolp = (pp < 2) ? (wn * 32 + pp * 16)
                                     : (64 + wn * 32 + (pp - 2) * 16);
                uint32_t bh_a = sb + (((kt * 16 + r8) * PP) + ch + pcolp) * 2;
                uint32_t Bh[4], Bl[4];
                ldsm4t(Bh, bh_a);
                if (need_lo) ldsm4t(Bl, bh_a + PT * 2);
#pragma unroll
                for (int mt = 0; mt < 2; mt++)
#pragma unroll
                    for (int sub = 0; sub < 2; sub++) {
                        float* d = acc[mt][pp * 2 + sub];
                        mma_bf16(d, (const uint32_t*)&Ah[mt], Bh + 2 * sub);
                        if (need_lo) {
                            mma_bf16(d, (const uint32_t*)&Ah[mt], Bl + 2 * sub);
                            mma_bf16(d, (const uint32_t*)&Al[mt], Bh + 2 * sub);
                        }
                    }
            }
        }

        // ---- chunk epilogue ----
        if (mc == 0) {
            float* outb = qo + (size_t)b * 8388608;
#pragma unroll
            for (int mt = 0; mt < 2; mt++) {
                int r = wm * 32 + mt * 16 + g;
                float b0 = bq[r], b1 = bq[r + 8];
#pragma unroll
                for (int nt = 0; nt < 8; nt++) {
                    int lcol = wn * 32 + ((nt & 3) >> 1) * 16 + (nt & 1) * 8 + tg * 2;
                    int col = (nt < 4 ? qc0 : qc1) + lcol;
                    *(float2*)&outb[(size_t)r * 65536 + col] =
                        make_float2(acc[mt][nt][0] + b0, acc[mt][nt][1] + b0);
                    *(float2*)&outb[(size_t)(r + 8) * 65536 + col] =
                        make_float2(acc[mt][nt][2] + b1, acc[mt][nt][3] + b1);
                }
            }
        } else {
            float* outb = (mc == 1) ? (ko + (size_t)b * 4194304)
                                    : (vo + (size_t)b * 8388608 + (size_t)(mc - 2) * 4194304);
            const float* bc = (mc == 1) ? bk : (bv + (mc - 2) * 128);
#pragma unroll
            for (int mt = 0; mt < 2; mt++) {
                int r = wm * 32 + mt * 16 + g;
                float b0 = bc[r], b1 = bc[r + 8];
#pragma unroll
                for (int nt = 0; nt < 4; nt++) {
                    int col = n0 + wn * 32 + (nt >> 1) * 16 + (nt & 1) * 8 + tg * 2;
                    float v00 = fmaxf(acc[mt][nt][0], acc[mt][nt + 4][0]) + b0;
                    float v01 = fmaxf(acc[mt][nt][1], acc[mt][nt + 4][1]) + b0;
                    float v10 = fmaxf(acc[mt][nt][2], acc[mt][nt + 4][2]) + b1;
                    float v11 = fmaxf(acc[mt][nt][3], acc[mt][nt + 4][3]) + b1;
                    *(float2*)&outb[(size_t)r * 32768 + col]       = make_float2(v00, v01);
                    *(float2*)&outb[(size_t)(r + 8) * 32768 + col] = make_float2(v10, v11);
                }
            }
        }
    }
}

// ---------------- attention logits: bf16x3 tensor-core streaming GEMM -------
template<int CELL0>
__global__ __launch_bounds__(256) void attn_mma(
    const float* __restrict__ q, const float* __restrict__ k,
    float* __restrict__ Sp)
{
    constexpr int Ac  = CELL0 ? 16 : 64;
    constexpr int A2c = CELL0 ? 8  : 32;
    constexpr int K   = CELL0 ? 524288 : 131072;
    constexpr int KSL = K / 256;
    constexpr int CJ  = CELL0 ? 128 : 64;
    constexpr int NCH = KSL / CJ;
    constexpr int PQ  = CELL0 ? 136 : 72;
    constexpr int PK  = CELL0 ? 8 : 40;
    constexpr int QT  = Ac * PQ;
    constexpr int KT  = CJ * PK;
    constexpr int NQ  = CELL0 ? 2 : 4;
    constexpr int NK  = CELL0 ? 1 : 2;

    extern __shared__ __nv_bfloat16 smb[];
    __nv_bfloat16 *QH = smb, *QL = QH + 2 * QT, *KH = QL + 2 * QT, *KL = KH + 2 * KT;

    int b = blockIdx.y, sl = blockIdx.x;
    const float* qb = q + (size_t)b * Ac * K + (size_t)sl * KSL;
    const float* kb = k + ((size_t)b * K + (size_t)sl * KSL) * A2c;

    int tid = threadIdx.x, lane = tid & 31, warp = tid >> 5;
    int g = lane >> 2, tg = lane & 3;

    float4 qv[NQ], kv[NK];
    auto LOAD = [&](int chk) {
        int j0 = chk * CJ;
#pragma unroll
        for (int l = 0; l < NQ; l++) {
            int idx = tid + 256 * l;
            int row = CELL0 ? (idx >> 5) : (idx >> 4);
            int c   = CELL0 ? ((idx & 31) * 4) : ((idx & 15) * 4);
            qv[l] = ld4(qb + (size_t)row * K + j0 + c);
        }
#pragma unroll
        for (int l = 0; l < NK; l++) {
            int idx = tid + 256 * l;
            int row = CELL0 ? (idx >> 1) : (idx >> 3);
            int c   = CELL0 ? ((idx & 1) * 4) : ((idx & 7) * 4);
            kv[l] = ld4(kb + (size_t)(j0 + row) * A2c + c);
        }
    };
    auto STORE = [&](int bf) {
#pragma unroll
        for (int l = 0; l < NQ; l++) {
            int idx = tid + 256 * l;
            int row = CELL0 ? (idx >> 5) : (idx >> 4);
            int c   = CELL0 ? ((idx & 31) * 4) : ((idx & 15) * 4);
            uint2 h, lo;
            split_f4(qv[l], h, lo);
            int off = bf * QT + row * PQ + c;
            *(uint2*)&QH[off] = h;
            *(uint2*)&QL[off] = lo;
        }
#pragma unroll
        for (int l = 0; l < NK; l++) {
            int idx = tid + 256 * l;
            int row = CELL0 ? (idx >> 1) : (idx >> 3);
            int c   = CELL0 ? ((idx & 1) * 4) : ((idx & 7) * 4);
            uint2 h, lo;
            split_f4(kv[l], h, lo);
            int off = bf * KT + row * PK + c;
            *(uint2*)&KH[off] = h;
            *(uint2*)&KL[off] = lo;
        }
    };

    uint32_t sb = (uint32_t)__cvta_generic_to_shared(smb);
    int r8 = (lane & 7) + (lane & 8);
    int aoe, boe, wm = warp & 3, wn = warp >> 2;
    if (CELL0) {
        aoe = r8 * PQ + ((lane & 16) >> 1) + warp * 16;
        boe = (warp * 16 + (lane & 15)) * PK;
    } else {
        aoe = (wm * 16 + r8) * PQ + ((lane & 16) >> 1);
        boe = r8 * PK + ((lane & 16) >> 1) + wn * 16;
    }
    constexpr int NACC = CELL0 ? 1 : 2;
    float acc[NACC][4];
#pragma unroll
    for (int a = 0; a < NACC; a++)
#pragma unroll
        for (int r = 0; r < 4; r++) acc[a][r] = 0.f;

    LOAD(0);
    STORE(0);
    __syncthreads();

#pragma unroll 1
    for (int chk = 0; chk < NCH; chk++) {
        int cb = chk & 1;
        if (chk < NCH - 1) LOAD(chk + 1);
        uint32_t qh = sb + (cb * QT + aoe) * 2;
        uint32_t ql = qh + 2 * QT * 2;
        uint32_t kh = sb + 4 * QT * 2 + (cb * KT + boe) * 2;
        uint32_t kl = kh + 2 * KT * 2;
        if (CELL0) {
            uint32_t Ah[4], Al[4], Bh[2], Bl[2];
            ldsm4(Ah, qh); ldsm4(Al, ql);
            ldsm2t(Bh, kh); ldsm2t(Bl, kl);
            mma_bf16(acc[0], Ah, Bh);
            mma_bf16(acc[0], Ah, Bl);
            mma_bf16(acc[0], Al, Bh);
        } else {
#pragma unroll
            for (int ks = 0; ks < 4; ks++) {
                uint32_t Ah[4], Al[4], Bh[4], Bl[4];
                ldsm4(Ah, qh + ks * 32);
                ldsm4(Al, ql + ks * 32);
                ldsm4t(Bh, kh + ks * 16 * PK * 2);
                ldsm4t(Bl, kl + ks * 16 * PK * 2);
#pragma unroll
                for (int sub = 0; sub < 2; sub++) {
                    mma_bf16(acc[sub], Ah, Bh + 2 * sub);
                    mma_bf16(acc[sub], Ah, Bl + 2 * sub);
                    mma_bf16(acc[sub], Al, Bh + 2 * sub);
                }
            }
        }
        if (chk < NCH - 1) STORE(1 - cb);
        __syncthreads();
    }

    if (CELL0) {
        float* red = reinterpret_cast<float*>(smb);
        red[warp * 128 + g * 8 + 2 * tg]           = acc[0][0];
        red[warp * 128 + g * 8 + 2 * tg + 1]       = acc[0][1];
        red[warp * 128 + (g + 8) * 8 + 2 * tg]     = acc[0][2];
        red[warp * 128 + (g + 8) * 8 + 2 * tg + 1] = acc[0][3];
        __syncthreads();
        if (tid < 128) {
            float sum = 0.f;
#pragma unroll
            for (int w = 0; w < 8; w++) sum += red[w * 128 + tid];
            Sp[(size_t)sl * 256 + b * 128 + tid] = sum;
        }
    } else {
        size_t base = (size_t)sl * 4096 + b * 2048;
#pragma unroll
        for (int sub = 0; sub < 2; sub++) {
            int s0 = wn * 16 + sub * 8 + 2 * tg;
            int i0 = wm * 16 + g;
            Sp[base + i0 * 32 + s0]           = acc[sub][0];
            Sp[base + i0 * 32 + s0 + 1]       = acc[sub][1];
            Sp[base + (i0 + 8) * 32 + s0]     = acc[sub][2];
            Sp[base + (i0 + 8) * 32 + s0 + 1] = acc[sub][3];
        }
    }
}

// ---------------- reduce partials + softmax over A2 --------------------------
__global__ __launch_bounds__(256) void softmax_reduce(
    const float* __restrict__ Sp, float* __restrict__ S,
    int A2, int nsl, int rowtot)
{
    int row = blockIdx.x * 8 + (threadIdx.x >> 5);
    int s = threadIdx.x & 31;
    float v = 0.f;
    if (s < A2) {
        for (int sl = 0; sl < nsl; sl += 4) {
            v += Sp[(size_t)(sl + 0) * rowtot + row * A2 + s]
               + Sp[(size_t)(sl + 1) * rowtot + row * A2 + s]
               + Sp[(size_t)(sl + 2) * rowtot + row * A2 + s]
               + Sp[(size_t)(sl + 3) * rowtot + row * A2 + s];
        }
    }
    float vm = (s < A2) ? v : -1e30f;
#pragma unroll
    for (int off = 16; off; off >>= 1)
        vm = fmaxf(vm, __shfl_xor_sync(0xffffffffu, vm, off));
    float e = (s < A2) ? expf(v - vm) : 0.f;
    float sum = e;
#pragma unroll
    for (int off = 16; off; off >>= 1)
        sum += __shfl_xor_sync(0xffffffffu, sum, off);
    if (s < A2) S[row * A2 + s] = e / sum;
}

// ---------------- o-GEMM + un-permute + residual (cells T, W) ---------------
template<int CELL>
__global__ __launch_bounds__(256) void epilogue_kernel(
    const float* __restrict__ v, const float* __restrict__ S,
    const float* __restrict__ cur, float* __restrict__ outp,
    const float* __restrict__ gammap)
{
    constexpr int A  = (CELL == 0) ? 16 : 64;
    constexpr int A2 = (CELL == 0) ? 8 : 32;
    constexpr int d  = (CELL == 0) ? 4096 : 1024;

    int b = blockIdx.y;
    __shared__ float attnS[A * A2];
    int tid = threadIdx.x;
    for (int idx = tid; idx < A * A2; idx += 256)
        attnS[idx] = S[b * A * A2 + idx];
    __syncthreads();

    float g = gammap[0];
    int x = blockIdx.x * 256 + tid;

    const float4* vr4 = reinterpret_cast<const float4*>(
        v + (size_t)b * 8388608 + (size_t)x * A2);
    float vv[A2];
#pragma unroll
    for (int s4 = 0; s4 < A2 / 4; s4++) {
        float4 t = vr4[s4];
        vv[s4 * 4 + 0] = t.x; vv[s4 * 4 + 1] = t.y;
        vv[s4 * 4 + 2] = t.z; vv[s4 * 4 + 3] = t.w;
    }
    int c  = x / d;
    int p  = x % d;
    int p1 = p / 64;
    int p2 = p % 64;
    size_t boff = (size_t)b * 16777216 + (size_t)c * 65536;
    int base, stride;
    if (CELL == 0) { base = p1 * 64   + p2; stride = 4096; }
    else           { base = p1 * 4096 + p2; stride = 64;   }

#pragma unroll 4
    for (int a = 0; a < A; a++) {
        float o = 0.f;
#pragma unroll
        for (int s = 0; s < A2; s++) o += vv[s] * attnS[a * A2 + s];
        int off = base + a * stride;
        outp[boff + off] = g * o + cur[boff + off];
    }
}

// ---------------- cell-H epilogue: smem transpose, fully coalesced I/O ------
__global__ __launch_bounds__(256) void epilogue2_kernel(
    const float* __restrict__ v, const float* __restrict__ S,
    const float* __restrict__ cur, float* __restrict__ outp,
    const float* __restrict__ gammap)
{
    int b  = blockIdx.y;
    int cp = blockIdx.x;        // c*16 + p1
    int c = cp >> 4, p1 = cp & 15;

    __shared__ float attnS[64 * 33];
    __shared__ float vs[64 * 33];
    __shared__ float os[64 * 65];
    int tid = threadIdx.x;

    for (int i = tid; i < 2048; i += 256)
        attnS[(i >> 5) * 33 + (i & 31)] = S[b * 2048 + i];
    size_t vbase = (size_t)b * 8388608 + ((size_t)c * 1024 + p1 * 64) * 32;
    for (int i = tid; i < 2048; i += 256)
        vs[(i >> 5) * 33 + (i & 31)] = v[vbase + i];
    __syncthreads();

    int p2 = tid & 63;
    int a0 = (tid >> 6) * 16;
    float vv[32];
#pragma unroll
    for (int s = 0; s < 32; s++) vv[s] = vs[p2 * 33 + s];
#pragma unroll
    for (int ai = 0; ai < 16; ai++) {
        int a = a0 + ai;
        float o = 0.f;
#pragma unroll
        for (int s = 0; s < 32; s++) o += vv[s] * attnS[a * 33 + s];
        os[p2 * 65 + a] = o;
    }
    __syncthreads();

    float g = gammap[0];
    size_t obase = (size_t)b * 16777216 + (size_t)c * 65536 + (size_t)p1 * 4096;
    for (int i = tid; i < 4096; i += 256)
        outp[obase + i] = g * os[(i >> 6) * 65 + (i & 63)] + cur[obase + i];
}

// ---------------- host orchestration ----------------
extern "C" void kernel_launch(void* const* d_in, const int* in_sizes, int n_in,
                              void* d_out, int out_size)
{
    const float* x  = (const float*)d_in[0];
    const float* Wq = (const float*)d_in[1];
    const float* bq = (const float*)d_in[2];
    const float* Wk = (const float*)d_in[3];
    const float* bk = (const float*)d_in[4];
    const float* Wv = (const float*)d_in[5];
    const float* bv = (const float*)d_in[6];
    const float* gm = (const float*)d_in[7];
    float* out = (float*)d_out;

    float *buf0, *buf1, *xp, *q, *k, *v, *Sp, *S;
    cudaGetSymbolAddress((void**)&buf0, g_buf0);
    cudaGetSymbolAddress((void**)&buf1, g_buf1);
    cudaGetSymbolAddress((void**)&xp,   g_xp);
    cudaGetSymbolAddress((void**)&q,    g_q);
    cudaGetSymbolAddress((void**)&k,    g_k);
    cudaGetSymbolAddress((void**)&v,    g_v);
    cudaGetSymbolAddress((void**)&Sp,   g_Sp);
    cudaGetSymbolAddress((void**)&S,    g_S);

    const int SM_CF = 2 * 256 * 136 * 2;                                // 139264
    const int SM_A0 = (2 * 2176 + 2 * 2176 + 2 * 1024 + 2 * 1024) * 2;  // 25600
    const int SM_A1 = (2 * 4608 + 2 * 4608 + 2 * 2560 + 2 * 2560) * 2;  // 57344

    cudaFuncSetAttribute(conv_fx<0,12>, cudaFuncAttributeMaxDynamicSharedMemorySize, SM_CF);
    cudaFuncSetAttribute(conv_fx<1,10>, cudaFuncAttributeMaxDynamicSharedMemorySize, SM_CF);
    cudaFuncSetAttribute(conv_fx<0,10>, cudaFuncAttributeMaxDynamicSharedMemorySize, SM_CF);
    cudaFuncSetAttribute(attn_mma<1>, cudaFuncAttributeMaxDynamicSharedMemorySize, SM_A0);
    cudaFuncSetAttribute(attn_mma<0>, cudaFuncAttributeMaxDynamicSharedMemorySize, SM_A1);

    // ================= cell 0 : attention over T (identity permutation) ======
    {
        wfrag_prep<<<64, 256>>>(Wq, Wk, Wv);
        conv_fx<0,12><<<dim3(512, 1, 2), 256, SM_CF>>>(x, bq, bk, bv, q, k, v);
        attn_mma<1><<<dim3(256, 2), 256, SM_A0>>>(q, k, Sp);
        softmax_reduce<<<4, 256>>>(Sp, S, 8, 256, 256);
        epilogue_kernel<0><<<dim3(4096, 2), 256>>>(v, S, x, buf0, gm + 0);
    }
    // ================= cell 1 : attention over W (fused permute in conv) =====
    {
        wfrag_prep<<<64, 256>>>(Wq + 32768, Wk + 32768, Wv + 65536);
        conv_fx<1,10><<<dim3(512, 1, 2), 256, SM_CF>>>(
            buf0, bq + 128, bk + 128, bv + 256, q, k, v);
        attn_mma<0><<<dim3(256, 2), 256, SM_A1>>>(q, k, Sp);
        softmax_reduce<<<16, 256>>>(Sp, S, 32, 256, 4096);
        epilogue_kernel<1><<<dim3(1024, 2), 256>>>(v, S, buf0, buf1, gm + 1);
    }
    // ================= cell 2 : attention over H ==============================
    {
        permuteH_kernel<<<dim3(64, 256, 2), 256>>>(buf1, xp);
        wfrag_prep<<<64, 256>>>(Wq + 65536, Wk + 65536, Wv + 131072);
        conv_fx<0,10><<<dim3(512, 1, 2), 256, SM_CF>>>(
            xp, bq + 256, bk + 256, bv + 512, q, k, v);
        attn_mma<0><<<dim3(256, 2), 256, SM_A1>>>(q, k, Sp);
        softmax_reduce<<<16, 256>>>(Sp, S, 32, 256, 4096);
        epilogue2_kernel<<<dim3(4096, 2), 256>>>(v, S, buf1, out, gm + 2);
    }
}

// round 10
// speedup vs baseline: 3.1498x; 1.0765x over previous
#include <cuda_runtime.h>
#include <cuda_bf16.h>
#include <cstdint>

#define NEL 33554432           // 2*256*16*64*64
#define NSP 65536               // T*W*H

// ---------------- scratch (device globals; no runtime alloc) ----------------
__device__ float g_buf0[NEL];
__device__ float g_buf1[NEL];
__device__ float g_xp[NEL];
__device__ float g_q[16777216];   // B * 128 * 65536
__device__ float g_k[8388608];    // B * 128 * 32768
__device__ float g_v[16777216];   // B * 256 * 32768
__device__ float g_Sp[1048576];   // split-K partials (256 slices * 4096)
__device__ float g_S[4096];       // attn after softmax: B*64*32 max
// fragment-major packed weights: 512 rows x 256 cols -> 32 mtiles x 16 ktiles
__device__ __align__(16) uint32_t g_wfh[65536];
__device__ __align__(16) uint32_t g_wfl[65536];

// ---------------- helpers ----------------
__device__ __forceinline__ float4 ld4(const float* p) {
    return *reinterpret_cast<const float4*>(p);
}
__device__ __forceinline__ void split_f4(float4 v, uint2& h, uint2& l) {
    asm("cvt.rn.bf16x2.f32 %0, %1, %2;" : "=r"(h.x) : "f"(v.y), "f"(v.x));
    asm("cvt.rn.bf16x2.f32 %0, %1, %2;" : "=r"(h.y) : "f"(v.w), "f"(v.z));
    float rx = v.x - __uint_as_float(h.x << 16);
    float ry = v.y - __uint_as_float(h.x & 0xffff0000u);
    float rz = v.z - __uint_as_float(h.y << 16);
    float rw = v.w - __uint_as_float(h.y & 0xffff0000u);
    asm("cvt.rn.bf16x2.f32 %0, %1, %2;" : "=r"(l.x) : "f"(ry), "f"(rx));
    asm("cvt.rn.bf16x2.f32 %0, %1, %2;" : "=r"(l.y) : "f"(rw), "f"(rz));
}
__device__ __forceinline__ void split_pair(float a, float b, uint32_t& h, uint32_t& l) {
    asm("cvt.rn.bf16x2.f32 %0, %1, %2;" : "=r"(h) : "f"(b), "f"(a));
    float ra = a - __uint_as_float(h << 16);
    float rb = b - __uint_as_float(h & 0xffff0000u);
    asm("cvt.rn.bf16x2.f32 %0, %1, %2;" : "=r"(l) : "f"(rb), "f"(ra));
}
__device__ __forceinline__ void ldsm4(uint32_t* r, uint32_t a) {
    asm volatile("ldmatrix.sync.aligned.m8n8.x4.shared.b16 {%0,%1,%2,%3}, [%4];"
        : "=r"(r[0]), "=r"(r[1]), "=r"(r[2]), "=r"(r[3]) : "r"(a));
}
__device__ __forceinline__ void ldsm4t(uint32_t* r, uint32_t a) {
    asm volatile("ldmatrix.sync.aligned.m8n8.x4.trans.shared.b16 {%0,%1,%2,%3}, [%4];"
        : "=r"(r[0]), "=r"(r[1]), "=r"(r[2]), "=r"(r[3]) : "r"(a));
}
__device__ __forceinline__ void ldsm2t(uint32_t* r, uint32_t a) {
    asm volatile("ldmatrix.sync.aligned.m8n8.x2.trans.shared.b16 {%0,%1}, [%2];"
        : "=r"(r[0]), "=r"(r[1]) : "r"(a));
}
__device__ __forceinline__ void mma_bf16(float* d, const uint32_t* a, const uint32_t* b) {
    asm volatile("mma.sync.aligned.m16n8k16.row.col.f32.bf16.bf16.f32 "
        "{%0,%1,%2,%3}, {%4,%5,%6,%7}, {%8,%9}, {%0,%1,%2,%3};"
        : "+f"(d[0]), "+f"(d[1]), "+f"(d[2]), "+f"(d[3])
        : "r"(a[0]), "r"(a[1]), "r"(a[2]), "r"(a[3]), "r"(b[0]), "r"(b[1]));
}

// ---------------- W fragment pre-pack (per cell) -----------------------------
__global__ __launch_bounds__(256) void wfrag_prep(
    const float* __restrict__ Wq, const float* __restrict__ Wk,
    const float* __restrict__ Wv)
{
    int idx = blockIdx.x * 256 + threadIdx.x;   // 16384 = 512 tiles * 32 lanes
    int tile = idx >> 5, lane = idx & 31;
    int mtile = tile >> 4, kt = tile & 15;
    int g = lane >> 2, tg = lane & 3;
    int r0 = mtile * 16 + g;
    int c0 = kt * 16 + tg * 2;

    uint32_t h[4], l[4];
#pragma unroll
    for (int j = 0; j < 4; j++) {
        int r = r0 + ((j & 1) ? 8 : 0);
        int c = c0 + ((j & 2) ? 8 : 0);
        const float* Wr;
        if (r < 128)      Wr = Wq + r * 256;
        else if (r < 256) Wr = Wk + (r - 128) * 256;
        else              Wr = Wv + (r - 256) * 256;
        split_pair(Wr[c], Wr[c + 1], h[j], l[j]);
    }
    *(uint4*)&g_wfh[tile * 128 + lane * 4] = make_uint4(h[0], h[1], h[2], h[3]);
    *(uint4*)&g_wfl[tile * 128 + lane * 4] = make_uint4(l[0], l[1], l[2], l[3]);
}

// ---------------- permute H (canonical -> [c][h][w][t]) via smem transpose ---
__global__ __launch_bounds__(256) void permuteH_kernel(
    const float* __restrict__ src, float* __restrict__ dst)
{
    __shared__ float s[16][65];
    int w = blockIdx.x;
    int c = blockIdx.y;
    int b = blockIdx.z;
    size_t base = ((size_t)b * 256 + c) * 65536;
    int tid = threadIdx.x;
    for (int idx = tid; idx < 1024; idx += 256) {
        int t = idx >> 6, h = idx & 63;
        s[t][h] = src[base + (size_t)t * 4096 + w * 64 + h];
    }
    __syncthreads();
    for (int idx = tid; idx < 1024; idx += 256) {
        int h = idx >> 4, t = idx & 15;
        dst[base + (size_t)h * 1024 + w * 16 + t] = s[t][h];
    }
}

// ---------------- fused q/k/v conv1x1, 512 threads (4 warps/SMSP) -----------
// 16 warps: wm = warp&7 (8 m-groups of 16 rows), wn = warp>>3 (2 n-groups).
// X panel (hi/lo) resident; A-frags LDG.128 from L2-resident fragment-major W.
template<int MODE, int LOGD>
__global__ __launch_bounds__(512) void conv_fx(
    const float* __restrict__ X,
    const float* __restrict__ bq, const float* __restrict__ bk,
    const float* __restrict__ bv,
    float* __restrict__ qo, float* __restrict__ ko, float* __restrict__ vo)
{
    constexpr int PP = 136;            // panel pitch (bf16)
    constexpr int PT = 256 * PP;       // panel elems per (hi|lo)

    extern __shared__ char smem_raw[];
    __nv_bfloat16* XPH = reinterpret_cast<__nv_bfloat16*>(smem_raw);
    __nv_bfloat16* XPL = XPH + PT;

    int b  = blockIdx.z;
    int n0 = blockIdx.x * 64;
    const float* Xb = X + (size_t)b * 256 * NSP;

    int tid  = threadIdx.x;
    int lane = tid & 31, warp = tid >> 5;
    int wm = warp & 7, wn = warp >> 3;      // 8 m-groups x 2 n-groups
    int g = lane >> 2, tg = lane & 3;
    int r8 = (lane & 7) + (lane & 8);
    int ch = (lane & 16) >> 1;

    // ---- strip bases ----
    int s0, s1, qc0, qc1;
    if (MODE == 0) {
        int a2 = n0 >> LOGD;
        int p0 = n0 & ((1 << LOGD) - 1);
        s0 = ((2 * a2) << LOGD) + p0;
        s1 = s0 + (1 << LOGD);
        qc0 = s0; qc1 = s1;
    } else {   // cell W canonical: col = a*1024 + p1*64 + p2 -> src p1*4096 + a*64 + p2
        int aa = n0 >> 10;
        int r  = n0 & 1023;
        s0 = (r >> 6) * 4096 + (2 * aa) * 64;
        s1 = s0 + 64;
        qc0 = (2 * aa) * 1024 + r;
        qc1 = qc0 + 1024;
    }

    // ---- fill X panel (once) ----
    {
        int prow = tid >> 4;               // 0..31
        int pcol = (tid & 15) * 4;
#pragma unroll
        for (int it = 0; it < 8; it++) {
            int row = it * 32 + prow;
            float4 x0 = ld4(Xb + (size_t)row * NSP + s0 + pcol);
            float4 x1 = ld4(Xb + (size_t)row * NSP + s1 + pcol);
            uint2 h0, l0, h1, l1;
            split_f4(x0, h0, l0);
            split_f4(x1, h1, l1);
            *(uint2*)&XPH[row * PP + pcol]      = h0;
            *(uint2*)&XPL[row * PP + pcol]      = l0;
            *(uint2*)&XPH[row * PP + 64 + pcol] = h1;
            *(uint2*)&XPL[row * PP + 64 + pcol] = l1;
        }
    }
    __syncthreads();

    uint32_t sb = (uint32_t)__cvta_generic_to_shared(XPH);
    const uint4* wfh4 = reinterpret_cast<const uint4*>(g_wfh);
    const uint4* wfl4 = reinterpret_cast<const uint4*>(g_wfl);

#pragma unroll 1
    for (int mc = 0; mc < 4; mc++) {
        const bool need_lo = (mc < 2);

        float acc[8][4];
#pragma unroll
        for (int nt = 0; nt < 8; nt++)
#pragma unroll
            for (int r = 0; r < 4; r++) acc[nt][r] = 0.f;

        int tbase = (mc * 8 + wm) * 16;    // this warp's mtile, ktile base

#pragma unroll 2
        for (int kt = 0; kt < 16; kt++) {
            uint4 Ah = wfh4[(tbase + kt) * 32 + lane];
            uint4 Al;
            if (need_lo) Al = wfl4[(tbase + kt) * 32 + lane];
#pragma unroll
            for (int pp = 0; pp < 4; pp++) {
                int pcolp = (pp < 2) ? (wn * 32 + pp * 16)
                                     : (64 + wn * 32 + (pp - 2) * 16);
                uint32_t bh_a = sb + (((kt * 16 + r8) * PP) + ch + pcolp) * 2;
                uint32_t Bh[4], Bl[4];
                ldsm4t(Bh, bh_a);
                if (need_lo) ldsm4t(Bl, bh_a + PT * 2);
#pragma unroll
                for (int sub = 0; sub < 2; sub++) {
                    float* d = acc[pp * 2 + sub];
                    mma_bf16(d, (const uint32_t*)&Ah, Bh + 2 * sub);
                    if (need_lo) {
                        mma_bf16(d, (const uint32_t*)&Ah, Bl + 2 * sub);
                        mma_bf16(d, (const uint32_t*)&Al, Bh + 2 * sub);
                    }
                }
            }
        }

        // ---- chunk epilogue ----
        if (mc == 0) {
            float* outb = qo + (size_t)b * 8388608;
            int r = wm * 16 + g;
            float b0 = bq[r], b1 = bq[r + 8];
#pragma unroll
            for (int nt = 0; nt < 8; nt++) {
                int lcol = wn * 32 + ((nt & 3) >> 1) * 16 + (nt & 1) * 8 + tg * 2;
                int col = (nt < 4 ? qc0 : qc1) + lcol;
                *(float2*)&outb[(size_t)r * 65536 + col] =
                    make_float2(acc[nt][0] + b0, acc[nt][1] + b0);
                *(float2*)&outb[(size_t)(r + 8) * 65536 + col] =
                    make_float2(acc[nt][2] + b1, acc[nt][3] + b1);
            }
        } else {
            float* outb = (mc == 1) ? (ko + (size_t)b * 4194304)
                                    : (vo + (size_t)b * 8388608 + (size_t)(mc - 2) * 4194304);
            const float* bc = (mc == 1) ? bk : (bv + (mc - 2) * 128);
            int r = wm * 16 + g;
            float b0 = bc[r], b1 = bc[r + 8];
#pragma unroll
            for (int nt = 0; nt < 4; nt++) {
                int col = n0 + wn * 32 + (nt >> 1) * 16 + (nt & 1) * 8 + tg * 2;
                float v00 = fmaxf(acc[nt][0], acc[nt + 4][0]) + b0;
                float v01 = fmaxf(acc[nt][1], acc[nt + 4][1]) + b0;
                float v10 = fmaxf(acc[nt][2], acc[nt + 4][2]) + b1;
                float v11 = fmaxf(acc[nt][3], acc[nt + 4][3]) + b1;
                *(float2*)&outb[(size_t)r * 32768 + col]       = make_float2(v00, v01);
                *(float2*)&outb[(size_t)(r + 8) * 32768 + col] = make_float2(v10, v11);
            }
        }
    }
}

// ---------------- attention logits: bf16x3 tensor-core streaming GEMM -------
template<int CELL0>
__global__ __launch_bounds__(256) void attn_mma(
    const float* __restrict__ q, const float* __restrict__ k,
    float* __restrict__ Sp)
{
    constexpr int Ac  = CELL0 ? 16 : 64;
    constexpr int A2c = CELL0 ? 8  : 32;
    constexpr int K   = CELL0 ? 524288 : 131072;
    constexpr int KSL = K / 256;
    constexpr int CJ  = CELL0 ? 128 : 64;
    constexpr int NCH = KSL / CJ;
    constexpr int PQ  = CELL0 ? 136 : 72;
    constexpr int PK  = CELL0 ? 8 : 40;
    constexpr int QT  = Ac * PQ;
    constexpr int KT  = CJ * PK;
    constexpr int NQ  = CELL0 ? 2 : 4;
    constexpr int NK  = CELL0 ? 1 : 2;

    extern __shared__ __nv_bfloat16 smb[];
    __nv_bfloat16 *QH = smb, *QL = QH + 2 * QT, *KH = QL + 2 * QT, *KL = KH + 2 * KT;

    int b = blockIdx.y, sl = blockIdx.x;
    const float* qb = q + (size_t)b * Ac * K + (size_t)sl * KSL;
    const float* kb = k + ((size_t)b * K + (size_t)sl * KSL) * A2c;

    int tid = threadIdx.x, lane = tid & 31, warp = tid >> 5;
    int g = lane >> 2, tg = lane & 3;

    float4 qv[NQ], kv[NK];
    auto LOAD = [&](int chk) {
        int j0 = chk * CJ;
#pragma unroll
        for (int l = 0; l < NQ; l++) {
            int idx = tid + 256 * l;
            int row = CELL0 ? (idx >> 5) : (idx >> 4);
            int c   = CELL0 ? ((idx & 31) * 4) : ((idx & 15) * 4);
            qv[l] = ld4(qb + (size_t)row * K + j0 + c);
        }
#pragma unroll
        for (int l = 0; l < NK; l++) {
            int idx = tid + 256 * l;
            int row = CELL0 ? (idx >> 1) : (idx >> 3);
            int c   = CELL0 ? ((idx & 1) * 4) : ((idx & 7) * 4);
            kv[l] = ld4(kb + (size_t)(j0 + row) * A2c + c);
        }
    };
    auto STORE = [&](int bf) {
#pragma unroll
        for (int l = 0; l < NQ; l++) {
            int idx = tid + 256 * l;
            int row = CELL0 ? (idx >> 5) : (idx >> 4);
            int c   = CELL0 ? ((idx & 31) * 4) : ((idx & 15) * 4);
            uint2 h, lo;
            split_f4(qv[l], h, lo);
            int off = bf * QT + row * PQ + c;
            *(uint2*)&QH[off] = h;
            *(uint2*)&QL[off] = lo;
        }
#pragma unroll
        for (int l = 0; l < NK; l++) {
            int idx = tid + 256 * l;
            int row = CELL0 ? (idx >> 1) : (idx >> 3);
            int c   = CELL0 ? ((idx & 1) * 4) : ((idx & 7) * 4);
            uint2 h, lo;
            split_f4(kv[l], h, lo);
            int off = bf * KT + row * PK + c;
            *(uint2*)&KH[off] = h;
            *(uint2*)&KL[off] = lo;
        }
    };

    uint32_t sb = (uint32_t)__cvta_generic_to_shared(smb);
    int r8 = (lane & 7) + (lane & 8);
    int aoe, boe, wm = warp & 3, wn = warp >> 2;
    if (CELL0) {
        aoe = r8 * PQ + ((lane & 16) >> 1) + warp * 16;
        boe = (warp * 16 + (lane & 15)) * PK;
    } else {
        aoe = (wm * 16 + r8) * PQ + ((lane & 16) >> 1);
        boe = r8 * PK + ((lane & 16) >> 1) + wn * 16;
    }
    constexpr int NACC = CELL0 ? 1 : 2;
    float acc[NACC][4];
#pragma unroll
    for (int a = 0; a < NACC; a++)
#pragma unroll
        for (int r = 0; r < 4; r++) acc[a][r] = 0.f;

    LOAD(0);
    STORE(0);
    __syncthreads();

#pragma unroll 1
    for (int chk = 0; chk < NCH; chk++) {
        int cb = chk & 1;
        if (chk < NCH - 1) LOAD(chk + 1);
        uint32_t qh = sb + (cb * QT + aoe) * 2;
        uint32_t ql = qh + 2 * QT * 2;
        uint32_t kh = sb + 4 * QT * 2 + (cb * KT + boe) * 2;
        uint32_t kl = kh + 2 * KT * 2;
        if (CELL0) {
            uint32_t Ah[4], Al[4], Bh[2], Bl[2];
            ldsm4(Ah, qh); ldsm4(Al, ql);
            ldsm2t(Bh, kh); ldsm2t(Bl, kl);
            mma_bf16(acc[0], Ah, Bh);
            mma_bf16(acc[0], Ah, Bl);
            mma_bf16(acc[0], Al, Bh);
        } else {
#pragma unroll
            for (int ks = 0; ks < 4; ks++) {
                uint32_t Ah[4], Al[4], Bh[4], Bl[4];
                ldsm4(Ah, qh + ks * 32);
                ldsm4(Al, ql + ks * 32);
                ldsm4t(Bh, kh + ks * 16 * PK * 2);
                ldsm4t(Bl, kl + ks * 16 * PK * 2);
#pragma unroll
                for (int sub = 0; sub < 2; sub++) {
                    mma_bf16(acc[sub], Ah, Bh + 2 * sub);
                    mma_bf16(acc[sub], Ah, Bl + 2 * sub);
                    mma_bf16(acc[sub], Al, Bh + 2 * sub);
                }
            }
        }
        if (chk < NCH - 1) STORE(1 - cb);
        __syncthreads();
    }

    if (CELL0) {
        float* red = reinterpret_cast<float*>(smb);
        red[warp * 128 + g * 8 + 2 * tg]           = acc[0][0];
        red[warp * 128 + g * 8 + 2 * tg + 1]       = acc[0][1];
        red[warp * 128 + (g + 8) * 8 + 2 * tg]     = acc[0][2];
        red[warp * 128 + (g + 8) * 8 + 2 * tg + 1] = acc[0][3];
        __syncthreads();
        if (tid < 128) {
            float sum = 0.f;
#pragma unroll
            for (int w = 0; w < 8; w++) sum += red[w * 128 + tid];
            Sp[(size_t)sl * 256 + b * 128 + tid] = sum;
        }
    } else {
        size_t base = (size_t)sl * 4096 + b * 2048;
#pragma unroll
        for (int sub = 0; sub < 2; sub++) {
            int s0 = wn * 16 + sub * 8 + 2 * tg;
            int i0 = wm * 16 + g;
            Sp[base + i0 * 32 + s0]           = acc[sub][0];
            Sp[base + i0 * 32 + s0 + 1]       = acc[sub][1];
            Sp[base + (i0 + 8) * 32 + s0]     = acc[sub][2];
            Sp[base + (i0 + 8) * 32 + s0 + 1] = acc[sub][3];
        }
    }
}

// ---------------- reduce partials + softmax: one block per row ---------------
__global__ __launch_bounds__(256) void softmax_reduce(
    const float* __restrict__ Sp, float* __restrict__ S,
    int A2, int rowtot)
{
    __shared__ float red[256];
    int row = blockIdx.x;
    int tid = threadIdx.x;
    int s = tid & (A2 - 1);
    int chunk = tid / A2;          // 256/A2 chunks, each covers A2 slices
    float v = 0.f;
#pragma unroll 4
    for (int i = 0; i < 32; i++) {   // A2 slices per chunk, max 32
        if (i >= A2) break;
        int sl = chunk * A2 + i;
        v += Sp[(size_t)sl * rowtot + row * A2 + s];
    }
    red[tid] = v;
    __syncthreads();
    for (int off = 128; off >= A2 && off >= 32; off >>= 1) {
        if (tid < off) red[tid] += red[tid + off];
        __syncthreads();
    }
    // remaining chunk folds within first warp region
    if (tid < 32) {
        float val = red[tid];
        for (int off = 32; off >= A2 && off < 32; off >>= 1) {} // no-op guard
        if (A2 < 32) {
            // fold chunks still present in [0,32): stride A2
            for (int off = 16; off >= A2; off >>= 1)
                val += red[tid + off] * 0.f + __shfl_down_sync(0xffffffffu, val, off) * 0.f
                     , val = val; // placeholder (handled below)
        }
        red[tid] = val;
    }
    __syncthreads();
    // final fold for A2 < 32: sum red[chunk*A2+s] over remaining chunks in [0,32)
    if (tid < A2) {
        float val = 0.f;
        int nch = 32 / A2;          // chunks remaining after tree (>=1)
        for (int c = 0; c < nch; c++) val += red[c * A2 + tid];
        unsigned mask = (A2 == 32) ? 0xffffffffu : ((1u << A2) - 1u);
        float vm = val;
        for (int off = A2 >> 1; off; off >>= 1)
            vm = fmaxf(vm, __shfl_xor_sync(mask, vm, off));
        float e = expf(val - vm);
        float sum = e;
        for (int off = A2 >> 1; off; off >>= 1)
            sum += __shfl_xor_sync(mask, sum, off);
        S[row * A2 + tid] = e / sum;
    }
}

// ---------------- o-GEMM + un-permute + residual (cells T, W) ---------------
template<int CELL>
__global__ __launch_bounds__(256) void epilogue_kernel(
    const float* __restrict__ v, const float* __restrict__ S,
    const float* __restrict__ cur, float* __restrict__ outp,
    const float* __restrict__ gammap)
{
    constexpr int A  = (CELL == 0) ? 16 : 64;
    constexpr int A2 = (CELL == 0) ? 8 : 32;
    constexpr int d  = (CELL == 0) ? 4096 : 1024;

    int b = blockIdx.y;
    __shared__ float attnS[A * A2];
    int tid = threadIdx.x;
    for (int idx = tid; idx < A * A2; idx += 256)
        attnS[idx] = S[b * A * A2 + idx];
    __syncthreads();

    float g = gammap[0];
    int x = blockIdx.x * 256 + tid;

    const float4* vr4 = reinterpret_cast<const float4*>(
        v + (size_t)b * 8388608 + (size_t)x * A2);
    float vv[A2];
#pragma unroll
    for (int s4 = 0; s4 < A2 / 4; s4++) {
        float4 t = vr4[s4];
        vv[s4 * 4 + 0] = t.x; vv[s4 * 4 + 1] = t.y;
        vv[s4 * 4 + 2] = t.z; vv[s4 * 4 + 3] = t.w;
    }
    int c  = x / d;
    int p  = x % d;
    int p1 = p / 64;
    int p2 = p % 64;
    size_t boff = (size_t)b * 16777216 + (size_t)c * 65536;
    int base, stride;
    if (CELL == 0) { base = p1 * 64   + p2; stride = 4096; }
    else           { base = p1 * 4096 + p2; stride = 64;   }

#pragma unroll 4
    for (int a = 0; a < A; a++) {
        float o = 0.f;
#pragma unroll
        for (int s = 0; s < A2; s++) o += vv[s] * attnS[a * A2 + s];
        int off = base + a * stride;
        outp[boff + off] = g * o + cur[boff + off];
    }
}

// ---------------- cell-H epilogue: smem transpose, fully coalesced I/O ------
__global__ __launch_bounds__(256) void epilogue2_kernel(
    const float* __restrict__ v, const float* __restrict__ S,
    const float* __restrict__ cur, float* __restrict__ outp,
    const float* __restrict__ gammap)
{
    int b  = blockIdx.y;
    int cp = blockIdx.x;        // c*16 + p1
    int c = cp >> 4, p1 = cp & 15;

    __shared__ float attnS[64 * 33];
    __shared__ float vs[64 * 33];
    __shared__ float os[64 * 65];
    int tid = threadIdx.x;

    for (int i = tid; i < 2048; i += 256)
        attnS[(i >> 5) * 33 + (i & 31)] = S[b * 2048 + i];
    size_t vbase = (size_t)b * 8388608 + ((size_t)c * 1024 + p1 * 64) * 32;
    for (int i = tid; i < 2048; i += 256)
        vs[(i >> 5) * 33 + (i & 31)] = v[vbase + i];
    __syncthreads();

    int p2 = tid & 63;
    int a0 = (tid >> 6) * 16;
    float vv[32];
#pragma unroll
    for (int s = 0; s < 32; s++) vv[s] = vs[p2 * 33 + s];
#pragma unroll
    for (int ai = 0; ai < 16; ai++) {
        int a = a0 + ai;
        float o = 0.f;
#pragma unroll
        for (int s = 0; s < 32; s++) o += vv[s] * attnS[a * 33 + s];
        os[p2 * 65 + a] = o;
    }
    __syncthreads();

    float g = gammap[0];
    size_t obase = (size_t)b * 16777216 + (size_t)c * 65536 + (size_t)p1 * 4096;
    for (int i = tid; i < 4096; i += 256)
        outp[obase + i] = g * os[(i >> 6) * 65 + (i & 63)] + cur[obase + i];
}

// ---------------- host orchestration ----------------
extern "C" void kernel_launch(void* const* d_in, const int* in_sizes, int n_in,
                              void* d_out, int out_size)
{
    const float* x  = (const float*)d_in[0];
    const float* Wq = (const float*)d_in[1];
    const float* bq = (const float*)d_in[2];
    const float* Wk = (const float*)d_in[3];
    const float* bk = (const float*)d_in[4];
    const float* Wv = (const float*)d_in[5];
    const float* bv = (const float*)d_in[6];
    const float* gm = (const float*)d_in[7];
    float* out = (float*)d_out;

    float *buf0, *buf1, *xp, *q, *k, *v, *Sp, *S;
    cudaGetSymbolAddress((void**)&buf0, g_buf0);
    cudaGetSymbolAddress((void**)&buf1, g_buf1);
    cudaGetSymbolAddress((void**)&xp,   g_xp);
    cudaGetSymbolAddress((void**)&q,    g_q);
    cudaGetSymbolAddress((void**)&k,    g_k);
    cudaGetSymbolAddress((void**)&v,    g_v);
    cudaGetSymbolAddress((void**)&Sp,   g_Sp);
    cudaGetSymbolAddress((void**)&S,    g_S);

    const int SM_CF = 2 * 256 * 136 * 2;                                // 139264
    const int SM_A0 = (2 * 2176 + 2 * 2176 + 2 * 1024 + 2 * 1024) * 2;  // 25600
    const int SM_A1 = (2 * 4608 + 2 * 4608 + 2 * 2560 + 2 * 2560) * 2;  // 57344

    cudaFuncSetAttribute(conv_fx<0,12>, cudaFuncAttributeMaxDynamicSharedMemorySize, SM_CF);
    cudaFuncSetAttribute(conv_fx<1,10>, cudaFuncAttributeMaxDynamicSharedMemorySize, SM_CF);
    cudaFuncSetAttribute(conv_fx<0,10>, cudaFuncAttributeMaxDynamicSharedMemorySize, SM_CF);
    cudaFuncSetAttribute(attn_mma<1>, cudaFuncAttributeMaxDynamicSharedMemorySize, SM_A0);
    cudaFuncSetAttribute(attn_mma<0>, cudaFuncAttributeMaxDynamicSharedMemorySize, SM_A1);

    // ================= cell 0 : attention over T (identity permutation) ======
    {
        wfrag_prep<<<64, 256>>>(Wq, Wk, Wv);
        conv_fx<0,12><<<dim3(512, 1, 2), 512, SM_CF>>>(x, bq, bk, bv, q, k, v);
        attn_mma<1><<<dim3(256, 2), 256, SM_A0>>>(q, k, Sp);
        softmax_reduce<<<32, 256>>>(Sp, S, 8, 256);
        epilogue_kernel<0><<<dim3(4096, 2), 256>>>(v, S, x, buf0, gm + 0);
    }
    // ================= cell 1 : attention over W (fused permute in conv) =====
    {
        wfrag_prep<<<64, 256>>>(Wq + 32768, Wk + 32768, Wv + 65536);
        conv_fx<1,10><<<dim3(512, 1, 2), 512, SM_CF>>>(
            buf0, bq + 128, bk + 128, bv + 256, q, k, v);
        attn_mma<0><<<dim3(256, 2), 256, SM_A1>>>(q, k, Sp);
        softmax_reduce<<<128, 256>>>(Sp, S, 32, 4096);
        epilogue_kernel<1><<<dim3(1024, 2), 256>>>(v, S, buf0, buf1, gm + 1);
    }
    // ================= cell 2 : attention over H ==============================
    {
        permuteH_kernel<<<dim3(64, 256, 2), 256>>>(buf1, xp);
        wfrag_prep<<<64, 256>>>(Wq + 65536, Wk + 65536, Wv + 131072);
        conv_fx<0,10><<<dim3(512, 1, 2), 512, SM_CF>>>(
            xp, bq + 256, bk + 256, bv + 512, q, k, v);
        attn_mma<0><<<dim3(256, 2), 256, SM_A1>>>(q, k, Sp);
        softmax_reduce<<<128, 256>>>(Sp, S, 32, 4096);
        epilogue2_kernel<<<dim3(4096, 2), 256>>>(v, S, buf1, out, gm + 2);
    }
}

// round 11
// speedup vs baseline: 3.4161x; 1.0845x over previous
#include <cuda_runtime.h>
#include <cuda_bf16.h>
#include <cstdint>

#define NEL 33554432           // 2*256*16*64*64
#define NSP 65536               // T*W*H

// ---------------- scratch (device globals; no runtime alloc) ----------------
__device__ float g_buf0[NEL];
__device__ float g_buf1[NEL];
__device__ float g_xp[NEL];
__device__ float g_q[16777216];   // B * 128 * 65536
__device__ float g_k[8388608];    // B * 128 * 32768
__device__ float g_v[16777216];   // B * 256 * 32768
__device__ float g_Sp[1048576];   // split-K partials (256 slices * 4096)
__device__ float g_S[4096];       // attn after softmax: B*64*32 max
// fragment-major packed weights: 512 rows x 256 cols -> 32 mtiles x 16 ktiles
__device__ __align__(16) uint32_t g_wfh[65536];
__device__ __align__(16) uint32_t g_wfl[65536];

// ---------------- helpers ----------------
__device__ __forceinline__ float4 ld4(const float* p) {
    return *reinterpret_cast<const float4*>(p);
}
__device__ __forceinline__ void split_f4(float4 v, uint2& h, uint2& l) {
    asm("cvt.rn.bf16x2.f32 %0, %1, %2;" : "=r"(h.x) : "f"(v.y), "f"(v.x));
    asm("cvt.rn.bf16x2.f32 %0, %1, %2;" : "=r"(h.y) : "f"(v.w), "f"(v.z));
    float rx = v.x - __uint_as_float(h.x << 16);
    float ry = v.y - __uint_as_float(h.x & 0xffff0000u);
    float rz = v.z - __uint_as_float(h.y << 16);
    float rw = v.w - __uint_as_float(h.y & 0xffff0000u);
    asm("cvt.rn.bf16x2.f32 %0, %1, %2;" : "=r"(l.x) : "f"(ry), "f"(rx));
    asm("cvt.rn.bf16x2.f32 %0, %1, %2;" : "=r"(l.y) : "f"(rw), "f"(rz));
}
__device__ __forceinline__ void split_pair(float a, float b, uint32_t& h, uint32_t& l) {
    asm("cvt.rn.bf16x2.f32 %0, %1, %2;" : "=r"(h) : "f"(b), "f"(a));
    float ra = a - __uint_as_float(h << 16);
    float rb = b - __uint_as_float(h & 0xffff0000u);
    asm("cvt.rn.bf16x2.f32 %0, %1, %2;" : "=r"(l) : "f"(rb), "f"(ra));
}
__device__ __forceinline__ void ldsm4(uint32_t* r, uint32_t a) {
    asm volatile("ldmatrix.sync.aligned.m8n8.x4.shared.b16 {%0,%1,%2,%3}, [%4];"
        : "=r"(r[0]), "=r"(r[1]), "=r"(r[2]), "=r"(r[3]) : "r"(a));
}
__device__ __forceinline__ void ldsm4t(uint32_t* r, uint32_t a) {
    asm volatile("ldmatrix.sync.aligned.m8n8.x4.trans.shared.b16 {%0,%1,%2,%3}, [%4];"
        : "=r"(r[0]), "=r"(r[1]), "=r"(r[2]), "=r"(r[3]) : "r"(a));
}
__device__ __forceinline__ void ldsm2t(uint32_t* r, uint32_t a) {
    asm volatile("ldmatrix.sync.aligned.m8n8.x2.trans.shared.b16 {%0,%1}, [%2];"
        : "=r"(r[0]), "=r"(r[1]) : "r"(a));
}
__device__ __forceinline__ void mma_bf16(float* d, const uint32_t* a, const uint32_t* b) {
    asm volatile("mma.sync.aligned.m16n8k16.row.col.f32.bf16.bf16.f32 "
        "{%0,%1,%2,%3}, {%4,%5,%6,%7}, {%8,%9}, {%0,%1,%2,%3};"
        : "+f"(d[0]), "+f"(d[1]), "+f"(d[2]), "+f"(d[3])
        : "r"(a[0]), "r"(a[1]), "r"(a[2]), "r"(a[3]), "r"(b[0]), "r"(b[1]));
}

// ---------------- W fragment pre-pack (per cell) -----------------------------
__global__ __launch_bounds__(256) void wfrag_prep(
    const float* __restrict__ Wq, const float* __restrict__ Wk,
    const float* __restrict__ Wv)
{
    int idx = blockIdx.x * 256 + threadIdx.x;   // 16384 = 512 tiles * 32 lanes
    int tile = idx >> 5, lane = idx & 31;
    int mtile = tile >> 4, kt = tile & 15;
    int g = lane >> 2, tg = lane & 3;
    int r0 = mtile * 16 + g;
    int c0 = kt * 16 + tg * 2;

    uint32_t h[4], l[4];
#pragma unroll
    for (int j = 0; j < 4; j++) {
        int r = r0 + ((j & 1) ? 8 : 0);
        int c = c0 + ((j & 2) ? 8 : 0);
        const float* Wr;
        if (r < 128)      Wr = Wq + r * 256;
        else if (r < 256) Wr = Wk + (r - 128) * 256;
        else              Wr = Wv + (r - 256) * 256;
        split_pair(Wr[c], Wr[c + 1], h[j], l[j]);
    }
    *(uint4*)&g_wfh[tile * 128 + lane * 4] = make_uint4(h[0], h[1], h[2], h[3]);
    *(uint4*)&g_wfl[tile * 128 + lane * 4] = make_uint4(l[0], l[1], l[2], l[3]);
}

// ---------------- permute H (canonical -> [c][h][w][t]) via smem transpose ---
__global__ __launch_bounds__(256) void permuteH_kernel(
    const float* __restrict__ src, float* __restrict__ dst)
{
    __shared__ float s[16][65];
    int w = blockIdx.x;
    int c = blockIdx.y;
    int b = blockIdx.z;
    size_t base = ((size_t)b * 256 + c) * 65536;
    int tid = threadIdx.x;
    for (int idx = tid; idx < 1024; idx += 256) {
        int t = idx >> 6, h = idx & 63;
        s[t][h] = src[base + (size_t)t * 4096 + w * 64 + h];
    }
    __syncthreads();
    for (int idx = tid; idx < 1024; idx += 256) {
        int h = idx >> 4, t = idx & 15;
        dst[base + (size_t)h * 1024 + w * 16 + t] = s[t][h];
    }
}

// ---------------- conv GEMM chunk: compile-time NPASS, pipelined ------------
template<int NPASS>
__device__ __forceinline__ void conv_chunk(
    int tbase, uint32_t sb, int wn, int r8, int ch,
    const uint4* __restrict__ wfh4, const uint4* __restrict__ wfl4,
    int lane, float acc[8][4])
{
    constexpr int PP = 136;
    constexpr int PT = 256 * PP;

    uint4 Ah = wfh4[tbase * 32 + lane];
    uint4 Al;
    if (NPASS == 3) Al = wfl4[tbase * 32 + lane];

#pragma unroll 1
    for (int kt = 0; kt < 16; kt++) {
        uint4 Ah_c = Ah, Al_c = Al;
        if (kt < 15) {
            Ah = wfh4[(tbase + kt + 1) * 32 + lane];
            if (NPASS == 3) Al = wfl4[(tbase + kt + 1) * 32 + lane];
        }
        // issue all B-fragment loads for this kt first
        uint32_t Bh[4][4], Bl[4][4];
#pragma unroll
        for (int pp = 0; pp < 4; pp++) {
            int pcolp = (pp < 2) ? (wn * 32 + pp * 16)
                                 : (64 + wn * 32 + (pp - 2) * 16);
            uint32_t ba = sb + (((kt * 16 + r8) * PP) + ch + pcolp) * 2;
            ldsm4t(Bh[pp], ba);
            if (NPASS == 3) ldsm4t(Bl[pp], ba + PT * 2);
        }
        // dense MMA block, operands resolved
#pragma unroll
        for (int pp = 0; pp < 4; pp++)
#pragma unroll
            for (int sub = 0; sub < 2; sub++) {
                float* d = acc[pp * 2 + sub];
                mma_bf16(d, (const uint32_t*)&Ah_c, Bh[pp] + 2 * sub);
                if (NPASS == 3) {
                    mma_bf16(d, (const uint32_t*)&Ah_c, Bl[pp] + 2 * sub);
                    mma_bf16(d, (const uint32_t*)&Al_c, Bh[pp] + 2 * sub);
                }
            }
    }
}

// ---------------- fused q/k/v conv1x1, 512 threads, pipelined ---------------
template<int MODE, int LOGD>
__global__ __launch_bounds__(512) void conv_fx(
    const float* __restrict__ X,
    const float* __restrict__ bq, const float* __restrict__ bk,
    const float* __restrict__ bv,
    float* __restrict__ qo, float* __restrict__ ko, float* __restrict__ vo)
{
    constexpr int PP = 136;            // panel pitch (bf16)
    constexpr int PT = 256 * PP;       // panel elems per (hi|lo)

    extern __shared__ char smem_raw[];
    __nv_bfloat16* XPH = reinterpret_cast<__nv_bfloat16*>(smem_raw);
    __nv_bfloat16* XPL = XPH + PT;

    int b  = blockIdx.z;
    int n0 = blockIdx.x * 64;
    const float* Xb = X + (size_t)b * 256 * NSP;

    int tid  = threadIdx.x;
    int lane = tid & 31, warp = tid >> 5;
    int wm = warp & 7, wn = warp >> 3;      // 8 m-groups x 2 n-groups
    int g = lane >> 2, tg = lane & 3;
    int r8 = (lane & 7) + (lane & 8);
    int ch = (lane & 16) >> 1;

    // ---- strip bases ----
    int s0, s1, qc0, qc1;
    if (MODE == 0) {
        int a2 = n0 >> LOGD;
        int p0 = n0 & ((1 << LOGD) - 1);
        s0 = ((2 * a2) << LOGD) + p0;
        s1 = s0 + (1 << LOGD);
        qc0 = s0; qc1 = s1;
    } else {   // cell W canonical: col = a*1024 + p1*64 + p2 -> src p1*4096 + a*64 + p2
        int aa = n0 >> 10;
        int r  = n0 & 1023;
        s0 = (r >> 6) * 4096 + (2 * aa) * 64;
        s1 = s0 + 64;
        qc0 = (2 * aa) * 1024 + r;
        qc1 = qc0 + 1024;
    }

    // ---- fill X panel (once) ----
    {
        int prow = tid >> 4;               // 0..31
        int pcol = (tid & 15) * 4;
#pragma unroll
        for (int it = 0; it < 8; it++) {
            int row = it * 32 + prow;
            float4 x0 = ld4(Xb + (size_t)row * NSP + s0 + pcol);
            float4 x1 = ld4(Xb + (size_t)row * NSP + s1 + pcol);
            uint2 h0, l0, h1, l1;
            split_f4(x0, h0, l0);
            split_f4(x1, h1, l1);
            *(uint2*)&XPH[row * PP + pcol]      = h0;
            *(uint2*)&XPL[row * PP + pcol]      = l0;
            *(uint2*)&XPH[row * PP + 64 + pcol] = h1;
            *(uint2*)&XPL[row * PP + 64 + pcol] = l1;
        }
    }
    __syncthreads();

    uint32_t sb = (uint32_t)__cvta_generic_to_shared(XPH);
    const uint4* wfh4 = reinterpret_cast<const uint4*>(g_wfh);
    const uint4* wfl4 = reinterpret_cast<const uint4*>(g_wfl);

    float acc[8][4];

    // ===================== mc0: q (3-pass, unpooled both strips) ============
    {
#pragma unroll
        for (int nt = 0; nt < 8; nt++)
#pragma unroll
            for (int r = 0; r < 4; r++) acc[nt][r] = 0.f;
        conv_chunk<3>((0 * 8 + wm) * 16, sb, wn, r8, ch, wfh4, wfl4, lane, acc);

        float* outb = qo + (size_t)b * 8388608;
        int r = wm * 16 + g;
        float b0 = bq[r], b1 = bq[r + 8];
#pragma unroll
        for (int nt = 0; nt < 8; nt++) {
            int lcol = wn * 32 + ((nt & 3) >> 1) * 16 + (nt & 1) * 8 + tg * 2;
            int col = (nt < 4 ? qc0 : qc1) + lcol;
            *(float2*)&outb[(size_t)r * 65536 + col] =
                make_float2(acc[nt][0] + b0, acc[nt][1] + b0);
            *(float2*)&outb[(size_t)(r + 8) * 65536 + col] =
                make_float2(acc[nt][2] + b1, acc[nt][3] + b1);
        }
    }
    // ===================== mc1..3: k (3-pass), v0, v1 (1-pass), pooled ======
#pragma unroll 1
    for (int mc = 1; mc < 4; mc++) {
#pragma unroll
        for (int nt = 0; nt < 8; nt++)
#pragma unroll
            for (int r = 0; r < 4; r++) acc[nt][r] = 0.f;
        if (mc == 1)
            conv_chunk<3>((1 * 8 + wm) * 16, sb, wn, r8, ch, wfh4, wfl4, lane, acc);
        else if (mc == 2)
            conv_chunk<1>((2 * 8 + wm) * 16, sb, wn, r8, ch, wfh4, wfl4, lane, acc);
        else
            conv_chunk<1>((3 * 8 + wm) * 16, sb, wn, r8, ch, wfh4, wfl4, lane, acc);

        float* outb = (mc == 1) ? (ko + (size_t)b * 4194304)
                                : (vo + (size_t)b * 8388608 + (size_t)(mc - 2) * 4194304);
        const float* bc = (mc == 1) ? bk : (bv + (mc - 2) * 128);
        int r = wm * 16 + g;
        float b0 = bc[r], b1 = bc[r + 8];
#pragma unroll
        for (int nt = 0; nt < 4; nt++) {
            int col = n0 + wn * 32 + (nt >> 1) * 16 + (nt & 1) * 8 + tg * 2;
            float v00 = fmaxf(acc[nt][0], acc[nt + 4][0]) + b0;
            float v01 = fmaxf(acc[nt][1], acc[nt + 4][1]) + b0;
            float v10 = fmaxf(acc[nt][2], acc[nt + 4][2]) + b1;
            float v11 = fmaxf(acc[nt][3], acc[nt + 4][3]) + b1;
            *(float2*)&outb[(size_t)r * 32768 + col]       = make_float2(v00, v01);
            *(float2*)&outb[(size_t)(r + 8) * 32768 + col] = make_float2(v10, v11);
        }
    }
}

// ---------------- attention logits: bf16x3 tensor-core streaming GEMM -------
template<int CELL0>
__global__ __launch_bounds__(256) void attn_mma(
    const float* __restrict__ q, const float* __restrict__ k,
    float* __restrict__ Sp)
{
    constexpr int Ac  = CELL0 ? 16 : 64;
    constexpr int A2c = CELL0 ? 8  : 32;
    constexpr int K   = CELL0 ? 524288 : 131072;
    constexpr int KSL = K / 256;
    constexpr int CJ  = CELL0 ? 128 : 64;
    constexpr int NCH = KSL / CJ;
    constexpr int PQ  = CELL0 ? 136 : 72;
    constexpr int PK  = CELL0 ? 8 : 40;
    constexpr int QT  = Ac * PQ;
    constexpr int KT  = CJ * PK;
    constexpr int NQ  = CELL0 ? 2 : 4;
    constexpr int NK  = CELL0 ? 1 : 2;

    extern __shared__ __nv_bfloat16 smb[];
    __nv_bfloat16 *QH = smb, *QL = QH + 2 * QT, *KH = QL + 2 * QT, *KL = KH + 2 * KT;

    int b = blockIdx.y, sl = blockIdx.x;
    const float* qb = q + (size_t)b * Ac * K + (size_t)sl * KSL;
    const float* kb = k + ((size_t)b * K + (size_t)sl * KSL) * A2c;

    int tid = threadIdx.x, lane = tid & 31, warp = tid >> 5;
    int g = lane >> 2, tg = lane & 3;

    float4 qv[NQ], kv[NK];
    auto LOAD = [&](int chk) {
        int j0 = chk * CJ;
#pragma unroll
        for (int l = 0; l < NQ; l++) {
            int idx = tid + 256 * l;
            int row = CELL0 ? (idx >> 5) : (idx >> 4);
            int c   = CELL0 ? ((idx & 31) * 4) : ((idx & 15) * 4);
            qv[l] = ld4(qb + (size_t)row * K + j0 + c);
        }
#pragma unroll
        for (int l = 0; l < NK; l++) {
            int idx = tid + 256 * l;
            int row = CELL0 ? (idx >> 1) : (idx >> 3);
            int c   = CELL0 ? ((idx & 1) * 4) : ((idx & 7) * 4);
            kv[l] = ld4(kb + (size_t)(j0 + row) * A2c + c);
        }
    };
    auto STORE = [&](int bf) {
#pragma unroll
        for (int l = 0; l < NQ; l++) {
            int idx = tid + 256 * l;
            int row = CELL0 ? (idx >> 5) : (idx >> 4);
            int c   = CELL0 ? ((idx & 31) * 4) : ((idx & 15) * 4);
            uint2 h, lo;
            split_f4(qv[l], h, lo);
            int off = bf * QT + row * PQ + c;
            *(uint2*)&QH[off] = h;
            *(uint2*)&QL[off] = lo;
        }
#pragma unroll
        for (int l = 0; l < NK; l++) {
            int idx = tid + 256 * l;
            int row = CELL0 ? (idx >> 1) : (idx >> 3);
            int c   = CELL0 ? ((idx & 1) * 4) : ((idx & 7) * 4);
            uint2 h, lo;
            split_f4(kv[l], h, lo);
            int off = bf * KT + row * PK + c;
            *(uint2*)&KH[off] = h;
            *(uint2*)&KL[off] = lo;
        }
    };

    uint32_t sb = (uint32_t)__cvta_generic_to_shared(smb);
    int r8 = (lane & 7) + (lane & 8);
    int aoe, boe, wm = warp & 3, wn = warp >> 2;
    if (CELL0) {
        aoe = r8 * PQ + ((lane & 16) >> 1) + warp * 16;
        boe = (warp * 16 + (lane & 15)) * PK;
    } else {
        aoe = (wm * 16 + r8) * PQ + ((lane & 16) >> 1);
        boe = r8 * PK + ((lane & 16) >> 1) + wn * 16;
    }
    constexpr int NACC = CELL0 ? 1 : 2;
    float acc[NACC][4];
#pragma unroll
    for (int a = 0; a < NACC; a++)
#pragma unroll
        for (int r = 0; r < 4; r++) acc[a][r] = 0.f;

    LOAD(0);
    STORE(0);
    __syncthreads();

#pragma unroll 1
    for (int chk = 0; chk < NCH; chk++) {
        int cb = chk & 1;
        if (chk < NCH - 1) LOAD(chk + 1);
        uint32_t qh = sb + (cb * QT + aoe) * 2;
        uint32_t ql = qh + 2 * QT * 2;
        uint32_t kh = sb + 4 * QT * 2 + (cb * KT + boe) * 2;
        uint32_t kl = kh + 2 * KT * 2;
        if (CELL0) {
            uint32_t Ah[4], Al[4], Bh[2], Bl[2];
            ldsm4(Ah, qh); ldsm4(Al, ql);
            ldsm2t(Bh, kh); ldsm2t(Bl, kl);
            mma_bf16(acc[0], Ah, Bh);
            mma_bf16(acc[0], Ah, Bl);
            mma_bf16(acc[0], Al, Bh);
        } else {
#pragma unroll
            for (int ks = 0; ks < 4; ks++) {
                uint32_t Ah[4], Al[4], Bh[4], Bl[4];
                ldsm4(Ah, qh + ks * 32);
                ldsm4(Al, ql + ks * 32);
                ldsm4t(Bh, kh + ks * 16 * PK * 2);
                ldsm4t(Bl, kl + ks * 16 * PK * 2);
#pragma unroll
                for (int sub = 0; sub < 2; sub++) {
                    mma_bf16(acc[sub], Ah, Bh + 2 * sub);
                    mma_bf16(acc[sub], Ah, Bl + 2 * sub);
                    mma_bf16(acc[sub], Al, Bh + 2 * sub);
                }
            }
        }
        if (chk < NCH - 1) STORE(1 - cb);
        __syncthreads();
    }

    if (CELL0) {
        float* red = reinterpret_cast<float*>(smb);
        red[warp * 128 + g * 8 + 2 * tg]           = acc[0][0];
        red[warp * 128 + g * 8 + 2 * tg + 1]       = acc[0][1];
        red[warp * 128 + (g + 8) * 8 + 2 * tg]     = acc[0][2];
        red[warp * 128 + (g + 8) * 8 + 2 * tg + 1] = acc[0][3];
        __syncthreads();
        if (tid < 128) {
            float sum = 0.f;
#pragma unroll
            for (int w = 0; w < 8; w++) sum += red[w * 128 + tid];
            Sp[(size_t)sl * 256 + b * 128 + tid] = sum;
        }
    } else {
        size_t base = (size_t)sl * 4096 + b * 2048;
#pragma unroll
        for (int sub = 0; sub < 2; sub++) {
            int s0 = wn * 16 + sub * 8 + 2 * tg;
            int i0 = wm * 16 + g;
            Sp[base + i0 * 32 + s0]           = acc[sub][0];
            Sp[base + i0 * 32 + s0 + 1]       = acc[sub][1];
            Sp[base + (i0 + 8) * 32 + s0]     = acc[sub][2];
            Sp[base + (i0 + 8) * 32 + s0 + 1] = acc[sub][3];
        }
    }
}

// ---------------- reduce partials + softmax: one block per row ---------------
__global__ __launch_bounds__(256) void softmax_reduce(
    const float* __restrict__ Sp, float* __restrict__ S,
    int A2, int rowtot)
{
    __shared__ float red[256];
    int row = blockIdx.x;
    int tid = threadIdx.x;
    int s = tid & (A2 - 1);
    int chunk = tid / A2;
    float v = 0.f;
#pragma unroll 4
    for (int i = 0; i < 32; i++) {
        if (i >= A2) break;
        int sl = chunk * A2 + i;
        v += Sp[(size_t)sl * rowtot + row * A2 + s];
    }
    red[tid] = v;
    __syncthreads();
    for (int off = 128; off >= 32; off >>= 1) {
        if (tid < off) red[tid] += red[tid + off];
        __syncthreads();
    }
    if (tid < A2) {
        float val = 0.f;
        int nch = 32 / A2;
        for (int c = 0; c < nch; c++) val += red[c * A2 + tid];
        unsigned mask = (A2 == 32) ? 0xffffffffu : ((1u << A2) - 1u);
        float vm = val;
        for (int off = A2 >> 1; off; off >>= 1)
            vm = fmaxf(vm, __shfl_xor_sync(mask, vm, off));
        float e = expf(val - vm);
        float sum = e;
        for (int off = A2 >> 1; off; off >>= 1)
            sum += __shfl_xor_sync(mask, sum, off);
        S[row * A2 + tid] = e / sum;
    }
}

// ---------------- o-GEMM + un-permute + residual (cells T, W) ---------------
template<int CELL>
__global__ __launch_bounds__(256) void epilogue_kernel(
    const float* __restrict__ v, const float* __restrict__ S,
    const float* __restrict__ cur, float* __restrict__ outp,
    const float* __restrict__ gammap)
{
    constexpr int A  = (CELL == 0) ? 16 : 64;
    constexpr int A2 = (CELL == 0) ? 8 : 32;
    constexpr int d  = (CELL == 0) ? 4096 : 1024;

    int b = blockIdx.y;
    __shared__ float attnS[A * A2];
    int tid = threadIdx.x;
    for (int idx = tid; idx < A * A2; idx += 256)
        attnS[idx] = S[b * A * A2 + idx];
    __syncthreads();

    float g = gammap[0];
    int x = blockIdx.x * 256 + tid;

    const float4* vr4 = reinterpret_cast<const float4*>(
        v + (size_t)b * 8388608 + (size_t)x * A2);
    float vv[A2];
#pragma unroll
    for (int s4 = 0; s4 < A2 / 4; s4++) {
        float4 t = vr4[s4];
        vv[s4 * 4 + 0] = t.x; vv[s4 * 4 + 1] = t.y;
        vv[s4 * 4 + 2] = t.z; vv[s4 * 4 + 3] = t.w;
    }
    int c  = x / d;
    int p  = x % d;
    int p1 = p / 64;
    int p2 = p % 64;
    size_t boff = (size_t)b * 16777216 + (size_t)c * 65536;
    int base, stride;
    if (CELL == 0) { base = p1 * 64   + p2; stride = 4096; }
    else           { base = p1 * 4096 + p2; stride = 64;   }

#pragma unroll 4
    for (int a = 0; a < A; a++) {
        float o = 0.f;
#pragma unroll
        for (int s = 0; s < A2; s++) o += vv[s] * attnS[a * A2 + s];
        int off = base + a * stride;
        outp[boff + off] = g * o + cur[boff + off];
    }
}

// ---------------- cell-H epilogue: smem transpose, fully coalesced I/O ------
__global__ __launch_bounds__(256) void epilogue2_kernel(
    const float* __restrict__ v, const float* __restrict__ S,
    const float* __restrict__ cur, float* __restrict__ outp,
    const float* __restrict__ gammap)
{
    int b  = blockIdx.y;
    int cp = blockIdx.x;        // c*16 + p1
    int c = cp >> 4, p1 = cp & 15;

    __shared__ float attnS[64 * 33];
    __shared__ float vs[64 * 33];
    __shared__ float os[64 * 65];
    int tid = threadIdx.x;

    for (int i = tid; i < 2048; i += 256)
        attnS[(i >> 5) * 33 + (i & 31)] = S[b * 2048 + i];
    size_t vbase = (size_t)b * 8388608 + ((size_t)c * 1024 + p1 * 64) * 32;
    for (int i = tid; i < 2048; i += 256)
        vs[(i >> 5) * 33 + (i & 31)] = v[vbase + i];
    __syncthreads();

    int p2 = tid & 63;
    int a0 = (tid >> 6) * 16;
    float vv[32];
#pragma unroll
    for (int s = 0; s < 32; s++) vv[s] = vs[p2 * 33 + s];
#pragma unroll
    for (int ai = 0; ai < 16; ai++) {
        int a = a0 + ai;
        float o = 0.f;
#pragma unroll
        for (int s = 0; s < 32; s++) o += vv[s] * attnS[a * 33 + s];
        os[p2 * 65 + a] = o;
    }
    __syncthreads();

    float g = gammap[0];
    size_t obase = (size_t)b * 16777216 + (size_t)c * 65536 + (size_t)p1 * 4096;
    for (int i = tid; i < 4096; i += 256)
        outp[obase + i] = g * os[(i >> 6) * 65 + (i & 63)] + cur[obase + i];
}

// ---------------- host orchestration ----------------
extern "C" void kernel_launch(void* const* d_in, const int* in_sizes, int n_in,
                              void* d_out, int out_size)
{
    const float* x  = (const float*)d_in[0];
    const float* Wq = (const float*)d_in[1];
    const float* bq = (const float*)d_in[2];
    const float* Wk = (const float*)d_in[3];
    const float* bk = (const float*)d_in[4];
    const float* Wv = (const float*)d_in[5];
    const float* bv = (const float*)d_in[6];
    const float* gm = (const float*)d_in[7];
    float* out = (float*)d_out;

    float *buf0, *buf1, *xp, *q, *k, *v, *Sp, *S;
    cudaGetSymbolAddress((void**)&buf0, g_buf0);
    cudaGetSymbolAddress((void**)&buf1, g_buf1);
    cudaGetSymbolAddress((void**)&xp,   g_xp);
    cudaGetSymbolAddress((void**)&q,    g_q);
    cudaGetSymbolAddress((void**)&k,    g_k);
    cudaGetSymbolAddress((void**)&v,    g_v);
    cudaGetSymbolAddress((void**)&Sp,   g_Sp);
    cudaGetSymbolAddress((void**)&S,    g_S);

    const int SM_CF = 2 * 256 * 136 * 2;                                // 139264
    const int SM_A0 = (2 * 2176 + 2 * 2176 + 2 * 1024 + 2 * 1024) * 2;  // 25600
    const int SM_A1 = (2 * 4608 + 2 * 4608 + 2 * 2560 + 2 * 2560) * 2;  // 57344

    cudaFuncSetAttribute(conv_fx<0,12>, cudaFuncAttributeMaxDynamicSharedMemorySize, SM_CF);
    cudaFuncSetAttribute(conv_fx<1,10>, cudaFuncAttributeMaxDynamicSharedMemorySize, SM_CF);
    cudaFuncSetAttribute(conv_fx<0,10>, cudaFuncAttributeMaxDynamicSharedMemorySize, SM_CF);
    cudaFuncSetAttribute(attn_mma<1>, cudaFuncAttributeMaxDynamicSharedMemorySize, SM_A0);
    cudaFuncSetAttribute(attn_mma<0>, cudaFuncAttributeMaxDynamicSharedMemorySize, SM_A1);

    // ================= cell 0 : attention over T (identity permutation) ======
    {
        wfrag_prep<<<64, 256>>>(Wq, Wk, Wv);
        conv_fx<0,12><<<dim3(512, 1, 2), 512, SM_CF>>>(x, bq, bk, bv, q, k, v);
        attn_mma<1><<<dim3(256, 2), 256, SM_A0>>>(q, k, Sp);
        softmax_reduce<<<32, 256>>>(Sp, S, 8, 256);
        epilogue_kernel<0><<<dim3(4096, 2), 256>>>(v, S, x, buf0, gm + 0);
    }
    // ================= cell 1 : attention over W (fused permute in conv) =====
    {
        wfrag_prep<<<64, 256>>>(Wq + 32768, Wk + 32768, Wv + 65536);
        conv_fx<1,10><<<dim3(512, 1, 2), 512, SM_CF>>>(
            buf0, bq + 128, bk + 128, bv + 256, q, k, v);
        attn_mma<0><<<dim3(256, 2), 256, SM_A1>>>(q, k, Sp);
        softmax_reduce<<<128, 256>>>(Sp, S, 32, 4096);
        epilogue_kernel<1><<<dim3(1024, 2), 256>>>(v, S, buf0, buf1, gm + 1);
    }
    // ================= cell 2 : attention over H ==============================
    {
        permuteH_kernel<<<dim3(64, 256, 2), 256>>>(buf1, xp);
        wfrag_prep<<<64, 256>>>(Wq + 65536, Wk + 65536, Wv + 131072);
        conv_fx<0,10><<<dim3(512, 1, 2), 512, SM_CF>>>(
            xp, bq + 256, bk + 256, bv + 512, q, k, v);
        attn_mma<0><<<dim3(256, 2), 256, SM_A1>>>(q, k, Sp);
        softmax_reduce<<<128, 256>>>(Sp, S, 32, 4096);
        epilogue2_kernel<<<dim3(4096, 2), 256>>>(v, S, buf1, out, gm + 2);
    }
}

// round 12
// speedup vs baseline: 3.4447x; 1.0084x over previous
#include <cuda_runtime.h>
#include <cuda_bf16.h>
#include <cstdint>

#define NEL 33554432           // 2*256*16*64*64
#define NSP 65536               // T*W*H

// ---------------- scratch (device globals; no runtime alloc) ----------------
__device__ float g_buf0[NEL];
__device__ float g_buf1[NEL];
__device__ float g_xp[NEL];
__device__ float g_q[16777216];   // B * 128 * 65536
__device__ float g_k[8388608];    // B * 128 * 32768
__device__ float g_v[16777216];   // B * 256 * 32768
__device__ float g_Sp[1048576];   // split-K partials (256 slices * 4096)
__device__ float g_S[4096];       // attn after softmax: B*64*32 max
// fragment-major packed weights (bf16 hi/lo planes, m16n8k16 A layout)
__device__ __align__(16) uint32_t g_wfh[65536];
__device__ __align__(16) uint32_t g_wfl[65536];
// tf32 fragment-major q/k weights: 16 mtiles x 16 kt x 32 lanes x 8 floats
__device__ __align__(16) float g_wft[65536];

// ---------------- helpers ----------------
__device__ __forceinline__ float4 ld4(const float* p) {
    return *reinterpret_cast<const float4*>(p);
}
__device__ __forceinline__ float tf32_rna(float x) {
    uint32_t u;
    asm("cvt.rna.tf32.f32 %0, %1;" : "=r"(u) : "f"(x));
    return __uint_as_float(u);
}
__device__ __forceinline__ float4 rna4(float4 x) {
    x.x = tf32_rna(x.x); x.y = tf32_rna(x.y);
    x.z = tf32_rna(x.z); x.w = tf32_rna(x.w);
    return x;
}
__device__ __forceinline__ void split_f4(float4 v, uint2& h, uint2& l) {
    asm("cvt.rn.bf16x2.f32 %0, %1, %2;" : "=r"(h.x) : "f"(v.y), "f"(v.x));
    asm("cvt.rn.bf16x2.f32 %0, %1, %2;" : "=r"(h.y) : "f"(v.w), "f"(v.z));
    float rx = v.x - __uint_as_float(h.x << 16);
    float ry = v.y - __uint_as_float(h.x & 0xffff0000u);
    float rz = v.z - __uint_as_float(h.y << 16);
    float rw = v.w - __uint_as_float(h.y & 0xffff0000u);
    asm("cvt.rn.bf16x2.f32 %0, %1, %2;" : "=r"(l.x) : "f"(ry), "f"(rx));
    asm("cvt.rn.bf16x2.f32 %0, %1, %2;" : "=r"(l.y) : "f"(rw), "f"(rz));
}
__device__ __forceinline__ void split_pair(float a, float b, uint32_t& h, uint32_t& l) {
    asm("cvt.rn.bf16x2.f32 %0, %1, %2;" : "=r"(h) : "f"(b), "f"(a));
    float ra = a - __uint_as_float(h << 16);
    float rb = b - __uint_as_float(h & 0xffff0000u);
    asm("cvt.rn.bf16x2.f32 %0, %1, %2;" : "=r"(l) : "f"(rb), "f"(ra));
}
__device__ __forceinline__ void ldsm4(uint32_t* r, uint32_t a) {
    asm volatile("ldmatrix.sync.aligned.m8n8.x4.shared.b16 {%0,%1,%2,%3}, [%4];"
        : "=r"(r[0]), "=r"(r[1]), "=r"(r[2]), "=r"(r[3]) : "r"(a));
}
__device__ __forceinline__ void ldsm4t(uint32_t* r, uint32_t a) {
    asm volatile("ldmatrix.sync.aligned.m8n8.x4.trans.shared.b16 {%0,%1,%2,%3}, [%4];"
        : "=r"(r[0]), "=r"(r[1]), "=r"(r[2]), "=r"(r[3]) : "r"(a));
}
__device__ __forceinline__ void ldsm2t(uint32_t* r, uint32_t a) {
    asm volatile("ldmatrix.sync.aligned.m8n8.x2.trans.shared.b16 {%0,%1}, [%2];"
        : "=r"(r[0]), "=r"(r[1]) : "r"(a));
}
__device__ __forceinline__ void mma_bf16(float* d, const uint32_t* a, const uint32_t* b) {
    asm volatile("mma.sync.aligned.m16n8k16.row.col.f32.bf16.bf16.f32 "
        "{%0,%1,%2,%3}, {%4,%5,%6,%7}, {%8,%9}, {%0,%1,%2,%3};"
        : "+f"(d[0]), "+f"(d[1]), "+f"(d[2]), "+f"(d[3])
        : "r"(a[0]), "r"(a[1]), "r"(a[2]), "r"(a[3]), "r"(b[0]), "r"(b[1]));
}
__device__ __forceinline__ void mma_tf32(float* d, const float* a, float b0, float b1) {
    asm volatile(
        "mma.sync.aligned.m16n8k8.row.col.f32.tf32.tf32.f32 "
        "{%0,%1,%2,%3}, {%4,%5,%6,%7}, {%8,%9}, {%0,%1,%2,%3};"
        : "+f"(d[0]), "+f"(d[1]), "+f"(d[2]), "+f"(d[3])
        : "r"(__float_as_uint(a[0])), "r"(__float_as_uint(a[1])),
          "r"(__float_as_uint(a[2])), "r"(__float_as_uint(a[3])),
          "r"(__float_as_uint(b0)), "r"(__float_as_uint(b1)));
}

// ---------------- W fragment pre-pack: bf16 hi/lo (all 512 rows) ------------
__global__ __launch_bounds__(256) void wfrag_prep(
    const float* __restrict__ Wq, const float* __restrict__ Wk,
    const float* __restrict__ Wv)
{
    int idx = blockIdx.x * 256 + threadIdx.x;   // 16384 = 512 tiles * 32 lanes
    int tile = idx >> 5, lane = idx & 31;
    int mtile = tile >> 4, kt = tile & 15;
    int g = lane >> 2, tg = lane & 3;
    int r0 = mtile * 16 + g;
    int c0 = kt * 16 + tg * 2;

    uint32_t h[4], l[4];
#pragma unroll
    for (int j = 0; j < 4; j++) {
        int r = r0 + ((j & 1) ? 8 : 0);
        int c = c0 + ((j & 2) ? 8 : 0);
        const float* Wr;
        if (r < 128)      Wr = Wq + r * 256;
        else if (r < 256) Wr = Wk + (r - 128) * 256;
        else              Wr = Wv + (r - 256) * 256;
        split_pair(Wr[c], Wr[c + 1], h[j], l[j]);
    }
    *(uint4*)&g_wfh[tile * 128 + lane * 4] = make_uint4(h[0], h[1], h[2], h[3]);
    *(uint4*)&g_wfl[tile * 128 + lane * 4] = make_uint4(l[0], l[1], l[2], l[3]);
}

// ---------------- W fragment pre-pack: tf32 (q,k rows only) -----------------
// m16n8k8 A-frag: a0=A[g][tg], a1=A[g+8][tg], a2=A[g][tg+4], a3=A[g+8][tg+4]
// 8 floats per lane per kt16 = two k8 fragments (s=0: k in [0,8), s=1: [8,16))
__global__ __launch_bounds__(256) void wfrag_tf(
    const float* __restrict__ Wq, const float* __restrict__ Wk)
{
    int idx = blockIdx.x * 256 + threadIdx.x;   // 8192 = 256 tiles * 32 lanes
    int tile = idx >> 5, lane = idx & 31;
    int mtile = tile >> 4, kt = tile & 15;
    int g = lane >> 2, tg = lane & 3;
    const float* Wr = (mtile < 8) ? Wq : Wk;
    int m0 = (mtile & 7) * 16;

    float out[8];
#pragma unroll
    for (int s = 0; s < 2; s++)
#pragma unroll
        for (int ai = 0; ai < 4; ai++) {
            int m = m0 + g + ((ai & 1) ? 8 : 0);
            int k = kt * 16 + s * 8 + tg + ((ai & 2) ? 4 : 0);
            out[s * 4 + ai] = tf32_rna(Wr[m * 256 + k]);
        }
    *(float4*)&g_wft[(tile * 32 + lane) * 8]     = make_float4(out[0], out[1], out[2], out[3]);
    *(float4*)&g_wft[(tile * 32 + lane) * 8 + 4] = make_float4(out[4], out[5], out[6], out[7]);
}

// ---------------- permute H (canonical -> [c][h][w][t]) via smem transpose ---
__global__ __launch_bounds__(256) void permuteH_kernel(
    const float* __restrict__ src, float* __restrict__ dst)
{
    __shared__ float s[16][65];
    int w = blockIdx.x;
    int c = blockIdx.y;
    int b = blockIdx.z;
    size_t base = ((size_t)b * 256 + c) * 65536;
    int tid = threadIdx.x;
    for (int idx = tid; idx < 1024; idx += 256) {
        int t = idx >> 6, h = idx & 63;
        s[t][h] = src[base + (size_t)t * 4096 + w * 64 + h];
    }
    __syncthreads();
    for (int idx = tid; idx < 1024; idx += 256) {
        int h = idx >> 4, t = idx & 15;
        dst[base + (size_t)h * 1024 + w * 16 + t] = s[t][h];
    }
}

// ---------------- bf16 conv GEMM chunk (compile-time NPASS, pipelined) ------
template<int NPASS>
__device__ __forceinline__ void conv_chunk(
    int tbase, uint32_t sb, int wn, int r8, int ch,
    const uint4* __restrict__ wfh4, const uint4* __restrict__ wfl4,
    int lane, float acc[8][4])
{
    constexpr int PP = 136;
    constexpr int PT = 256 * PP;

    uint4 Ah = wfh4[tbase * 32 + lane];
    uint4 Al;
    if (NPASS == 3) Al = wfl4[tbase * 32 + lane];

#pragma unroll 1
    for (int kt = 0; kt < 16; kt++) {
        uint4 Ah_c = Ah, Al_c = Al;
        if (kt < 15) {
            Ah = wfh4[(tbase + kt + 1) * 32 + lane];
            if (NPASS == 3) Al = wfl4[(tbase + kt + 1) * 32 + lane];
        }
        uint32_t Bh[4][4], Bl[4][4];
#pragma unroll
        for (int pp = 0; pp < 4; pp++) {
            int pcolp = (pp < 2) ? (wn * 32 + pp * 16)
                                 : (64 + wn * 32 + (pp - 2) * 16);
            uint32_t ba = sb + (((kt * 16 + r8) * PP) + ch + pcolp) * 2;
            ldsm4t(Bh[pp], ba);
            if (NPASS == 3) ldsm4t(Bl[pp], ba + PT * 2);
        }
#pragma unroll
        for (int pp = 0; pp < 4; pp++)
#pragma unroll
            for (int sub = 0; sub < 2; sub++) {
                float* d = acc[pp * 2 + sub];
                mma_bf16(d, (const uint32_t*)&Ah_c, Bh[pp] + 2 * sub);
                if (NPASS == 3) {
                    mma_bf16(d, (const uint32_t*)&Ah_c, Bl[pp] + 2 * sub);
                    mma_bf16(d, (const uint32_t*)&Al_c, Bh[pp] + 2 * sub);
                }
            }
    }
}

// ---------------- tf32 conv GEMM chunk (1-pass, pipelined) ------------------
__device__ __forceinline__ void conv_chunk_tf(
    int tbase, const float* __restrict__ XPT, int wn, int g, int tg,
    const float4* __restrict__ wft4, int lane, float acc[8][4])
{
    constexpr int PPT = 136;

    float4 A0 = wft4[(tbase * 32 + lane) * 2];
    float4 A1 = wft4[(tbase * 32 + lane) * 2 + 1];

#pragma unroll 1
    for (int kt = 0; kt < 16; kt++) {
        float4 A0c = A0, A1c = A1;
        if (kt < 15) {
            A0 = wft4[((tbase + kt + 1) * 32 + lane) * 2];
            A1 = wft4[((tbase + kt + 1) * 32 + lane) * 2 + 1];
        }
        int kb = kt * 16;
#pragma unroll
        for (int pp = 0; pp < 4; pp++) {
            int nb = ((pp < 2) ? (wn * 32 + pp * 16)
                               : (64 + wn * 32 + (pp - 2) * 16)) + g;
#pragma unroll
            for (int sub = 0; sub < 2; sub++) {
                float* d = acc[pp * 2 + sub];
                int n = nb + sub * 8;
                float b0 = XPT[(kb + tg) * PPT + n];
                float b1 = XPT[(kb + tg + 4) * PPT + n];
                mma_tf32(d, (const float*)&A0c, b0, b1);
                float b2 = XPT[(kb + 8 + tg) * PPT + n];
                float b3 = XPT[(kb + 8 + tg + 4) * PPT + n];
                mma_tf32(d, (const float*)&A1c, b2, b3);
            }
        }
    }
}

// ---------------- shared conv epilogues --------------------------------------
__device__ __forceinline__ void conv_epi_q(
    float acc[8][4], float* qo, const float* bq, int b,
    int wm, int wn, int g, int tg, int qc0, int qc1)
{
    float* outb = qo + (size_t)b * 8388608;
    int r = wm * 16 + g;
    float b0 = bq[r], b1 = bq[r + 8];
#pragma unroll
    for (int nt = 0; nt < 8; nt++) {
        int lcol = wn * 32 + ((nt & 3) >> 1) * 16 + (nt & 1) * 8 + tg * 2;
        int col = (nt < 4 ? qc0 : qc1) + lcol;
        *(float2*)&outb[(size_t)r * 65536 + col] =
            make_float2(acc[nt][0] + b0, acc[nt][1] + b0);
        *(float2*)&outb[(size_t)(r + 8) * 65536 + col] =
            make_float2(acc[nt][2] + b1, acc[nt][3] + b1);
    }
}
__device__ __forceinline__ void conv_epi_pool(
    float acc[8][4], float* outb, const float* bc,
    int wm, int wn, int g, int tg, int n0)
{
    int r = wm * 16 + g;
    float b0 = bc[r], b1 = bc[r + 8];
#pragma unroll
    for (int nt = 0; nt < 4; nt++) {
        int col = n0 + wn * 32 + (nt >> 1) * 16 + (nt & 1) * 8 + tg * 2;
        float v00 = fmaxf(acc[nt][0], acc[nt + 4][0]) + b0;
        float v01 = fmaxf(acc[nt][1], acc[nt + 4][1]) + b0;
        float v10 = fmaxf(acc[nt][2], acc[nt + 4][2]) + b1;
        float v11 = fmaxf(acc[nt][3], acc[nt + 4][3]) + b1;
        *(float2*)&outb[(size_t)r * 32768 + col]       = make_float2(v00, v01);
        *(float2*)&outb[(size_t)(r + 8) * 32768 + col] = make_float2(v10, v11);
    }
}

// ---------------- strip-base computation --------------------------------------
template<int MODE, int LOGD>
__device__ __forceinline__ void strip_bases(int n0, int& s0, int& s1, int& qc0, int& qc1) {
    if (MODE == 0) {
        int a2 = n0 >> LOGD;
        int p0 = n0 & ((1 << LOGD) - 1);
        s0 = ((2 * a2) << LOGD) + p0;
        s1 = s0 + (1 << LOGD);
        qc0 = s0; qc1 = s1;
    } else {
        int aa = n0 >> 10;
        int r  = n0 & 1023;
        s0 = (r >> 6) * 4096 + (2 * aa) * 64;
        s1 = s0 + 64;
        qc0 = (2 * aa) * 1024 + r;
        qc1 = qc0 + 1024;
    }
}

// ---------------- cell-T conv: bf16 hi/lo panels, q/k 3-pass, v 1-pass ------
template<int MODE, int LOGD>
__global__ __launch_bounds__(512) void conv_fx(
    const float* __restrict__ X,
    const float* __restrict__ bq, const float* __restrict__ bk,
    const float* __restrict__ bv,
    float* __restrict__ qo, float* __restrict__ ko, float* __restrict__ vo)
{
    constexpr int PP = 136;
    constexpr int PT = 256 * PP;

    extern __shared__ char smem_raw[];
    __nv_bfloat16* XPH = reinterpret_cast<__nv_bfloat16*>(smem_raw);
    __nv_bfloat16* XPL = XPH + PT;

    int b  = blockIdx.z;
    int n0 = blockIdx.x * 64;
    const float* Xb = X + (size_t)b * 256 * NSP;

    int tid  = threadIdx.x;
    int lane = tid & 31, warp = tid >> 5;
    int wm = warp & 7, wn = warp >> 3;
    int g = lane >> 2, tg = lane & 3;
    int r8 = (lane & 7) + (lane & 8);
    int ch = (lane & 16) >> 1;

    int s0, s1, qc0, qc1;
    strip_bases<MODE, LOGD>(n0, s0, s1, qc0, qc1);

    {
        int prow = tid >> 4;
        int pcol = (tid & 15) * 4;
#pragma unroll
        for (int it = 0; it < 8; it++) {
            int row = it * 32 + prow;
            float4 x0 = ld4(Xb + (size_t)row * NSP + s0 + pcol);
            float4 x1 = ld4(Xb + (size_t)row * NSP + s1 + pcol);
            uint2 h0, l0, h1, l1;
            split_f4(x0, h0, l0);
            split_f4(x1, h1, l1);
            *(uint2*)&XPH[row * PP + pcol]      = h0;
            *(uint2*)&XPL[row * PP + pcol]      = l0;
            *(uint2*)&XPH[row * PP + 64 + pcol] = h1;
            *(uint2*)&XPL[row * PP + 64 + pcol] = l1;
        }
    }
    __syncthreads();

    uint32_t sb = (uint32_t)__cvta_generic_to_shared(XPH);
    const uint4* wfh4 = reinterpret_cast<const uint4*>(g_wfh);
    const uint4* wfl4 = reinterpret_cast<const uint4*>(g_wfl);

    float acc[8][4];
    {
#pragma unroll
        for (int nt = 0; nt < 8; nt++)
#pragma unroll
            for (int r = 0; r < 4; r++) acc[nt][r] = 0.f;
        conv_chunk<3>((0 * 8 + wm) * 16, sb, wn, r8, ch, wfh4, wfl4, lane, acc);
        conv_epi_q(acc, qo, bq, b, wm, wn, g, tg, qc0, qc1);
    }
#pragma unroll 1
    for (int mc = 1; mc < 4; mc++) {
#pragma unroll
        for (int nt = 0; nt < 8; nt++)
#pragma unroll
            for (int r = 0; r < 4; r++) acc[nt][r] = 0.f;
        if (mc == 1)
            conv_chunk<3>((1 * 8 + wm) * 16, sb, wn, r8, ch, wfh4, wfl4, lane, acc);
        else if (mc == 2)
            conv_chunk<1>((2 * 8 + wm) * 16, sb, wn, r8, ch, wfh4, wfl4, lane, acc);
        else
            conv_chunk<1>((3 * 8 + wm) * 16, sb, wn, r8, ch, wfh4, wfl4, lane, acc);

        float* outb = (mc == 1) ? (ko + (size_t)b * 4194304)
                                : (vo + (size_t)b * 8388608 + (size_t)(mc - 2) * 4194304);
        const float* bc = (mc == 1) ? bk : (bv + (mc - 2) * 128);
        conv_epi_pool(acc, outb, bc, wm, wn, g, tg, n0);
    }
}

// ---------------- cells W/H conv: q/k tf32 1-pass, v bf16 1-pass ------------
template<int MODE, int LOGD>
__global__ __launch_bounds__(512) void conv_tf(
    const float* __restrict__ X,
    const float* __restrict__ bq, const float* __restrict__ bk,
    const float* __restrict__ bv,
    float* __restrict__ qo, float* __restrict__ ko, float* __restrict__ vo)
{
    constexpr int PPT = 136;           // tf32 panel pitch (floats)
    constexpr int PPB = 136;           // bf16 panel pitch (bf16)

    extern __shared__ char smem_raw[];
    float* XPT = reinterpret_cast<float*>(smem_raw);               // 256*136 f32
    __nv_bfloat16* XPB = reinterpret_cast<__nv_bfloat16*>(XPT + 256 * PPT);

    int b  = blockIdx.z;
    int n0 = blockIdx.x * 64;
    const float* Xb = X + (size_t)b * 256 * NSP;

    int tid  = threadIdx.x;
    int lane = tid & 31, warp = tid >> 5;
    int wm = warp & 7, wn = warp >> 3;
    int g = lane >> 2, tg = lane & 3;
    int r8 = (lane & 7) + (lane & 8);
    int ch = (lane & 16) >> 1;

    int s0, s1, qc0, qc1;
    strip_bases<MODE, LOGD>(n0, s0, s1, qc0, qc1);

    // ---- fill both panels (once) ----
    {
        int prow = tid >> 4;
        int pcol = (tid & 15) * 4;
#pragma unroll
        for (int it = 0; it < 8; it++) {
            int row = it * 32 + prow;
            float4 x0 = ld4(Xb + (size_t)row * NSP + s0 + pcol);
            float4 x1 = ld4(Xb + (size_t)row * NSP + s1 + pcol);
            *(float4*)&XPT[row * PPT + pcol]      = rna4(x0);
            *(float4*)&XPT[row * PPT + 64 + pcol] = rna4(x1);
            uint2 h0, l0, h1, l1;
            split_f4(x0, h0, l0);
            split_f4(x1, h1, l1);
            *(uint2*)&XPB[row * PPB + pcol]      = h0;
            *(uint2*)&XPB[row * PPB + 64 + pcol] = h1;
        }
    }
    __syncthreads();

    uint32_t sbB = (uint32_t)__cvta_generic_to_shared(XPB);
    const uint4*  wfh4 = reinterpret_cast<const uint4*>(g_wfh);
    const uint4*  wfl4 = reinterpret_cast<const uint4*>(g_wfl);
    const float4* wft4 = reinterpret_cast<const float4*>(g_wft);

    float acc[8][4];
    // ---- q: tf32 1-pass (mtiles 0..7 of g_wft) ----
    {
#pragma unroll
        for (int nt = 0; nt < 8; nt++)
#pragma unroll
            for (int r = 0; r < 4; r++) acc[nt][r] = 0.f;
        conv_chunk_tf((0 * 8 + wm) * 16, XPT, wn, g, tg, wft4, lane, acc);
        conv_epi_q(acc, qo, bq, b, wm, wn, g, tg, qc0, qc1);
    }
    // ---- k: tf32 1-pass (mtiles 8..15 of g_wft) ----
    {
#pragma unroll
        for (int nt = 0; nt < 8; nt++)
#pragma unroll
            for (int r = 0; r < 4; r++) acc[nt][r] = 0.f;
        conv_chunk_tf((1 * 8 + wm) * 16, XPT, wn, g, tg, wft4, lane, acc);
        conv_epi_pool(acc, ko + (size_t)b * 4194304, bk, wm, wn, g, tg, n0);
    }
    // ---- v0, v1: bf16 1-pass (mtiles 16..31 of g_wfh) ----
#pragma unroll 1
    for (int mc = 2; mc < 4; mc++) {
#pragma unroll
        for (int nt = 0; nt < 8; nt++)
#pragma unroll
            for (int r = 0; r < 4; r++) acc[nt][r] = 0.f;
        if (mc == 2)
            conv_chunk<1>((2 * 8 + wm) * 16, sbB, wn, r8, ch, wfh4, wfl4, lane, acc);
        else
            conv_chunk<1>((3 * 8 + wm) * 16, sbB, wn, r8, ch, wfh4, wfl4, lane, acc);
        conv_epi_pool(acc, vo + (size_t)b * 8388608 + (size_t)(mc - 2) * 4194304,
                      bv + (mc - 2) * 128, wm, wn, g, tg, n0);
    }
}

// ---------------- attention logits: bf16x3 tensor-core streaming GEMM -------
template<int CELL0>
__global__ __launch_bounds__(256) void attn_mma(
    const float* __restrict__ q, const float* __restrict__ k,
    float* __restrict__ Sp)
{
    constexpr int Ac  = CELL0 ? 16 : 64;
    constexpr int A2c = CELL0 ? 8  : 32;
    constexpr int K   = CELL0 ? 524288 : 131072;
    constexpr int KSL = K / 256;
    constexpr int CJ  = CELL0 ? 128 : 64;
    constexpr int NCH = KSL / CJ;
    constexpr int PQ  = CELL0 ? 136 : 72;
    constexpr int PK  = CELL0 ? 8 : 40;
    constexpr int QT  = Ac * PQ;
    constexpr int KT  = CJ * PK;
    constexpr int NQ  = CELL0 ? 2 : 4;
    constexpr int NK  = CELL0 ? 1 : 2;

    extern __shared__ __nv_bfloat16 smb[];
    __nv_bfloat16 *QH = smb, *QL = QH + 2 * QT, *KH = QL + 2 * QT, *KL = KH + 2 * KT;

    int b = blockIdx.y, sl = blockIdx.x;
    const float* qb = q + (size_t)b * Ac * K + (size_t)sl * KSL;
    const float* kb = k + ((size_t)b * K + (size_t)sl * KSL) * A2c;

    int tid = threadIdx.x, lane = tid & 31, warp = tid >> 5;
    int g = lane >> 2, tg = lane & 3;

    float4 qv[NQ], kv[NK];
    auto LOAD = [&](int chk) {
        int j0 = chk * CJ;
#pragma unroll
        for (int l = 0; l < NQ; l++) {
            int idx = tid + 256 * l;
            int row = CELL0 ? (idx >> 5) : (idx >> 4);
            int c   = CELL0 ? ((idx & 31) * 4) : ((idx & 15) * 4);
            qv[l] = ld4(qb + (size_t)row * K + j0 + c);
        }
#pragma unroll
        for (int l = 0; l < NK; l++) {
            int idx = tid + 256 * l;
            int row = CELL0 ? (idx >> 1) : (idx >> 3);
            int c   = CELL0 ? ((idx & 1) * 4) : ((idx & 7) * 4);
            kv[l] = ld4(kb + (size_t)(j0 + row) * A2c + c);
        }
    };
    auto STORE = [&](int bf) {
#pragma unroll
        for (int l = 0; l < NQ; l++) {
            int idx = tid + 256 * l;
            int row = CELL0 ? (idx >> 5) : (idx >> 4);
            int c   = CELL0 ? ((idx & 31) * 4) : ((idx & 15) * 4);
            uint2 h, lo;
            split_f4(qv[l], h, lo);
            int off = bf * QT + row * PQ + c;
            *(uint2*)&QH[off] = h;
            *(uint2*)&QL[off] = lo;
        }
#pragma unroll
        for (int l = 0; l < NK; l++) {
            int idx = tid + 256 * l;
            int row = CELL0 ? (idx >> 1) : (idx >> 3);
            int c   = CELL0 ? ((idx & 1) * 4) : ((idx & 7) * 4);
            uint2 h, lo;
            split_f4(kv[l], h, lo);
            int off = bf * KT + row * PK + c;
            *(uint2*)&KH[off] = h;
            *(uint2*)&KL[off] = lo;
        }
    };

    uint32_t sb = (uint32_t)__cvta_generic_to_shared(smb);
    int r8 = (lane & 7) + (lane & 8);
    int aoe, boe, wm = warp & 3, wn = warp >> 2;
    if (CELL0) {
        aoe = r8 * PQ + ((lane & 16) >> 1) + warp * 16;
        boe = (warp * 16 + (lane & 15)) * PK;
    } else {
        aoe = (wm * 16 + r8) * PQ + ((lane & 16) >> 1);
        boe = r8 * PK + ((lane & 16) >> 1) + wn * 16;
    }
    constexpr int NACC = CELL0 ? 1 : 2;
    float acc[NACC][4];
#pragma unroll
    for (int a = 0; a < NACC; a++)
#pragma unroll
        for (int r = 0; r < 4; r++) acc[a][r] = 0.f;

    LOAD(0);
    STORE(0);
    __syncthreads();

#pragma unroll 1
    for (int chk = 0; chk < NCH; chk++) {
        int cb = chk & 1;
        if (chk < NCH - 1) LOAD(chk + 1);
        uint32_t qh = sb + (cb * QT + aoe) * 2;
        uint32_t ql = qh + 2 * QT * 2;
        uint32_t kh = sb + 4 * QT * 2 + (cb * KT + boe) * 2;
        uint32_t kl = kh + 2 * KT * 2;
        if (CELL0) {
            uint32_t Ah[4], Al[4], Bh[2], Bl[2];
            ldsm4(Ah, qh); ldsm4(Al, ql);
            ldsm2t(Bh, kh); ldsm2t(Bl, kl);
            mma_bf16(acc[0], Ah, Bh);
            mma_bf16(acc[0], Ah, Bl);
            mma_bf16(acc[0], Al, Bh);
        } else {
#pragma unroll
            for (int ks = 0; ks < 4; ks++) {
                uint32_t Ah[4], Al[4], Bh[4], Bl[4];
                ldsm4(Ah, qh + ks * 32);
                ldsm4(Al, ql + ks * 32);
                ldsm4t(Bh, kh + ks * 16 * PK * 2);
                ldsm4t(Bl, kl + ks * 16 * PK * 2);
#pragma unroll
                for (int sub = 0; sub < 2; sub++) {
                    mma_bf16(acc[sub], Ah, Bh + 2 * sub);
                    mma_bf16(acc[sub], Ah, Bl + 2 * sub);
                    mma_bf16(acc[sub], Al, Bh + 2 * sub);
                }
            }
        }
        if (chk < NCH - 1) STORE(1 - cb);
        __syncthreads();
    }

    if (CELL0) {
        float* red = reinterpret_cast<float*>(smb);
        red[warp * 128 + g * 8 + 2 * tg]           = acc[0][0];
        red[warp * 128 + g * 8 + 2 * tg + 1]       = acc[0][1];
        red[warp * 128 + (g + 8) * 8 + 2 * tg]     = acc[0][2];
        red[warp * 128 + (g + 8) * 8 + 2 * tg + 1] = acc[0][3];
        __syncthreads();
        if (tid < 128) {
            float sum = 0.f;
#pragma unroll
            for (int w = 0; w < 8; w++) sum += red[w * 128 + tid];
            Sp[(size_t)sl * 256 + b * 128 + tid] = sum;
        }
    } else {
        size_t base = (size_t)sl * 4096 + b * 2048;
#pragma unroll
        for (int sub = 0; sub < 2; sub++) {
            int s0 = wn * 16 + sub * 8 + 2 * tg;
            int i0 = wm * 16 + g;
            Sp[base + i0 * 32 + s0]           = acc[sub][0];
            Sp[base + i0 * 32 + s0 + 1]       = acc[sub][1];
            Sp[base + (i0 + 8) * 32 + s0]     = acc[sub][2];
            Sp[base + (i0 + 8) * 32 + s0 + 1] = acc[sub][3];
        }
    }
}

// ---------------- reduce partials + softmax: one block per row ---------------
__global__ __launch_bounds__(256) void softmax_reduce(
    const float* __restrict__ Sp, float* __restrict__ S,
    int A2, int rowtot)
{
    __shared__ float red[256];
    int row = blockIdx.x;
    int tid = threadIdx.x;
    int s = tid & (A2 - 1);
    int chunk = tid / A2;
    float v = 0.f;
#pragma unroll 4
    for (int i = 0; i < 32; i++) {
        if (i >= A2) break;
        int sl = chunk * A2 + i;
        v += Sp[(size_t)sl * rowtot + row * A2 + s];
    }
    red[tid] = v;
    __syncthreads();
    for (int off = 128; off >= 32; off >>= 1) {
        if (tid < off) red[tid] += red[tid + off];
        __syncthreads();
    }
    if (tid < A2) {
        float val = 0.f;
        int nch = 32 / A2;
        for (int c = 0; c < nch; c++) val += red[c * A2 + tid];
        unsigned mask = (A2 == 32) ? 0xffffffffu : ((1u << A2) - 1u);
        float vm = val;
        for (int off = A2 >> 1; off; off >>= 1)
            vm = fmaxf(vm, __shfl_xor_sync(mask, vm, off));
        float e = expf(val - vm);
        float sum = e;
        for (int off = A2 >> 1; off; off >>= 1)
            sum += __shfl_xor_sync(mask, sum, off);
        S[row * A2 + tid] = e / sum;
    }
}

// ---------------- o-GEMM + un-permute + residual (cells T, W) ---------------
template<int CELL>
__global__ __launch_bounds__(256) void epilogue_kernel(
    const float* __restrict__ v, const float* __restrict__ S,
    const float* __restrict__ cur, float* __restrict__ outp,
    const float* __restrict__ gammap)
{
    constexpr int A  = (CELL == 0) ? 16 : 64;
    constexpr int A2 = (CELL == 0) ? 8 : 32;
    constexpr int d  = (CELL == 0) ? 4096 : 1024;

    int b = blockIdx.y;
    __shared__ float attnS[A * A2];
    int tid = threadIdx.x;
    for (int idx = tid; idx < A * A2; idx += 256)
        attnS[idx] = S[b * A * A2 + idx];
    __syncthreads();

    float g = gammap[0];
    int x = blockIdx.x * 256 + tid;

    const float4* vr4 = reinterpret_cast<const float4*>(
        v + (size_t)b * 8388608 + (size_t)x * A2);
    float vv[A2];
#pragma unroll
    for (int s4 = 0; s4 < A2 / 4; s4++) {
        float4 t = vr4[s4];
        vv[s4 * 4 + 0] = t.x; vv[s4 * 4 + 1] = t.y;
        vv[s4 * 4 + 2] = t.z; vv[s4 * 4 + 3] = t.w;
    }
    int c  = x / d;
    int p  = x % d;
    int p1 = p / 64;
    int p2 = p % 64;
    size_t boff = (size_t)b * 16777216 + (size_t)c * 65536;
    int base, stride;
    if (CELL == 0) { base = p1 * 64   + p2; stride = 4096; }
    else           { base = p1 * 4096 + p2; stride = 64;   }

#pragma unroll 4
    for (int a = 0; a < A; a++) {
        float o = 0.f;
#pragma unroll
        for (int s = 0; s < A2; s++) o += vv[s] * attnS[a * A2 + s];
        int off = base + a * stride;
        outp[boff + off] = g * o + cur[boff + off];
    }
}

// ---------------- cell-H epilogue: smem transpose, fully coalesced I/O ------
__global__ __launch_bounds__(256) void epilogue2_kernel(
    const float* __restrict__ v, const float* __restrict__ S,
    const float* __restrict__ cur, float* __restrict__ outp,
    const float* __restrict__ gammap)
{
    int b  = blockIdx.y;
    int cp = blockIdx.x;        // c*16 + p1
    int c = cp >> 4, p1 = cp & 15;

    __shared__ float attnS[64 * 33];
    __shared__ float vs[64 * 33];
    __shared__ float os[64 * 65];
    int tid = threadIdx.x;

    for (int i = tid; i < 2048; i += 256)
        attnS[(i >> 5) * 33 + (i & 31)] = S[b * 2048 + i];
    size_t vbase = (size_t)b * 8388608 + ((size_t)c * 1024 + p1 * 64) * 32;
    for (int i = tid; i < 2048; i += 256)
        vs[(i >> 5) * 33 + (i & 31)] = v[vbase + i];
    __syncthreads();

    int p2 = tid & 63;
    int a0 = (tid >> 6) * 16;
    float vv[32];
#pragma unroll
    for (int s = 0; s < 32; s++) vv[s] = vs[p2 * 33 + s];
#pragma unroll
    for (int ai = 0; ai < 16; ai++) {
        int a = a0 + ai;
        float o = 0.f;
#pragma unroll
        for (int s = 0; s < 32; s++) o += vv[s] * attnS[a * 33 + s];
        os[p2 * 65 + a] = o;
    }
    __syncthreads();

    float g = gammap[0];
    size_t obase = (size_t)b * 16777216 + (size_t)c * 65536 + (size_t)p1 * 4096;
    for (int i = tid; i < 4096; i += 256)
        outp[obase + i] = g * os[(i >> 6) * 65 + (i & 63)] + cur[obase + i];
}

// ---------------- host orchestration ----------------
extern "C" void kernel_launch(void* const* d_in, const int* in_sizes, int n_in,
                              void* d_out, int out_size)
{
    const float* x  = (const float*)d_in[0];
    const float* Wq = (const float*)d_in[1];
    const float* bq = (const float*)d_in[2];
    const float* Wk = (const float*)d_in[3];
    const float* bk = (const float*)d_in[4];
    const float* Wv = (const float*)d_in[5];
    const float* bv = (const float*)d_in[6];
    const float* gm = (const float*)d_in[7];
    float* out = (float*)d_out;

    float *buf0, *buf1, *xp, *q, *k, *v, *Sp, *S;
    cudaGetSymbolAddress((void**)&buf0, g_buf0);
    cudaGetSymbolAddress((void**)&buf1, g_buf1);
    cudaGetSymbolAddress((void**)&xp,   g_xp);
    cudaGetSymbolAddress((void**)&q,    g_q);
    cudaGetSymbolAddress((void**)&k,    g_k);
    cudaGetSymbolAddress((void**)&v,    g_v);
    cudaGetSymbolAddress((void**)&Sp,   g_Sp);
    cudaGetSymbolAddress((void**)&S,    g_S);

    const int SM_CF = 2 * 256 * 136 * 2;                                // 139264
    const int SM_TF = 256 * 136 * 4 + 256 * 136 * 2;                    // 208896
    const int SM_A0 = (2 * 2176 + 2 * 2176 + 2 * 1024 + 2 * 1024) * 2;  // 25600
    const int SM_A1 = (2 * 4608 + 2 * 4608 + 2 * 2560 + 2 * 2560) * 2;  // 57344

    cudaFuncSetAttribute(conv_fx<0,12>, cudaFuncAttributeMaxDynamicSharedMemorySize, SM_CF);
    cudaFuncSetAttribute(conv_tf<1,10>, cudaFuncAttributeMaxDynamicSharedMemorySize, SM_TF);
    cudaFuncSetAttribute(conv_tf<0,10>, cudaFuncAttributeMaxDynamicSharedMemorySize, SM_TF);
    cudaFuncSetAttribute(attn_mma<1>, cudaFuncAttributeMaxDynamicSharedMemorySize, SM_A0);
    cudaFuncSetAttribute(attn_mma<0>, cudaFuncAttributeMaxDynamicSharedMemorySize, SM_A1);

    // ================= cell 0 : attention over T (bf16x3 q/k, identity) ======
    {
        wfrag_prep<<<64, 256>>>(Wq, Wk, Wv);
        conv_fx<0,12><<<dim3(512, 1, 2), 512, SM_CF>>>(x, bq, bk, bv, q, k, v);
        attn_mma<1><<<dim3(256, 2), 256, SM_A0>>>(q, k, Sp);
        softmax_reduce<<<32, 256>>>(Sp, S, 8, 256);
        epilogue_kernel<0><<<dim3(4096, 2), 256>>>(v, S, x, buf0, gm + 0);
    }
    // ================= cell 1 : attention over W (tf32 q/k, fused permute) ===
    {
        wfrag_prep<<<64, 256>>>(Wq + 32768, Wk + 32768, Wv + 65536);
        wfrag_tf<<<32, 256>>>(Wq + 32768, Wk + 32768);
        conv_tf<1,10><<<dim3(512, 1, 2), 512, SM_TF>>>(
            buf0, bq + 128, bk + 128, bv + 256, q, k, v);
        attn_mma<0><<<dim3(256, 2), 256, SM_A1>>>(q, k, Sp);
        softmax_reduce<<<128, 256>>>(Sp, S, 32, 4096);
        epilogue_kernel<1><<<dim3(1024, 2), 256>>>(v, S, buf0, buf1, gm + 1);
    }
    // ================= cell 2 : attention over H (tf32 q/k) ==================
    {
        permuteH_kernel<<<dim3(64, 256, 2), 256>>>(buf1, xp);
        wfrag_prep<<<64, 256>>>(Wq + 65536, Wk + 65536, Wv + 131072);
        wfrag_tf<<<32, 256>>>(Wq + 65536, Wk + 65536);
        conv_tf<0,10><<<dim3(512, 1, 2), 512, SM_TF>>>(
            xp, bq + 256, bk + 256, bv + 512, q, k, v);
        attn_mma<0><<<dim3(256, 2), 256, SM_A1>>>(q, k, Sp);
        softmax_reduce<<<128, 256>>>(Sp, S, 32, 4096);
        epilogue2_kernel<<<dim3(4096, 2), 256>>>(v, S, buf1, out, gm + 2);
    }
}